// round 2
// baseline (speedup 1.0000x reference)
#include <cuda_runtime.h>
#include <math.h>
#include <stdint.h>

// Problem constants (fixed shapes)
#define B_    2
#define S_    2048
#define DM    2048
#define NH    16
#define DK_   128
#define MROWS (B_ * S_)      // 4096
#define EPS_  1e-5f

// ---------------------------------------------------------------------------
// Scratch (no cudaMalloc allowed)
// ---------------------------------------------------------------------------
__device__ float g_xn[(size_t)MROWS * DM];
__device__ float g_q [(size_t)MROWS * DM];
__device__ float g_k [(size_t)MROWS * DM];
__device__ float g_v [(size_t)MROWS * DM];
__device__ float g_o [(size_t)MROWS * DM];
__device__ float2 g_rope[(size_t)S_ * 64];   // (cos, sin) per (pos, j)

// ---------------------------------------------------------------------------
// RoPE table: accurate double-precision sincos of the fp32-quantized phase.
// fast-math __sincosf is catastrically wrong for args ~2000 rad; this kernel
// avoids it entirely.
// ---------------------------------------------------------------------------
__global__ __launch_bounds__(256)
void rope_table_kernel(float2* __restrict__ tab)
{
    int idx = blockIdx.x * 256 + threadIdx.x;     // [0, S_*64)
    if (idx >= S_ * 64) return;
    int j   = idx & 63;
    int pos = idx >> 6;
    // theta as the reference computes it (fp32 result of the power)
    double theta_d = 1.0 / pow(10000.0, (double)j / 64.0);
    float  theta_f = (float)theta_d;
    // phase quantized to fp32 exactly like jnp: pos(f32) * theta(f32)
    float fr = (float)pos * theta_f;
    double dfr = (double)fr;
    tab[idx] = make_float2((float)cos(dfr), (float)sin(dfr));
}

// ---------------------------------------------------------------------------
// LayerNorm: one block per row (2048 floats), 256 threads, float4
// ---------------------------------------------------------------------------
__global__ __launch_bounds__(256)
void ln_kernel(const float* __restrict__ x, const float* __restrict__ g,
               const float* __restrict__ bb, float* __restrict__ out)
{
    int row = blockIdx.x;
    int t = threadIdx.x;
    const float4* xr = (const float4*)(x + (size_t)row * DM);
    float4* orow = (float4*)(out + (size_t)row * DM);

    float4 v0 = xr[t];
    float4 v1 = xr[t + 256];
    float sum = v0.x + v0.y + v0.z + v0.w + v1.x + v1.y + v1.z + v1.w;
    float sq  = v0.x*v0.x + v0.y*v0.y + v0.z*v0.z + v0.w*v0.w
              + v1.x*v1.x + v1.y*v1.y + v1.z*v1.z + v1.w*v1.w;

    #pragma unroll
    for (int off = 16; off; off >>= 1) {
        sum += __shfl_xor_sync(0xffffffffu, sum, off);
        sq  += __shfl_xor_sync(0xffffffffu, sq,  off);
    }
    __shared__ float s_sum[8], s_sq[8];
    int w = t >> 5;
    if ((t & 31) == 0) { s_sum[w] = sum; s_sq[w] = sq; }
    __syncthreads();
    if (t < 32) {
        float a = (t < 8) ? s_sum[t] : 0.f;
        float b = (t < 8) ? s_sq[t]  : 0.f;
        #pragma unroll
        for (int off = 4; off; off >>= 1) {
            a += __shfl_xor_sync(0xffffffffu, a, off);
            b += __shfl_xor_sync(0xffffffffu, b, off);
        }
        if (t == 0) { s_sum[0] = a; s_sq[0] = b; }
    }
    __syncthreads();

    float mu  = s_sum[0] * (1.0f / DM);
    float var = s_sq[0] * (1.0f / DM) - mu * mu;
    float rstd = rsqrtf(var + EPS_);

    const float4* g4 = (const float4*)g;
    const float4* b4 = (const float4*)bb;
    {
        float4 gv = g4[t], bv = b4[t], o;
        o.x = (v0.x - mu) * rstd * gv.x + bv.x;
        o.y = (v0.y - mu) * rstd * gv.y + bv.y;
        o.z = (v0.z - mu) * rstd * gv.z + bv.z;
        o.w = (v0.w - mu) * rstd * gv.w + bv.w;
        orow[t] = o;
    }
    {
        float4 gv = g4[t + 256], bv = b4[t + 256], o;
        o.x = (v1.x - mu) * rstd * gv.x + bv.x;
        o.y = (v1.y - mu) * rstd * gv.y + bv.y;
        o.z = (v1.z - mu) * rstd * gv.z + bv.z;
        o.w = (v1.w - mu) * rstd * gv.w + bv.w;
        orow[t + 256] = o;
    }
}

// ---------------------------------------------------------------------------
// SGEMM NT: C[M,N] = A[M,K] * W[N,K]^T + bias[N] (+ res[M,N])
// 128x128 tile, BK=8, 256 threads, 8x8 per thread
// ---------------------------------------------------------------------------
__global__ __launch_bounds__(256, 2)
void sgemm_nt(const float* __restrict__ A, const float* __restrict__ W,
              const float* __restrict__ bias, const float* __restrict__ res,
              float* __restrict__ C, int K, int N)
{
    __shared__ float As[8][132];
    __shared__ float Bs[8][132];

    int t  = threadIdx.x;
    int tx = t & 15, ty = t >> 4;
    int m0 = blockIdx.y << 7, n0 = blockIdx.x << 7;

    int mr = t >> 1;
    int kr = (t & 1) << 2;
    const float* Ap = A + (size_t)(m0 + mr) * K + kr;
    const float* Wp = W + (size_t)(n0 + mr) * K + kr;

    float acc[8][8];
    #pragma unroll
    for (int i = 0; i < 8; i++)
        #pragma unroll
        for (int j = 0; j < 8; j++) acc[i][j] = 0.f;

    for (int k0 = 0; k0 < K; k0 += 8) {
        float4 av = *(const float4*)(Ap + k0);
        float4 bv = *(const float4*)(Wp + k0);
        As[kr + 0][mr] = av.x; As[kr + 1][mr] = av.y;
        As[kr + 2][mr] = av.z; As[kr + 3][mr] = av.w;
        Bs[kr + 0][mr] = bv.x; Bs[kr + 1][mr] = bv.y;
        Bs[kr + 2][mr] = bv.z; Bs[kr + 3][mr] = bv.w;
        __syncthreads();

        #pragma unroll
        for (int kk = 0; kk < 8; kk++) {
            float a[8], b[8];
            *(float4*)(&a[0]) = *(const float4*)(&As[kk][ty << 3]);
            *(float4*)(&a[4]) = *(const float4*)(&As[kk][(ty << 3) + 4]);
            *(float4*)(&b[0]) = *(const float4*)(&Bs[kk][tx << 3]);
            *(float4*)(&b[4]) = *(const float4*)(&Bs[kk][(tx << 3) + 4]);
            #pragma unroll
            for (int i = 0; i < 8; i++)
                #pragma unroll
                for (int j = 0; j < 8; j++)
                    acc[i][j] += a[i] * b[j];
        }
        __syncthreads();
    }

    float bcol[8];
    #pragma unroll
    for (int j = 0; j < 8; j++) bcol[j] = bias[n0 + (tx << 3) + j];

    #pragma unroll
    for (int i = 0; i < 8; i++) {
        size_t off = (size_t)(m0 + (ty << 3) + i) * N + n0 + (tx << 3);
        float4 r0, r1;
        r0.x = acc[i][0] + bcol[0]; r0.y = acc[i][1] + bcol[1];
        r0.z = acc[i][2] + bcol[2]; r0.w = acc[i][3] + bcol[3];
        r1.x = acc[i][4] + bcol[4]; r1.y = acc[i][5] + bcol[5];
        r1.z = acc[i][6] + bcol[6]; r1.w = acc[i][7] + bcol[7];
        if (res) {
            float4 e0 = *(const float4*)(res + off);
            float4 e1 = *(const float4*)(res + off + 4);
            r0.x += e0.x; r0.y += e0.y; r0.z += e0.z; r0.w += e0.w;
            r1.x += e1.x; r1.y += e1.y; r1.z += e1.z; r1.w += e1.w;
        }
        *(float4*)(C + off)     = r0;
        *(float4*)(C + off + 4) = r1;
    }
}

// ---------------------------------------------------------------------------
// RoPE apply (in place on q and k), reading the precomputed table.
// ---------------------------------------------------------------------------
__global__ __launch_bounds__(256)
void rope_kernel(float* __restrict__ q, float* __restrict__ k,
                 const float2* __restrict__ tab)
{
    int idx = blockIdx.x * 256 + threadIdx.x;   // [0, MROWS*NH*64)
    float* base = (blockIdx.y == 0) ? q : k;

    int j   = idx & 63;
    int hh  = (idx >> 6) & (NH - 1);
    int row = idx >> 10;          // 64 * 16
    int pos = row & (S_ - 1);

    float2 cs = tab[(pos << 6) + j];
    float c = cs.x, s = cs.y;

    float* p = base + (size_t)row * DM + (hh << 7) + j;
    float x0 = p[0], x1 = p[64];
    p[0]  = x0 * c - x1 * s;
    p[64] = x1 * c + x0 * s;
}

// ---------------------------------------------------------------------------
// Flash attention fp32, causal. Block = (64 queries, one head, one batch).
// ---------------------------------------------------------------------------
#define QK_STRIDE 68
#define SS_STRIDE 65

__global__ __launch_bounds__(256)
void attn_kernel(const float* __restrict__ q, const float* __restrict__ k,
                 const float* __restrict__ v, float* __restrict__ o)
{
    extern __shared__ float sm[];
    float* Qs = sm;                       // 128 * 68
    float* Ks = Qs + 128 * QK_STRIDE;     // 128 * 68
    float* Vs = Ks + 128 * QK_STRIDE;     // 64 * 128
    float* Ss = Vs + 64 * 128;            // 64 * 65
    float* m_s = Ss + 64 * SS_STRIDE;
    float* l_s = m_s + 64;
    float* c_s = l_s + 64;

    int t  = threadIdx.x;
    int tx = t & 15, ty = t >> 4;
    int q0 = blockIdx.x << 6;
    int hh = blockIdx.y;
    int bb = blockIdx.z;
    size_t base = ((size_t)bb * S_) * DM + ((size_t)hh << 7);

    // ---- load Q tile, d-major transposed ----
    {
        int mm  = t >> 2;
        int d4b = t & 3;
        const float* src = q + base + (size_t)(q0 + mm) * DM;
        #pragma unroll
        for (int it = 0; it < 8; it++) {
            int d4 = d4b + (it << 2);
            float4 x = *(const float4*)(src + (d4 << 2));
            int d = d4 << 2;
            Qs[(d + 0) * QK_STRIDE + mm] = x.x;
            Qs[(d + 1) * QK_STRIDE + mm] = x.y;
            Qs[(d + 2) * QK_STRIDE + mm] = x.z;
            Qs[(d + 3) * QK_STRIDE + mm] = x.w;
        }
    }
    if (t < 64) { m_s[t] = -INFINITY; l_s[t] = 0.f; }

    float oa[4][8];
    #pragma unroll
    for (int i = 0; i < 4; i++)
        #pragma unroll
        for (int j = 0; j < 8; j++) oa[i][j] = 0.f;

    __syncthreads();

    for (int j0 = 0; j0 <= q0; j0 += 64) {
        // ---- load K tile (transposed) and V tile (natural) ----
        {
            int mm  = t >> 2;
            int d4b = t & 3;
            const float* ksrc = k + base + (size_t)(j0 + mm) * DM;
            #pragma unroll
            for (int it = 0; it < 8; it++) {
                int d4 = d4b + (it << 2);
                float4 x = *(const float4*)(ksrc + (d4 << 2));
                int d = d4 << 2;
                Ks[(d + 0) * QK_STRIDE + mm] = x.x;
                Ks[(d + 1) * QK_STRIDE + mm] = x.y;
                Ks[(d + 2) * QK_STRIDE + mm] = x.z;
                Ks[(d + 3) * QK_STRIDE + mm] = x.w;
            }
            #pragma unroll
            for (int it = 0; it < 8; it++) {
                int idx = t + (it << 8);
                int vm = idx >> 5, vd4 = idx & 31;
                float4 x = *(const float4*)(v + base + (size_t)(j0 + vm) * DM + (vd4 << 2));
                *(float4*)(Vs + vm * 128 + (vd4 << 2)) = x;
            }
        }
        __syncthreads();

        // ---- S = Q K^T (each thread 4x4 of 64x64) ----
        float s4[4][4];
        #pragma unroll
        for (int i = 0; i < 4; i++)
            #pragma unroll
            for (int j = 0; j < 4; j++) s4[i][j] = 0.f;

        #pragma unroll 4
        for (int kk = 0; kk < 128; kk++) {
            float a[4], b[4];
            *(float4*)a = *(const float4*)(Qs + kk * QK_STRIDE + (ty << 2));
            *(float4*)b = *(const float4*)(Ks + kk * QK_STRIDE + (tx << 2));
            #pragma unroll
            for (int i = 0; i < 4; i++)
                #pragma unroll
                for (int j = 0; j < 4; j++)
                    s4[i][j] += a[i] * b[j];
        }

        const float sc = 0.08838834764831845f;   // 1/sqrt(128)
        #pragma unroll
        for (int i = 0; i < 4; i++) {
            int qi = q0 + (ty << 2) + i;
            #pragma unroll
            for (int j = 0; j < 4; j++) {
                int kj = j0 + (tx << 2) + j;
                float val = s4[i][j] * sc;
                if (kj > qi) val = -INFINITY;
                Ss[((ty << 2) + i) * SS_STRIDE + (tx << 2) + j] = val;
            }
        }
        __syncthreads();

        // ---- online softmax: one warp per 8 rows ----
        {
            int w = t >> 5, lane = t & 31;
            #pragma unroll
            for (int r8 = 0; r8 < 8; r8++) {
                int r = (w << 3) + r8;
                float v0 = Ss[r * SS_STRIDE + lane];
                float v1 = Ss[r * SS_STRIDE + 32 + lane];
                float mx = fmaxf(v0, v1);
                #pragma unroll
                for (int off = 16; off; off >>= 1)
                    mx = fmaxf(mx, __shfl_xor_sync(0xffffffffu, mx, off));
                float mold = m_s[r];
                float mn = fmaxf(mold, mx);
                float e0 = expf(v0 - mn);
                float e1 = expf(v1 - mn);
                Ss[r * SS_STRIDE + lane] = e0;
                Ss[r * SS_STRIDE + 32 + lane] = e1;
                float sum = e0 + e1;
                #pragma unroll
                for (int off = 16; off; off >>= 1)
                    sum += __shfl_xor_sync(0xffffffffu, sum, off);
                if (lane == 0) {
                    float corr = expf(mold - mn);
                    l_s[r] = l_s[r] * corr + sum;
                    m_s[r] = mn;
                    c_s[r] = corr;
                }
            }
        }
        __syncthreads();

        // ---- rescale O and accumulate P @ V (each thread 4x8 of 64x128) ----
        #pragma unroll
        for (int i = 0; i < 4; i++) {
            float corr = c_s[(ty << 2) + i];
            #pragma unroll
            for (int j = 0; j < 8; j++) oa[i][j] *= corr;
        }
        #pragma unroll 4
        for (int kk = 0; kk < 64; kk++) {
            float a[4], b[8];
            #pragma unroll
            for (int i = 0; i < 4; i++)
                a[i] = Ss[((ty << 2) + i) * SS_STRIDE + kk];
            *(float4*)(&b[0]) = *(const float4*)(Vs + kk * 128 + (tx << 3));
            *(float4*)(&b[4]) = *(const float4*)(Vs + kk * 128 + (tx << 3) + 4);
            #pragma unroll
            for (int i = 0; i < 4; i++)
                #pragma unroll
                for (int j = 0; j < 8; j++)
                    oa[i][j] += a[i] * b[j];
        }
        __syncthreads();
    }

    // ---- epilogue: O / l ----
    #pragma unroll
    for (int i = 0; i < 4; i++) {
        int r = (ty << 2) + i;
        float inv = 1.0f / l_s[r];
        float* dst = o + base + (size_t)(q0 + r) * DM + (tx << 3);
        float4 r0, r1;
        r0.x = oa[i][0] * inv; r0.y = oa[i][1] * inv;
        r0.z = oa[i][2] * inv; r0.w = oa[i][3] * inv;
        r1.x = oa[i][4] * inv; r1.y = oa[i][5] * inv;
        r1.z = oa[i][6] * inv; r1.w = oa[i][7] * inv;
        *(float4*)(dst)     = r0;
        *(float4*)(dst + 4) = r1;
    }
}

// ---------------------------------------------------------------------------
// Launch
// ---------------------------------------------------------------------------
extern "C" void kernel_launch(void* const* d_in, const int* in_sizes, int n_in,
                              void* d_out, int out_size)
{
    const float* h  = (const float*)d_in[0];
    const float* wq = (const float*)d_in[1];
    const float* bq = (const float*)d_in[2];
    const float* wk = (const float*)d_in[3];
    const float* bk = (const float*)d_in[4];
    const float* wv = (const float*)d_in[5];
    const float* bv = (const float*)d_in[6];
    const float* wo = (const float*)d_in[7];
    const float* bo = (const float*)d_in[8];
    const float* lg = (const float*)d_in[9];
    const float* lb = (const float*)d_in[10];
    float* out = (float*)d_out;

    float *xn, *qb, *kb, *vb, *ob;
    float2* rt;
    cudaGetSymbolAddress((void**)&xn, g_xn);
    cudaGetSymbolAddress((void**)&qb, g_q);
    cudaGetSymbolAddress((void**)&kb, g_k);
    cudaGetSymbolAddress((void**)&vb, g_v);
    cudaGetSymbolAddress((void**)&ob, g_o);
    cudaGetSymbolAddress((void**)&rt, g_rope);

    // 0. RoPE table (accurate sincos; overlaps nothing but is tiny)
    rope_table_kernel<<<(S_ * 64 + 255) / 256, 256>>>(rt);

    // 1. LayerNorm
    ln_kernel<<<MROWS, 256>>>(h, lg, lb, xn);

    // 2. QKV projections
    dim3 gg(DM / 128, MROWS / 128);
    sgemm_nt<<<gg, 256>>>(xn, wq, bq, nullptr, qb, DM, DM);
    sgemm_nt<<<gg, 256>>>(xn, wk, bk, nullptr, kb, DM, DM);
    sgemm_nt<<<gg, 256>>>(xn, wv, bv, nullptr, vb, DM, DM);

    // 3. RoPE on q, k
    rope_kernel<<<dim3((MROWS * NH * 64) / 256, 2), 256>>>(qb, kb, rt);

    // 4. Causal flash attention
    int smem_attn = (128 * QK_STRIDE * 2 + 64 * 128 + 64 * SS_STRIDE + 192) * 4;
    cudaFuncSetAttribute(attn_kernel, cudaFuncAttributeMaxDynamicSharedMemorySize,
                         smem_attn);
    attn_kernel<<<dim3(S_ / 64, NH, B_), 256, smem_attn>>>(qb, kb, vb, ob);

    // 5. Output projection + bias + residual
    sgemm_nt<<<gg, 256>>>(ob, wo, bo, h, out, DM, DM);
}

// round 4
// speedup vs baseline: 1.6215x; 1.6215x over previous
#include <cuda_runtime.h>
#include <math.h>
#include <stdint.h>

// Problem constants (fixed shapes)
#define B_    2
#define S_    2048
#define DM    2048
#define NH    16
#define DK_   128
#define MROWS (B_ * S_)      // 4096
#define EPS_  1e-5f

// ---------------------------------------------------------------------------
// Scratch (no cudaMalloc allowed)
// ---------------------------------------------------------------------------
__device__ float g_xn[(size_t)MROWS * DM];
__device__ float g_q [(size_t)MROWS * DM];
__device__ float g_k [(size_t)MROWS * DM];
__device__ float g_v [(size_t)MROWS * DM];
__device__ float g_o [(size_t)MROWS * DM];
__device__ float2 g_rope[(size_t)S_ * 64];   // (cos, sin) per (pos, j)

// ---------------------------------------------------------------------------
// RoPE table: accurate double-precision sincos of the fp32-quantized phase.
// ---------------------------------------------------------------------------
__global__ __launch_bounds__(256)
void rope_table_kernel(float2* __restrict__ tab)
{
    int idx = blockIdx.x * 256 + threadIdx.x;     // [0, S_*64)
    if (idx >= S_ * 64) return;
    int j   = idx & 63;
    int pos = idx >> 6;
    double theta_d = 1.0 / pow(10000.0, (double)j / 64.0);
    float  theta_f = (float)theta_d;
    float fr = (float)pos * theta_f;
    double dfr = (double)fr;
    tab[idx] = make_float2((float)cos(dfr), (float)sin(dfr));
}

// ---------------------------------------------------------------------------
// LayerNorm
// ---------------------------------------------------------------------------
__global__ __launch_bounds__(256)
void ln_kernel(const float* __restrict__ x, const float* __restrict__ g,
               const float* __restrict__ bb, float* __restrict__ out)
{
    int row = blockIdx.x;
    int t = threadIdx.x;
    const float4* xr = (const float4*)(x + (size_t)row * DM);
    float4* orow = (float4*)(out + (size_t)row * DM);

    float4 v0 = xr[t];
    float4 v1 = xr[t + 256];
    float sum = v0.x + v0.y + v0.z + v0.w + v1.x + v1.y + v1.z + v1.w;
    float sq  = v0.x*v0.x + v0.y*v0.y + v0.z*v0.z + v0.w*v0.w
              + v1.x*v1.x + v1.y*v1.y + v1.z*v1.z + v1.w*v1.w;

    #pragma unroll
    for (int off = 16; off; off >>= 1) {
        sum += __shfl_xor_sync(0xffffffffu, sum, off);
        sq  += __shfl_xor_sync(0xffffffffu, sq,  off);
    }
    __shared__ float s_sum[8], s_sq[8];
    int w = t >> 5;
    if ((t & 31) == 0) { s_sum[w] = sum; s_sq[w] = sq; }
    __syncthreads();
    if (t < 32) {
        float a = (t < 8) ? s_sum[t] : 0.f;
        float b = (t < 8) ? s_sq[t]  : 0.f;
        #pragma unroll
        for (int off = 4; off; off >>= 1) {
            a += __shfl_xor_sync(0xffffffffu, a, off);
            b += __shfl_xor_sync(0xffffffffu, b, off);
        }
        if (t == 0) { s_sum[0] = a; s_sq[0] = b; }
    }
    __syncthreads();

    float mu  = s_sum[0] * (1.0f / DM);
    float var = s_sq[0] * (1.0f / DM) - mu * mu;
    float rstd = rsqrtf(var + EPS_);

    const float4* g4 = (const float4*)g;
    const float4* b4 = (const float4*)bb;
    {
        float4 gv = g4[t], bv = b4[t], o;
        o.x = (v0.x - mu) * rstd * gv.x + bv.x;
        o.y = (v0.y - mu) * rstd * gv.y + bv.y;
        o.z = (v0.z - mu) * rstd * gv.z + bv.z;
        o.w = (v0.w - mu) * rstd * gv.w + bv.w;
        orow[t] = o;
    }
    {
        float4 gv = g4[t + 256], bv = b4[t + 256], o;
        o.x = (v1.x - mu) * rstd * gv.x + bv.x;
        o.y = (v1.y - mu) * rstd * gv.y + bv.y;
        o.z = (v1.z - mu) * rstd * gv.z + bv.z;
        o.w = (v1.w - mu) * rstd * gv.w + bv.w;
        orow[t + 256] = o;
    }
}

// ---------------------------------------------------------------------------
// TF32 tensor-core GEMM NT: C[M,N] = A[M,K] * W[N,K]^T + bias[N] (+ res)
// Block 128x128, BK=16, 256 threads (8 warps, 2x4), warp tile 64x32.
// Smem holds tf32 values pre-permuted into exact mma fragment order:
//   A frag (m16n8k8): a0=(r,c) a1=(r+8,c) a2=(r,c+4) a3=(r+8,c+4),
//     lane l -> r=l/4, c=l%4.  As idx: ksub*1024 + msub*128 + lane*4 + reg
//   B frag: b0=(k=l%4, n=l/4) b1=(k+4, n).  Bs idx: ksub*1024 + nsub*64 + lane*2 + reg
// ---------------------------------------------------------------------------
__device__ __forceinline__ uint32_t f2tf32(float f)
{
    uint32_t r;
    asm("cvt.rna.tf32.f32 %0, %1;" : "=r"(r) : "f"(f));
    return r;
}

__device__ __forceinline__ void mma_tf32(float* c, const uint4& a, const uint2& b)
{
    asm volatile(
        "mma.sync.aligned.m16n8k8.row.col.f32.tf32.tf32.f32 "
        "{%0,%1,%2,%3}, {%4,%5,%6,%7}, {%8,%9}, {%0,%1,%2,%3};\n"
        : "+f"(c[0]), "+f"(c[1]), "+f"(c[2]), "+f"(c[3])
        : "r"(a.x), "r"(a.y), "r"(a.z), "r"(a.w), "r"(b.x), "r"(b.y));
}

__global__ __launch_bounds__(256, 2)
void tgemm_nt(const float* __restrict__ A, const float* __restrict__ W,
              const float* __restrict__ bias, const float* __restrict__ res,
              float* __restrict__ C, int K, int N)
{
    __shared__ uint32_t As[2][2048];   // 2 buf x (2 ksub x 8 msub x 32 lane x 4)
    __shared__ uint32_t Bs[2][2048];   // 2 buf x (2 ksub x 16 nsub x 32 lane x 2)

    int t = threadIdx.x;
    int lane = t & 31;
    int w = t >> 5;
    int wm = w >> 2, wn = w & 3;       // warp grid 2(m) x 4(n)
    int m0 = blockIdx.y << 7, n0 = blockIdx.x << 7;

    // loader: thread t covers rows (t>>2) and (t>>2)+64, k-quad kq = t&3
    int lm = t >> 2;        // 0..63
    int kq = t & 3;         // float4 index within BK=16
    const float* Ag = A + (size_t)(m0 + lm) * K + (kq << 2);
    const float* Wg = W + (size_t)(n0 + lm) * K + (kq << 2);

    // STS base offsets (element i at +i*4 for A, +i*2 for B)
    auto a_sts = [&](int m) {
        return (kq >> 1) * 1024 + (m >> 4) * 128 + (m & 7) * 16 +
               (((kq & 1) << 1) | ((m >> 3) & 1));
    };
    auto b_sts = [&](int n) {
        return (kq >> 1) * 1024 + (n >> 3) * 64 + (n & 7) * 8 + (kq & 1);
    };
    int aoff0 = a_sts(lm), aoff1 = a_sts(lm + 64);
    int boff0 = b_sts(lm), boff1 = b_sts(lm + 64);

    float acc[4][4][4];
    #pragma unroll
    for (int i = 0; i < 4; i++)
        #pragma unroll
        for (int j = 0; j < 4; j++)
            #pragma unroll
            for (int r = 0; r < 4; r++) acc[i][j][r] = 0.f;

    const int nIter = K >> 4;    // K/16

    // prologue: load tile 0
    float4 aR0 = *(const float4*)(Ag);
    float4 aR1 = *(const float4*)(Ag + (size_t)64 * K);
    float4 bR0 = *(const float4*)(Wg);
    float4 bR1 = *(const float4*)(Wg + (size_t)64 * K);
    {
        uint32_t* pa = As[0]; uint32_t* pb = Bs[0];
        pa[aoff0+0]=f2tf32(aR0.x); pa[aoff0+4]=f2tf32(aR0.y); pa[aoff0+8]=f2tf32(aR0.z); pa[aoff0+12]=f2tf32(aR0.w);
        pa[aoff1+0]=f2tf32(aR1.x); pa[aoff1+4]=f2tf32(aR1.y); pa[aoff1+8]=f2tf32(aR1.z); pa[aoff1+12]=f2tf32(aR1.w);
        pb[boff0+0]=f2tf32(bR0.x); pb[boff0+2]=f2tf32(bR0.y); pb[boff0+4]=f2tf32(bR0.z); pb[boff0+6]=f2tf32(bR0.w);
        pb[boff1+0]=f2tf32(bR1.x); pb[boff1+2]=f2tf32(bR1.y); pb[boff1+4]=f2tf32(bR1.z); pb[boff1+6]=f2tf32(bR1.w);
    }
    __syncthreads();

    for (int it = 0; it < nIter; it++) {
        int buf = it & 1;
        // prefetch next tile into registers
        if (it + 1 < nIter) {
            const float* ag = Ag + (it + 1) * 16;
            const float* wg = Wg + (it + 1) * 16;
            aR0 = *(const float4*)(ag);
            aR1 = *(const float4*)(ag + (size_t)64 * K);
            bR0 = *(const float4*)(wg);
            bR1 = *(const float4*)(wg + (size_t)64 * K);
        }

        // compute from buf
        #pragma unroll
        for (int ks = 0; ks < 2; ks++) {
            uint4 af[4]; uint2 bf[4];
            #pragma unroll
            for (int i = 0; i < 4; i++)
                af[i] = *(const uint4*)&As[buf][ks * 1024 + (wm * 4 + i) * 128 + lane * 4];
            #pragma unroll
            for (int j = 0; j < 4; j++)
                bf[j] = *(const uint2*)&Bs[buf][ks * 1024 + (wn * 4 + j) * 64 + lane * 2];
            #pragma unroll
            for (int i = 0; i < 4; i++)
                #pragma unroll
                for (int j = 0; j < 4; j++)
                    mma_tf32(acc[i][j], af[i], bf[j]);
        }

        // stage next tile into the other buffer
        if (it + 1 < nIter) {
            uint32_t* pa = As[buf ^ 1]; uint32_t* pb = Bs[buf ^ 1];
            pa[aoff0+0]=f2tf32(aR0.x); pa[aoff0+4]=f2tf32(aR0.y); pa[aoff0+8]=f2tf32(aR0.z); pa[aoff0+12]=f2tf32(aR0.w);
            pa[aoff1+0]=f2tf32(aR1.x); pa[aoff1+4]=f2tf32(aR1.y); pa[aoff1+8]=f2tf32(aR1.z); pa[aoff1+12]=f2tf32(aR1.w);
            pb[boff0+0]=f2tf32(bR0.x); pb[boff0+2]=f2tf32(bR0.y); pb[boff0+4]=f2tf32(bR0.z); pb[boff0+6]=f2tf32(bR0.w);
            pb[boff1+0]=f2tf32(bR1.x); pb[boff1+2]=f2tf32(bR1.y); pb[boff1+4]=f2tf32(bR1.z); pb[boff1+6]=f2tf32(bR1.w);
        }
        __syncthreads();
    }

    // epilogue: C frag c0=(r, 2c) c1=(r, 2c+1) c2=(r+8, 2c) c3=(r+8, 2c+1)
    #pragma unroll
    for (int i = 0; i < 4; i++) {
        int r0 = m0 + wm * 64 + i * 16 + (lane >> 2);
        #pragma unroll
        for (int j = 0; j < 4; j++) {
            int c = n0 + wn * 32 + j * 8 + (lane & 3) * 2;
            float b0 = bias[c], b1 = bias[c + 1];
            size_t o0 = (size_t)r0 * N + c;
            size_t o1 = (size_t)(r0 + 8) * N + c;
            float2 v0 = make_float2(acc[i][j][0] + b0, acc[i][j][1] + b1);
            float2 v1 = make_float2(acc[i][j][2] + b0, acc[i][j][3] + b1);
            if (res) {
                float2 e0 = *(const float2*)(res + o0);
                float2 e1 = *(const float2*)(res + o1);
                v0.x += e0.x; v0.y += e0.y;
                v1.x += e1.x; v1.y += e1.y;
            }
            *(float2*)(C + o0) = v0;
            *(float2*)(C + o1) = v1;
        }
    }
}

// ---------------------------------------------------------------------------
// RoPE apply
// ---------------------------------------------------------------------------
__global__ __launch_bounds__(256)
void rope_kernel(float* __restrict__ q, float* __restrict__ k,
                 const float2* __restrict__ tab)
{
    int idx = blockIdx.x * 256 + threadIdx.x;   // [0, MROWS*NH*64)
    float* base = (blockIdx.y == 0) ? q : k;

    int j   = idx & 63;
    int hh  = (idx >> 6) & (NH - 1);
    int row = idx >> 10;
    int pos = row & (S_ - 1);

    float2 cs = tab[(pos << 6) + j];
    float c = cs.x, s = cs.y;

    float* p = base + (size_t)row * DM + (hh << 7) + j;
    float x0 = p[0], x1 = p[64];
    p[0]  = x0 * c - x1 * s;
    p[64] = x1 * c + x0 * s;
}

// ---------------------------------------------------------------------------
// Flash attention fp32, causal
// ---------------------------------------------------------------------------
#define QK_STRIDE 68
#define SS_STRIDE 65

__global__ __launch_bounds__(256)
void attn_kernel(const float* __restrict__ q, const float* __restrict__ k,
                 const float* __restrict__ v, float* __restrict__ o)
{
    extern __shared__ float sm[];
    float* Qs = sm;
    float* Ks = Qs + 128 * QK_STRIDE;
    float* Vs = Ks + 128 * QK_STRIDE;
    float* Ss = Vs + 64 * 128;
    float* m_s = Ss + 64 * SS_STRIDE;
    float* l_s = m_s + 64;
    float* c_s = l_s + 64;

    int t  = threadIdx.x;
    int tx = t & 15, ty = t >> 4;
    int q0 = blockIdx.x << 6;
    int hh = blockIdx.y;
    int bb = blockIdx.z;
    size_t base = ((size_t)bb * S_) * DM + ((size_t)hh << 7);

    {
        int mm  = t >> 2;
        int d4b = t & 3;
        const float* src = q + base + (size_t)(q0 + mm) * DM;
        #pragma unroll
        for (int it = 0; it < 8; it++) {
            int d4 = d4b + (it << 2);
            float4 x = *(const float4*)(src + (d4 << 2));
            int d = d4 << 2;
            Qs[(d + 0) * QK_STRIDE + mm] = x.x;
            Qs[(d + 1) * QK_STRIDE + mm] = x.y;
            Qs[(d + 2) * QK_STRIDE + mm] = x.z;
            Qs[(d + 3) * QK_STRIDE + mm] = x.w;
        }
    }
    if (t < 64) { m_s[t] = -INFINITY; l_s[t] = 0.f; }

    float oa[4][8];
    #pragma unroll
    for (int i = 0; i < 4; i++)
        #pragma unroll
        for (int j = 0; j < 8; j++) oa[i][j] = 0.f;

    __syncthreads();

    for (int j0 = 0; j0 <= q0; j0 += 64) {
        {
            int mm  = t >> 2;
            int d4b = t & 3;
            const float* ksrc = k + base + (size_t)(j0 + mm) * DM;
            #pragma unroll
            for (int it = 0; it < 8; it++) {
                int d4 = d4b + (it << 2);
                float4 x = *(const float4*)(ksrc + (d4 << 2));
                int d = d4 << 2;
                Ks[(d + 0) * QK_STRIDE + mm] = x.x;
                Ks[(d + 1) * QK_STRIDE + mm] = x.y;
                Ks[(d + 2) * QK_STRIDE + mm] = x.z;
                Ks[(d + 3) * QK_STRIDE + mm] = x.w;
            }
            #pragma unroll
            for (int it = 0; it < 8; it++) {
                int idx = t + (it << 8);
                int vm = idx >> 5, vd4 = idx & 31;
                float4 x = *(const float4*)(v + base + (size_t)(j0 + vm) * DM + (vd4 << 2));
                *(float4*)(Vs + vm * 128 + (vd4 << 2)) = x;
            }
        }
        __syncthreads();

        float s4[4][4];
        #pragma unroll
        for (int i = 0; i < 4; i++)
            #pragma unroll
            for (int j = 0; j < 4; j++) s4[i][j] = 0.f;

        #pragma unroll 4
        for (int kk = 0; kk < 128; kk++) {
            float a[4], b[4];
            *(float4*)a = *(const float4*)(Qs + kk * QK_STRIDE + (ty << 2));
            *(float4*)b = *(const float4*)(Ks + kk * QK_STRIDE + (tx << 2));
            #pragma unroll
            for (int i = 0; i < 4; i++)
                #pragma unroll
                for (int j = 0; j < 4; j++)
                    s4[i][j] += a[i] * b[j];
        }

        const float sc = 0.08838834764831845f;
        #pragma unroll
        for (int i = 0; i < 4; i++) {
            int qi = q0 + (ty << 2) + i;
            #pragma unroll
            for (int j = 0; j < 4; j++) {
                int kj = j0 + (tx << 2) + j;
                float val = s4[i][j] * sc;
                if (kj > qi) val = -INFINITY;
                Ss[((ty << 2) + i) * SS_STRIDE + (tx << 2) + j] = val;
            }
        }
        __syncthreads();

        {
            int w = t >> 5, lane = t & 31;
            #pragma unroll
            for (int r8 = 0; r8 < 8; r8++) {
                int r = (w << 3) + r8;
                float v0 = Ss[r * SS_STRIDE + lane];
                float v1 = Ss[r * SS_STRIDE + 32 + lane];
                float mx = fmaxf(v0, v1);
                #pragma unroll
                for (int off = 16; off; off >>= 1)
                    mx = fmaxf(mx, __shfl_xor_sync(0xffffffffu, mx, off));
                float mold = m_s[r];
                float mn = fmaxf(mold, mx);
                float e0 = expf(v0 - mn);
                float e1 = expf(v1 - mn);
                Ss[r * SS_STRIDE + lane] = e0;
                Ss[r * SS_STRIDE + 32 + lane] = e1;
                float sum = e0 + e1;
                #pragma unroll
                for (int off = 16; off; off >>= 1)
                    sum += __shfl_xor_sync(0xffffffffu, sum, off);
                if (lane == 0) {
                    float corr = expf(mold - mn);
                    l_s[r] = l_s[r] * corr + sum;
                    m_s[r] = mn;
                    c_s[r] = corr;
                }
            }
        }
        __syncthreads();

        #pragma unroll
        for (int i = 0; i < 4; i++) {
            float corr = c_s[(ty << 2) + i];
            #pragma unroll
            for (int j = 0; j < 8; j++) oa[i][j] *= corr;
        }
        #pragma unroll 4
        for (int kk = 0; kk < 64; kk++) {
            float a[4], b[8];
            #pragma unroll
            for (int i = 0; i < 4; i++)
                a[i] = Ss[((ty << 2) + i) * SS_STRIDE + kk];
            *(float4*)(&b[0]) = *(const float4*)(Vs + kk * 128 + (tx << 3));
            *(float4*)(&b[4]) = *(const float4*)(Vs + kk * 128 + (tx << 3) + 4);
            #pragma unroll
            for (int i = 0; i < 4; i++)
                #pragma unroll
                for (int j = 0; j < 8; j++)
                    oa[i][j] += a[i] * b[j];
        }
        __syncthreads();
    }

    #pragma unroll
    for (int i = 0; i < 4; i++) {
        int r = (ty << 2) + i;
        float inv = 1.0f / l_s[r];
        float* dst = o + base + (size_t)(q0 + r) * DM + (tx << 3);
        float4 r0, r1;
        r0.x = oa[i][0] * inv; r0.y = oa[i][1] * inv;
        r0.z = oa[i][2] * inv; r0.w = oa[i][3] * inv;
        r1.x = oa[i][4] * inv; r1.y = oa[i][5] * inv;
        r1.z = oa[i][6] * inv; r1.w = oa[i][7] * inv;
        *(float4*)(dst)     = r0;
        *(float4*)(dst + 4) = r1;
    }
}

// ---------------------------------------------------------------------------
// Launch
// ---------------------------------------------------------------------------
extern "C" void kernel_launch(void* const* d_in, const int* in_sizes, int n_in,
                              void* d_out, int out_size)
{
    const float* h  = (const float*)d_in[0];
    const float* wq = (const float*)d_in[1];
    const float* bq = (const float*)d_in[2];
    const float* wk = (const float*)d_in[3];
    const float* bk = (const float*)d_in[4];
    const float* wv = (const float*)d_in[5];
    const float* bv = (const float*)d_in[6];
    const float* wo = (const float*)d_in[7];
    const float* bo = (const float*)d_in[8];
    const float* lg = (const float*)d_in[9];
    const float* lb = (const float*)d_in[10];
    float* out = (float*)d_out;

    float *xn, *qb, *kb, *vb, *ob;
    float2* rt;
    cudaGetSymbolAddress((void**)&xn, g_xn);
    cudaGetSymbolAddress((void**)&qb, g_q);
    cudaGetSymbolAddress((void**)&kb, g_k);
    cudaGetSymbolAddress((void**)&vb, g_v);
    cudaGetSymbolAddress((void**)&ob, g_o);
    cudaGetSymbolAddress((void**)&rt, g_rope);

    // 0. RoPE table
    rope_table_kernel<<<(S_ * 64 + 255) / 256, 256>>>(rt);

    // 1. LayerNorm
    ln_kernel<<<MROWS, 256>>>(h, lg, lb, xn);

    // 2. QKV projections (tf32 tensor cores)
    dim3 gg(DM / 128, MROWS / 128);
    tgemm_nt<<<gg, 256>>>(xn, wq, bq, nullptr, qb, DM, DM);
    tgemm_nt<<<gg, 256>>>(xn, wk, bk, nullptr, kb, DM, DM);
    tgemm_nt<<<gg, 256>>>(xn, wv, bv, nullptr, vb, DM, DM);

    // 3. RoPE on q, k
    rope_kernel<<<dim3((MROWS * NH * 64) / 256, 2), 256>>>(qb, kb, rt);

    // 4. Causal flash attention
    int smem_attn = (128 * QK_STRIDE * 2 + 64 * 128 + 64 * SS_STRIDE + 192) * 4;
    cudaFuncSetAttribute(attn_kernel, cudaFuncAttributeMaxDynamicSharedMemorySize,
                         smem_attn);
    attn_kernel<<<dim3(S_ / 64, NH, B_), 256, smem_attn>>>(qb, kb, vb, ob);

    // 5. Output projection + bias + residual (tf32)
    tgemm_nt<<<gg, 256>>>(ob, wo, bo, h, out, DM, DM);
}

// round 5
// speedup vs baseline: 2.3236x; 1.4330x over previous
#include <cuda_runtime.h>
#include <math.h>
#include <stdint.h>

// Problem constants (fixed shapes)
#define B_    2
#define S_    2048
#define DM    2048
#define NH    16
#define DK_   128
#define MROWS (B_ * S_)      // 4096
#define EPS_  1e-5f

// ---------------------------------------------------------------------------
// Scratch (no cudaMalloc allowed)
// ---------------------------------------------------------------------------
__device__ float g_xn[(size_t)MROWS * DM];
__device__ float g_q [(size_t)MROWS * DM];
__device__ float g_k [(size_t)MROWS * DM];
__device__ float g_v [(size_t)MROWS * DM];
__device__ float g_o [(size_t)MROWS * DM];
__device__ float2 g_rope[(size_t)S_ * 64];   // (cos, sin) per (pos, j)

// ---------------------------------------------------------------------------
// tf32 helpers
// ---------------------------------------------------------------------------
__device__ __forceinline__ uint32_t f2tf32(float f)
{
    uint32_t r;
    asm("cvt.rna.tf32.f32 %0, %1;" : "=r"(r) : "f"(f));
    return r;
}

__device__ __forceinline__ void mma_tf32(float* c, const uint4& a, const uint2& b)
{
    asm volatile(
        "mma.sync.aligned.m16n8k8.row.col.f32.tf32.tf32.f32 "
        "{%0,%1,%2,%3}, {%4,%5,%6,%7}, {%8,%9}, {%0,%1,%2,%3};\n"
        : "+f"(c[0]), "+f"(c[1]), "+f"(c[2]), "+f"(c[3])
        : "r"(a.x), "r"(a.y), "r"(a.z), "r"(a.w), "r"(b.x), "r"(b.y));
}

// ---------------------------------------------------------------------------
// RoPE table: accurate double-precision sincos of the fp32-quantized phase.
// ---------------------------------------------------------------------------
__global__ __launch_bounds__(256)
void rope_table_kernel(float2* __restrict__ tab)
{
    int idx = blockIdx.x * 256 + threadIdx.x;     // [0, S_*64)
    if (idx >= S_ * 64) return;
    int j   = idx & 63;
    int pos = idx >> 6;
    double theta_d = 1.0 / pow(10000.0, (double)j / 64.0);
    float  theta_f = (float)theta_d;
    float fr = (float)pos * theta_f;
    double dfr = (double)fr;
    tab[idx] = make_float2((float)cos(dfr), (float)sin(dfr));
}

// ---------------------------------------------------------------------------
// LayerNorm
// ---------------------------------------------------------------------------
__global__ __launch_bounds__(256)
void ln_kernel(const float* __restrict__ x, const float* __restrict__ g,
               const float* __restrict__ bb, float* __restrict__ out)
{
    int row = blockIdx.x;
    int t = threadIdx.x;
    const float4* xr = (const float4*)(x + (size_t)row * DM);
    float4* orow = (float4*)(out + (size_t)row * DM);

    float4 v0 = xr[t];
    float4 v1 = xr[t + 256];
    float sum = v0.x + v0.y + v0.z + v0.w + v1.x + v1.y + v1.z + v1.w;
    float sq  = v0.x*v0.x + v0.y*v0.y + v0.z*v0.z + v0.w*v0.w
              + v1.x*v1.x + v1.y*v1.y + v1.z*v1.z + v1.w*v1.w;

    #pragma unroll
    for (int off = 16; off; off >>= 1) {
        sum += __shfl_xor_sync(0xffffffffu, sum, off);
        sq  += __shfl_xor_sync(0xffffffffu, sq,  off);
    }
    __shared__ float s_sum[8], s_sq[8];
    int w = t >> 5;
    if ((t & 31) == 0) { s_sum[w] = sum; s_sq[w] = sq; }
    __syncthreads();
    if (t < 32) {
        float a = (t < 8) ? s_sum[t] : 0.f;
        float b = (t < 8) ? s_sq[t]  : 0.f;
        #pragma unroll
        for (int off = 4; off; off >>= 1) {
            a += __shfl_xor_sync(0xffffffffu, a, off);
            b += __shfl_xor_sync(0xffffffffu, b, off);
        }
        if (t == 0) { s_sum[0] = a; s_sq[0] = b; }
    }
    __syncthreads();

    float mu  = s_sum[0] * (1.0f / DM);
    float var = s_sq[0] * (1.0f / DM) - mu * mu;
    float rstd = rsqrtf(var + EPS_);

    const float4* g4 = (const float4*)g;
    const float4* b4 = (const float4*)bb;
    {
        float4 gv = g4[t], bv = b4[t], o;
        o.x = (v0.x - mu) * rstd * gv.x + bv.x;
        o.y = (v0.y - mu) * rstd * gv.y + bv.y;
        o.z = (v0.z - mu) * rstd * gv.z + bv.z;
        o.w = (v0.w - mu) * rstd * gv.w + bv.w;
        orow[t] = o;
    }
    {
        float4 gv = g4[t + 256], bv = b4[t + 256], o;
        o.x = (v1.x - mu) * rstd * gv.x + bv.x;
        o.y = (v1.y - mu) * rstd * gv.y + bv.y;
        o.z = (v1.z - mu) * rstd * gv.z + bv.z;
        o.w = (v1.w - mu) * rstd * gv.w + bv.w;
        orow[t + 256] = o;
    }
}

// ---------------------------------------------------------------------------
// TF32 tensor-core GEMM NT (unchanged from R2/R4)
// ---------------------------------------------------------------------------
__global__ __launch_bounds__(256, 2)
void tgemm_nt(const float* __restrict__ A, const float* __restrict__ W,
              const float* __restrict__ bias, const float* __restrict__ res,
              float* __restrict__ C, int K, int N)
{
    __shared__ uint32_t As[2][2048];
    __shared__ uint32_t Bs[2][2048];

    int t = threadIdx.x;
    int lane = t & 31;
    int w = t >> 5;
    int wm = w >> 2, wn = w & 3;
    int m0 = blockIdx.y << 7, n0 = blockIdx.x << 7;

    int lm = t >> 2;
    int kq = t & 3;
    const float* Ag = A + (size_t)(m0 + lm) * K + (kq << 2);
    const float* Wg = W + (size_t)(n0 + lm) * K + (kq << 2);

    auto a_sts = [&](int m) {
        return (kq >> 1) * 1024 + (m >> 4) * 128 + (m & 7) * 16 +
               (((kq & 1) << 1) | ((m >> 3) & 1));
    };
    auto b_sts = [&](int n) {
        return (kq >> 1) * 1024 + (n >> 3) * 64 + (n & 7) * 8 + (kq & 1);
    };
    int aoff0 = a_sts(lm), aoff1 = a_sts(lm + 64);
    int boff0 = b_sts(lm), boff1 = b_sts(lm + 64);

    float acc[4][4][4];
    #pragma unroll
    for (int i = 0; i < 4; i++)
        #pragma unroll
        for (int j = 0; j < 4; j++)
            #pragma unroll
            for (int r = 0; r < 4; r++) acc[i][j][r] = 0.f;

    const int nIter = K >> 4;

    float4 aR0 = *(const float4*)(Ag);
    float4 aR1 = *(const float4*)(Ag + (size_t)64 * K);
    float4 bR0 = *(const float4*)(Wg);
    float4 bR1 = *(const float4*)(Wg + (size_t)64 * K);
    {
        uint32_t* pa = As[0]; uint32_t* pb = Bs[0];
        pa[aoff0+0]=f2tf32(aR0.x); pa[aoff0+4]=f2tf32(aR0.y); pa[aoff0+8]=f2tf32(aR0.z); pa[aoff0+12]=f2tf32(aR0.w);
        pa[aoff1+0]=f2tf32(aR1.x); pa[aoff1+4]=f2tf32(aR1.y); pa[aoff1+8]=f2tf32(aR1.z); pa[aoff1+12]=f2tf32(aR1.w);
        pb[boff0+0]=f2tf32(bR0.x); pb[boff0+2]=f2tf32(bR0.y); pb[boff0+4]=f2tf32(bR0.z); pb[boff0+6]=f2tf32(bR0.w);
        pb[boff1+0]=f2tf32(bR1.x); pb[boff1+2]=f2tf32(bR1.y); pb[boff1+4]=f2tf32(bR1.z); pb[boff1+6]=f2tf32(bR1.w);
    }
    __syncthreads();

    for (int it = 0; it < nIter; it++) {
        int buf = it & 1;
        if (it + 1 < nIter) {
            const float* ag = Ag + (it + 1) * 16;
            const float* wg = Wg + (it + 1) * 16;
            aR0 = *(const float4*)(ag);
            aR1 = *(const float4*)(ag + (size_t)64 * K);
            bR0 = *(const float4*)(wg);
            bR1 = *(const float4*)(wg + (size_t)64 * K);
        }

        #pragma unroll
        for (int ks = 0; ks < 2; ks++) {
            uint4 af[4]; uint2 bf[4];
            #pragma unroll
            for (int i = 0; i < 4; i++)
                af[i] = *(const uint4*)&As[buf][ks * 1024 + (wm * 4 + i) * 128 + lane * 4];
            #pragma unroll
            for (int j = 0; j < 4; j++)
                bf[j] = *(const uint2*)&Bs[buf][ks * 1024 + (wn * 4 + j) * 64 + lane * 2];
            #pragma unroll
            for (int i = 0; i < 4; i++)
                #pragma unroll
                for (int j = 0; j < 4; j++)
                    mma_tf32(acc[i][j], af[i], bf[j]);
        }

        if (it + 1 < nIter) {
            uint32_t* pa = As[buf ^ 1]; uint32_t* pb = Bs[buf ^ 1];
            pa[aoff0+0]=f2tf32(aR0.x); pa[aoff0+4]=f2tf32(aR0.y); pa[aoff0+8]=f2tf32(aR0.z); pa[aoff0+12]=f2tf32(aR0.w);
            pa[aoff1+0]=f2tf32(aR1.x); pa[aoff1+4]=f2tf32(aR1.y); pa[aoff1+8]=f2tf32(aR1.z); pa[aoff1+12]=f2tf32(aR1.w);
            pb[boff0+0]=f2tf32(bR0.x); pb[boff0+2]=f2tf32(bR0.y); pb[boff0+4]=f2tf32(bR0.z); pb[boff0+6]=f2tf32(bR0.w);
            pb[boff1+0]=f2tf32(bR1.x); pb[boff1+2]=f2tf32(bR1.y); pb[boff1+4]=f2tf32(bR1.z); pb[boff1+6]=f2tf32(bR1.w);
        }
        __syncthreads();
    }

    #pragma unroll
    for (int i = 0; i < 4; i++) {
        int r0 = m0 + wm * 64 + i * 16 + (lane >> 2);
        #pragma unroll
        for (int j = 0; j < 4; j++) {
            int c = n0 + wn * 32 + j * 8 + (lane & 3) * 2;
            float b0 = bias[c], b1 = bias[c + 1];
            size_t o0 = (size_t)r0 * N + c;
            size_t o1 = (size_t)(r0 + 8) * N + c;
            float2 v0 = make_float2(acc[i][j][0] + b0, acc[i][j][1] + b1);
            float2 v1 = make_float2(acc[i][j][2] + b0, acc[i][j][3] + b1);
            if (res) {
                float2 e0 = *(const float2*)(res + o0);
                float2 e1 = *(const float2*)(res + o1);
                v0.x += e0.x; v0.y += e0.y;
                v1.x += e1.x; v1.y += e1.y;
            }
            *(float2*)(C + o0) = v0;
            *(float2*)(C + o1) = v1;
        }
    }
}

// ---------------------------------------------------------------------------
// RoPE apply
// ---------------------------------------------------------------------------
__global__ __launch_bounds__(256)
void rope_kernel(float* __restrict__ q, float* __restrict__ k,
                 const float2* __restrict__ tab)
{
    int idx = blockIdx.x * 256 + threadIdx.x;
    float* base = (blockIdx.y == 0) ? q : k;

    int j   = idx & 63;
    int hh  = (idx >> 6) & (NH - 1);
    int row = idx >> 10;
    int pos = row & (S_ - 1);

    float2 cs = tab[(pos << 6) + j];
    float c = cs.x, s = cs.y;

    float* p = base + (size_t)row * DM + (hh << 7) + j;
    float x0 = p[0], x1 = p[64];
    p[0]  = x0 * c - x1 * s;
    p[64] = x1 * c + x0 * s;
}

// ---------------------------------------------------------------------------
// TF32 tensor-core flash attention, causal.
// Block = 64 queries x (1 head, 1 batch), 256 threads (8 warps).
// Q/K natural layout pad 132 (A/B frag LDS conflict-free: bank 4*(l/4)+l%4)
// V   natural layout pad 136 (PV B-frag LDS conflict-free: bank 8*(l%4)+l/4)
// Ss  pad 68 (P A-frag LDS conflict-free)
// S phase: 8 warps = 4(m) x 2(n), warp tile 16x32.
// PV phase: same warps = 4(m rows) x 2(n=d half), warp tile 16x64.
// ---------------------------------------------------------------------------
#define QKPAD 132
#define VPAD  136
#define SSPAD 68

__global__ __launch_bounds__(256)
void attn_tc_kernel(const float* __restrict__ q, const float* __restrict__ k,
                    const float* __restrict__ v, float* __restrict__ o)
{
    extern __shared__ float sm[];
    uint32_t* Qs = (uint32_t*)sm;             // 64 * 132 (tf32)
    uint32_t* Ks = Qs + 64 * QKPAD;           // 64 * 132 (tf32)
    uint32_t* Vs = Ks + 64 * QKPAD;           // 64 * 136 (tf32)
    float* Ss  = (float*)(Vs + 64 * VPAD);    // 64 * 68
    float* m_s = Ss + 64 * SSPAD;
    float* l_s = m_s + 64;
    float* c_s = l_s + 64;

    int t = threadIdx.x;
    int lane = t & 31;
    int w = t >> 5;
    int wm = w >> 1;          // 0..3 : row group (16 rows)
    int wn = w & 1;           // 0..1 : col group
    int lr = lane >> 2;       // 0..7
    int lc = lane & 3;        // 0..3

    int q0 = blockIdx.x << 6;
    size_t base = ((size_t)blockIdx.z * S_) * DM + ((size_t)blockIdx.y << 7);

    // ---- load Q tile (64 x 128) -> tf32, natural, pad 132 ----
    #pragma unroll
    for (int it = 0; it < 8; it++) {
        int idx = t + (it << 8);          // 0..2047
        int r = idx >> 5, c4 = idx & 31;
        float4 x = *(const float4*)(q + base + (size_t)(q0 + r) * DM + (c4 << 2));
        uint32_t* dst = Qs + r * QKPAD + (c4 << 2);
        dst[0] = f2tf32(x.x); dst[1] = f2tf32(x.y);
        dst[2] = f2tf32(x.z); dst[3] = f2tf32(x.w);
    }
    if (t < 64) { m_s[t] = -INFINITY; l_s[t] = 0.f; }

    float oacc[8][4];
    #pragma unroll
    for (int i = 0; i < 8; i++)
        #pragma unroll
        for (int r = 0; r < 4; r++) oacc[i][r] = 0.f;

    for (int j0 = 0; j0 <= q0; j0 += 64) {
        // ---- load K, V tiles -> tf32 ----
        #pragma unroll
        for (int it = 0; it < 8; it++) {
            int idx = t + (it << 8);
            int r = idx >> 5, c4 = idx & 31;
            size_t goff = base + (size_t)(j0 + r) * DM + (c4 << 2);
            float4 xk = *(const float4*)(k + goff);
            uint32_t* dk = Ks + r * QKPAD + (c4 << 2);
            dk[0] = f2tf32(xk.x); dk[1] = f2tf32(xk.y);
            dk[2] = f2tf32(xk.z); dk[3] = f2tf32(xk.w);
            float4 xv = *(const float4*)(v + goff);
            uint32_t* dv = Vs + r * VPAD + (c4 << 2);
            dv[0] = f2tf32(xv.x); dv[1] = f2tf32(xv.y);
            dv[2] = f2tf32(xv.z); dv[3] = f2tf32(xv.w);
        }
        __syncthreads();

        // ---- S = Q K^T : warp tile rows [wm*16,+16), cols [wn*32,+32) ----
        float sacc[4][4];
        #pragma unroll
        for (int nf = 0; nf < 4; nf++)
            #pragma unroll
            for (int r = 0; r < 4; r++) sacc[nf][r] = 0.f;

        #pragma unroll
        for (int kf = 0; kf < 16; kf++) {
            int kd = kf << 3;
            const uint32_t* ap = Qs + (wm * 16 + lr) * QKPAD + kd + lc;
            uint4 af;
            af.x = ap[0];
            af.y = ap[8 * QKPAD];
            af.z = ap[4];
            af.w = ap[8 * QKPAD + 4];
            #pragma unroll
            for (int nf = 0; nf < 4; nf++) {
                const uint32_t* bp = Ks + (wn * 32 + nf * 8 + lr) * QKPAD + kd + lc;
                uint2 bf;
                bf.x = bp[0];
                bf.y = bp[4];
                mma_tf32(sacc[nf], af, bf);
            }
        }

        // ---- scale + causal mask + store S to smem ----
        const float sc = 0.08838834764831845f;   // 1/sqrt(128)
        int r_lo = wm * 16 + lr, r_hi = r_lo + 8;
        int qi_lo = q0 + r_lo,  qi_hi = q0 + r_hi;
        #pragma unroll
        for (int nf = 0; nf < 4; nf++) {
            int col = wn * 32 + nf * 8 + lc * 2;
            int kj = j0 + col;
            float v0 = sacc[nf][0] * sc, v1 = sacc[nf][1] * sc;
            float v2 = sacc[nf][2] * sc, v3 = sacc[nf][3] * sc;
            if (kj     > qi_lo) v0 = -INFINITY;
            if (kj + 1 > qi_lo) v1 = -INFINITY;
            if (kj     > qi_hi) v2 = -INFINITY;
            if (kj + 1 > qi_hi) v3 = -INFINITY;
            Ss[r_lo * SSPAD + col]     = v0;
            Ss[r_lo * SSPAD + col + 1] = v1;
            Ss[r_hi * SSPAD + col]     = v2;
            Ss[r_hi * SSPAD + col + 1] = v3;
        }
        __syncthreads();

        // ---- online softmax: warp w owns rows w*8..w*8+7 ----
        #pragma unroll
        for (int r8 = 0; r8 < 8; r8++) {
            int r = (w << 3) + r8;
            float s0 = Ss[r * SSPAD + lane];
            float s1 = Ss[r * SSPAD + 32 + lane];
            float mx = fmaxf(s0, s1);
            #pragma unroll
            for (int off = 16; off; off >>= 1)
                mx = fmaxf(mx, __shfl_xor_sync(0xffffffffu, mx, off));
            float mold = m_s[r];
            float mn = fmaxf(mold, mx);
            float e0 = expf(s0 - mn);
            float e1 = expf(s1 - mn);
            // round P to tf32 so l matches what the PV mma consumes
            e0 = __uint_as_float(f2tf32(e0));
            e1 = __uint_as_float(f2tf32(e1));
            Ss[r * SSPAD + lane]      = e0;
            Ss[r * SSPAD + 32 + lane] = e1;
            float sum = e0 + e1;
            #pragma unroll
            for (int off = 16; off; off >>= 1)
                sum += __shfl_xor_sync(0xffffffffu, sum, off);
            if (lane == 0) {
                float corr = expf(mold - mn);
                l_s[r] = l_s[r] * corr + sum;
                m_s[r] = mn;
                c_s[r] = corr;
            }
        }
        __syncthreads();

        // ---- rescale O, then O += P V : warp rows [wm*16,+16), cols [wn*64,+64) ----
        float corr_lo = c_s[r_lo];
        float corr_hi = c_s[r_hi];
        #pragma unroll
        for (int nf = 0; nf < 8; nf++) {
            oacc[nf][0] *= corr_lo; oacc[nf][1] *= corr_lo;
            oacc[nf][2] *= corr_hi; oacc[nf][3] *= corr_hi;
        }

        #pragma unroll
        for (int kf = 0; kf < 8; kf++) {
            int kk = kf << 3;
            const float* pp = Ss + (wm * 16 + lr) * SSPAD + kk + lc;
            uint4 af;
            af.x = __float_as_uint(pp[0]);
            af.y = __float_as_uint(pp[8 * SSPAD]);
            af.z = __float_as_uint(pp[4]);
            af.w = __float_as_uint(pp[8 * SSPAD + 4]);
            #pragma unroll
            for (int nf = 0; nf < 8; nf++) {
                const uint32_t* bp = Vs + (kk + lc) * VPAD + wn * 64 + nf * 8 + lr;
                uint2 bf;
                bf.x = bp[0];
                bf.y = bp[4 * VPAD];
                mma_tf32(oacc[nf], af, bf);
            }
        }
        __syncthreads();   // protect K/V/Ss before next iteration overwrites
    }

    // ---- epilogue: O / l ----
    {
        int r_lo = wm * 16 + lr, r_hi = r_lo + 8;
        float inv_lo = 1.0f / l_s[r_lo];
        float inv_hi = 1.0f / l_s[r_hi];
        #pragma unroll
        for (int nf = 0; nf < 8; nf++) {
            int col = wn * 64 + nf * 8 + lc * 2;
            float* d0 = o + base + (size_t)(q0 + r_lo) * DM + col;
            float* d1 = o + base + (size_t)(q0 + r_hi) * DM + col;
            *(float2*)d0 = make_float2(oacc[nf][0] * inv_lo, oacc[nf][1] * inv_lo);
            *(float2*)d1 = make_float2(oacc[nf][2] * inv_hi, oacc[nf][3] * inv_hi);
        }
    }
}

// ---------------------------------------------------------------------------
// Launch
// ---------------------------------------------------------------------------
extern "C" void kernel_launch(void* const* d_in, const int* in_sizes, int n_in,
                              void* d_out, int out_size)
{
    const float* h  = (const float*)d_in[0];
    const float* wq = (const float*)d_in[1];
    const float* bq = (const float*)d_in[2];
    const float* wk = (const float*)d_in[3];
    const float* bk = (const float*)d_in[4];
    const float* wv = (const float*)d_in[5];
    const float* bv = (const float*)d_in[6];
    const float* wo = (const float*)d_in[7];
    const float* bo = (const float*)d_in[8];
    const float* lg = (const float*)d_in[9];
    const float* lb = (const float*)d_in[10];
    float* out = (float*)d_out;

    float *xn, *qb, *kb, *vb, *ob;
    float2* rt;
    cudaGetSymbolAddress((void**)&xn, g_xn);
    cudaGetSymbolAddress((void**)&qb, g_q);
    cudaGetSymbolAddress((void**)&kb, g_k);
    cudaGetSymbolAddress((void**)&vb, g_v);
    cudaGetSymbolAddress((void**)&ob, g_o);
    cudaGetSymbolAddress((void**)&rt, g_rope);

    // 0. RoPE table
    rope_table_kernel<<<(S_ * 64 + 255) / 256, 256>>>(rt);

    // 1. LayerNorm
    ln_kernel<<<MROWS, 256>>>(h, lg, lb, xn);

    // 2. QKV projections (tf32 tensor cores)
    dim3 gg(DM / 128, MROWS / 128);
    tgemm_nt<<<gg, 256>>>(xn, wq, bq, nullptr, qb, DM, DM);
    tgemm_nt<<<gg, 256>>>(xn, wk, bk, nullptr, kb, DM, DM);
    tgemm_nt<<<gg, 256>>>(xn, wv, bv, nullptr, vb, DM, DM);

    // 3. RoPE on q, k
    rope_kernel<<<dim3((MROWS * NH * 64) / 256, 2), 256>>>(qb, kb, rt);

    // 4. Causal flash attention (tf32 tensor cores)
    int smem_attn = (64 * QKPAD * 2 + 64 * VPAD + 64 * SSPAD + 192) * 4;
    cudaFuncSetAttribute(attn_tc_kernel, cudaFuncAttributeMaxDynamicSharedMemorySize,
                         smem_attn);
    attn_tc_kernel<<<dim3(S_ / 64, NH, B_), 256, smem_attn>>>(qb, kb, vb, ob);

    // 5. Output projection + bias + residual (tf32)
    tgemm_nt<<<gg, 256>>>(ob, wo, bo, h, out, DM, DM);
}

// round 7
// speedup vs baseline: 2.3353x; 1.0050x over previous
#include <cuda_runtime.h>
#include <math.h>
#include <stdint.h>

// Problem constants (fixed shapes)
#define B_    2
#define S_    2048
#define DM    2048
#define NH    16
#define DK_   128
#define MROWS (B_ * S_)      // 4096
#define EPS_  1e-5f

// ---------------------------------------------------------------------------
// Scratch (no cudaMalloc allowed)
// ---------------------------------------------------------------------------
__device__ float g_xn[(size_t)MROWS * DM];
__device__ float g_q [(size_t)MROWS * DM];
__device__ float g_k [(size_t)MROWS * DM];
__device__ float g_v [(size_t)MROWS * DM];
__device__ float g_o [(size_t)MROWS * DM];
__device__ float2 g_rope[(size_t)S_ * 64];   // (cos, sin) per (pos, j)

// ---------------------------------------------------------------------------
// tf32 helpers
// ---------------------------------------------------------------------------
__device__ __forceinline__ uint32_t f2tf32(float f)
{
    uint32_t r;
    asm("cvt.rna.tf32.f32 %0, %1;" : "=r"(r) : "f"(f));
    return r;
}

__device__ __forceinline__ void mma_tf32(float* c, const uint4& a, const uint2& b)
{
    asm volatile(
        "mma.sync.aligned.m16n8k8.row.col.f32.tf32.tf32.f32 "
        "{%0,%1,%2,%3}, {%4,%5,%6,%7}, {%8,%9}, {%0,%1,%2,%3};\n"
        : "+f"(c[0]), "+f"(c[1]), "+f"(c[2]), "+f"(c[3])
        : "r"(a.x), "r"(a.y), "r"(a.z), "r"(a.w), "r"(b.x), "r"(b.y));
}

// cp.async + ldmatrix (sm_80 / sm_75 era -- supported on plain sm_100 target)
#define CP_ASYNC16(dst, src) \
    asm volatile("cp.async.cg.shared.global [%0], [%1], 16;" \
                 :: "r"((uint32_t)(dst)), "l"(src))
#define CP_COMMIT() asm volatile("cp.async.commit_group;" ::: "memory")
#define CP_WAIT(N)  asm volatile("cp.async.wait_group %0;" :: "n"(N) : "memory")

#define LDSM_X4(d, addr) \
    asm volatile("ldmatrix.sync.aligned.m8n8.x4.shared.b16 {%0,%1,%2,%3}, [%4];" \
                 : "=r"((d).x), "=r"((d).y), "=r"((d).z), "=r"((d).w) \
                 : "r"((uint32_t)(addr)))
#define LDSM_X2(d, addr) \
    asm volatile("ldmatrix.sync.aligned.m8n8.x2.shared.b16 {%0,%1}, [%2];" \
                 : "=r"((d).x), "=r"((d).y) \
                 : "r"((uint32_t)(addr)))

// ---------------------------------------------------------------------------
// RoPE table: accurate double-precision sincos of the fp32-quantized phase.
// ---------------------------------------------------------------------------
__global__ __launch_bounds__(256)
void rope_table_kernel(float2* __restrict__ tab)
{
    int idx = blockIdx.x * 256 + threadIdx.x;     // [0, S_*64)
    if (idx >= S_ * 64) return;
    int j   = idx & 63;
    int pos = idx >> 6;
    double theta_d = 1.0 / pow(10000.0, (double)j / 64.0);
    float  theta_f = (float)theta_d;
    float fr = (float)pos * theta_f;
    double dfr = (double)fr;
    tab[idx] = make_float2((float)cos(dfr), (float)sin(dfr));
}

// ---------------------------------------------------------------------------
// LayerNorm
// ---------------------------------------------------------------------------
__global__ __launch_bounds__(256)
void ln_kernel(const float* __restrict__ x, const float* __restrict__ g,
               const float* __restrict__ bb, float* __restrict__ out)
{
    int row = blockIdx.x;
    int t = threadIdx.x;
    const float4* xr = (const float4*)(x + (size_t)row * DM);
    float4* orow = (float4*)(out + (size_t)row * DM);

    float4 v0 = xr[t];
    float4 v1 = xr[t + 256];
    float sum = v0.x + v0.y + v0.z + v0.w + v1.x + v1.y + v1.z + v1.w;
    float sq  = v0.x*v0.x + v0.y*v0.y + v0.z*v0.z + v0.w*v0.w
              + v1.x*v1.x + v1.y*v1.y + v1.z*v1.z + v1.w*v1.w;

    #pragma unroll
    for (int off = 16; off; off >>= 1) {
        sum += __shfl_xor_sync(0xffffffffu, sum, off);
        sq  += __shfl_xor_sync(0xffffffffu, sq,  off);
    }
    __shared__ float s_sum[8], s_sq[8];
    int w = t >> 5;
    if ((t & 31) == 0) { s_sum[w] = sum; s_sq[w] = sq; }
    __syncthreads();
    if (t < 32) {
        float a = (t < 8) ? s_sum[t] : 0.f;
        float b = (t < 8) ? s_sq[t]  : 0.f;
        #pragma unroll
        for (int off = 4; off; off >>= 1) {
            a += __shfl_xor_sync(0xffffffffu, a, off);
            b += __shfl_xor_sync(0xffffffffu, b, off);
        }
        if (t == 0) { s_sum[0] = a; s_sq[0] = b; }
    }
    __syncthreads();

    float mu  = s_sum[0] * (1.0f / DM);
    float var = s_sq[0] * (1.0f / DM) - mu * mu;
    float rstd = rsqrtf(var + EPS_);

    const float4* g4 = (const float4*)g;
    const float4* b4 = (const float4*)bb;
    {
        float4 gv = g4[t], bv = b4[t], o;
        o.x = (v0.x - mu) * rstd * gv.x + bv.x;
        o.y = (v0.y - mu) * rstd * gv.y + bv.y;
        o.z = (v0.z - mu) * rstd * gv.z + bv.z;
        o.w = (v0.w - mu) * rstd * gv.w + bv.w;
        orow[t] = o;
    }
    {
        float4 gv = g4[t + 256], bv = b4[t + 256], o;
        o.x = (v1.x - mu) * rstd * gv.x + bv.x;
        o.y = (v1.y - mu) * rstd * gv.y + bv.y;
        o.z = (v1.z - mu) * rstd * gv.z + bv.z;
        o.w = (v1.w - mu) * rstd * gv.w + bv.w;
        orow[t + 256] = o;
    }
}

// ---------------------------------------------------------------------------
// Pipelined TF32 GEMM NT: C[M,N] = A[M,K] * W[N,K]^T + bias[N] (+ res)
// Block 128x128, BK=16, 256 threads (8 warps 2x4), warp tile 64x32.
// 4-stage cp.async pipeline (16KB/stage). Raw fp32 fed to mma.tf32 (HW
// truncates to tf32). Fragments gathered with ldmatrix.b16 (one tf32 = one
// delivered 32-bit reg).
// Stage layout (bytes): A chunk (m,kq) at (kq*128+m)*16 ; B chunk (n,kq) at
// 8192 + (kq*128+n)*16. kq = 16-byte column index (4 tf32), 4 per BK=16.
// ---------------------------------------------------------------------------
#define PSTAGES 4
#define PSTAGE_BYTES 16384

__global__ __launch_bounds__(256, 2)
void pgemm_nt(const float* __restrict__ A, const float* __restrict__ W,
              const float* __restrict__ bias, const float* __restrict__ res,
              float* __restrict__ C, int K, int N)
{
    extern __shared__ char smem[];
    uint32_t sb = (uint32_t)__cvta_generic_to_shared(smem);

    int t = threadIdx.x;
    int lane = t & 31;
    int w = t >> 5;
    int wm = w >> 2, wn = w & 3;           // 2(m) x 4(n) warps
    int m0 = blockIdx.y << 7, n0 = blockIdx.x << 7;

    // ---- loader: thread t covers rows lm, lm+64 in both A and W; kq = t&3
    int lm = t >> 2;
    int kq = t & 3;
    const float* gA0 = A + (size_t)(m0 + lm) * K + (kq << 2);
    const float* gA1 = gA0 + (size_t)64 * K;
    const float* gW0 = W + (size_t)(n0 + lm) * K + (kq << 2);
    const float* gW1 = gW0 + (size_t)64 * K;
    uint32_t dA0 = (uint32_t)(kq * 128 + lm) * 16;
    uint32_t dA1 = dA0 + 64 * 16;
    uint32_t dB0 = 8192 + dA0;
    uint32_t dB1 = 8192 + dA1;

    // ---- per-lane ldmatrix offsets (bytes within stage)
    // A frag (ks, i): tiles a0..a3 <- lane groups 0-7/8-15/16-23/24-31
    int aoff[2][4], boff[2][4];
    #pragma unroll
    for (int ks = 0; ks < 2; ks++) {
        #pragma unroll
        for (int i = 0; i < 4; i++) {
            int msub = wm * 4 + i;
            int kqa  = ks * 2 + (lane >> 4);
            int mrow = msub * 16 + (lane & 7) + ((lane >> 3) & 1) * 8;
            aoff[ks][i] = kqa * 2048 + mrow * 16;
            int nsub = wn * 4 + i;
            int kqb  = ks * 2 + ((lane >> 3) & 1);
            int nrow = nsub * 8 + (lane & 7);
            boff[ks][i] = 8192 + kqb * 2048 + nrow * 16;
        }
    }

    float acc[4][4][4];
    #pragma unroll
    for (int i = 0; i < 4; i++)
        #pragma unroll
        for (int j = 0; j < 4; j++)
            #pragma unroll
            for (int r = 0; r < 4; r++) acc[i][j][r] = 0.f;

    const int nIter = K >> 4;     // 128

    auto load_stage = [&](int c) {
        uint32_t s = sb + (uint32_t)(c & 3) * PSTAGE_BYTES;
        int ko = c << 4;
        CP_ASYNC16(s + dA0, gA0 + ko);
        CP_ASYNC16(s + dA1, gA1 + ko);
        CP_ASYNC16(s + dB0, gW0 + ko);
        CP_ASYNC16(s + dB1, gW1 + ko);
        CP_COMMIT();
    };

    load_stage(0); load_stage(1); load_stage(2);

    for (int c = 0; c < nIter; c++) {
        if (c <= nIter - 3)      CP_WAIT(2);
        else if (c == nIter - 2) CP_WAIT(1);
        else                     CP_WAIT(0);
        __syncthreads();

        if (c + 3 < nIter) load_stage(c + 3);

        uint32_t s = sb + (uint32_t)(c & 3) * PSTAGE_BYTES;
        #pragma unroll
        for (int ks = 0; ks < 2; ks++) {
            uint4 af[4]; uint2 bf[4];
            #pragma unroll
            for (int i = 0; i < 4; i++) LDSM_X4(af[i], s + aoff[ks][i]);
            #pragma unroll
            for (int j = 0; j < 4; j++) LDSM_X2(bf[j], s + boff[ks][j]);
            #pragma unroll
            for (int i = 0; i < 4; i++)
                #pragma unroll
                for (int j = 0; j < 4; j++)
                    mma_tf32(acc[i][j], af[i], bf[j]);
        }
    }

    // ---- epilogue: C frag c0=(r,2c) c1=(r,2c+1) c2=(r+8,2c) c3=(r+8,2c+1)
    #pragma unroll
    for (int i = 0; i < 4; i++) {
        int r0 = m0 + wm * 64 + i * 16 + (lane >> 2);
        #pragma unroll
        for (int j = 0; j < 4; j++) {
            int c = n0 + wn * 32 + j * 8 + (lane & 3) * 2;
            float b0 = bias[c], b1 = bias[c + 1];
            size_t o0 = (size_t)r0 * N + c;
            size_t o1 = (size_t)(r0 + 8) * N + c;
            float2 v0 = make_float2(acc[i][j][0] + b0, acc[i][j][1] + b1);
            float2 v1 = make_float2(acc[i][j][2] + b0, acc[i][j][3] + b1);
            if (res) {
                float2 e0 = *(const float2*)(res + o0);
                float2 e1 = *(const float2*)(res + o1);
                v0.x += e0.x; v0.y += e0.y;
                v1.x += e1.x; v1.y += e1.y;
            }
            *(float2*)(C + o0) = v0;
            *(float2*)(C + o1) = v1;
        }
    }
}

// ---------------------------------------------------------------------------
// RoPE apply
// ---------------------------------------------------------------------------
__global__ __launch_bounds__(256)
void rope_kernel(float* __restrict__ q, float* __restrict__ k,
                 const float2* __restrict__ tab)
{
    int idx = blockIdx.x * 256 + threadIdx.x;
    float* base = (blockIdx.y == 0) ? q : k;

    int j   = idx & 63;
    int hh  = (idx >> 6) & (NH - 1);
    int row = idx >> 10;
    int pos = row & (S_ - 1);

    float2 cs = tab[(pos << 6) + j];
    float c = cs.x, s = cs.y;

    float* p = base + (size_t)row * DM + (hh << 7) + j;
    float x0 = p[0], x1 = p[64];
    p[0]  = x0 * c - x1 * s;
    p[64] = x1 * c + x0 * s;
}

// ---------------------------------------------------------------------------
// TF32 tensor-core flash attention, causal (unchanged from R5)
// ---------------------------------------------------------------------------
#define QKPAD 132
#define VPAD  136
#define SSPAD 68

__global__ __launch_bounds__(256)
void attn_tc_kernel(const float* __restrict__ q, const float* __restrict__ k,
                    const float* __restrict__ v, float* __restrict__ o)
{
    extern __shared__ float sm[];
    uint32_t* Qs = (uint32_t*)sm;
    uint32_t* Ks = Qs + 64 * QKPAD;
    uint32_t* Vs = Ks + 64 * QKPAD;
    float* Ss  = (float*)(Vs + 64 * VPAD);
    float* m_s = Ss + 64 * SSPAD;
    float* l_s = m_s + 64;
    float* c_s = l_s + 64;

    int t = threadIdx.x;
    int lane = t & 31;
    int w = t >> 5;
    int wm = w >> 1;
    int wn = w & 1;
    int lr = lane >> 2;
    int lc = lane & 3;

    int q0 = blockIdx.x << 6;
    size_t base = ((size_t)blockIdx.z * S_) * DM + ((size_t)blockIdx.y << 7);

    #pragma unroll
    for (int it = 0; it < 8; it++) {
        int idx = t + (it << 8);
        int r = idx >> 5, c4 = idx & 31;
        float4 x = *(const float4*)(q + base + (size_t)(q0 + r) * DM + (c4 << 2));
        uint32_t* dst = Qs + r * QKPAD + (c4 << 2);
        dst[0] = f2tf32(x.x); dst[1] = f2tf32(x.y);
        dst[2] = f2tf32(x.z); dst[3] = f2tf32(x.w);
    }
    if (t < 64) { m_s[t] = -INFINITY; l_s[t] = 0.f; }

    float oacc[8][4];
    #pragma unroll
    for (int i = 0; i < 8; i++)
        #pragma unroll
        for (int r = 0; r < 4; r++) oacc[i][r] = 0.f;

    for (int j0 = 0; j0 <= q0; j0 += 64) {
        #pragma unroll
        for (int it = 0; it < 8; it++) {
            int idx = t + (it << 8);
            int r = idx >> 5, c4 = idx & 31;
            size_t goff = base + (size_t)(j0 + r) * DM + (c4 << 2);
            float4 xk = *(const float4*)(k + goff);
            uint32_t* dk = Ks + r * QKPAD + (c4 << 2);
            dk[0] = f2tf32(xk.x); dk[1] = f2tf32(xk.y);
            dk[2] = f2tf32(xk.z); dk[3] = f2tf32(xk.w);
            float4 xv = *(const float4*)(v + goff);
            uint32_t* dv = Vs + r * VPAD + (c4 << 2);
            dv[0] = f2tf32(xv.x); dv[1] = f2tf32(xv.y);
            dv[2] = f2tf32(xv.z); dv[3] = f2tf32(xv.w);
        }
        __syncthreads();

        float sacc[4][4];
        #pragma unroll
        for (int nf = 0; nf < 4; nf++)
            #pragma unroll
            for (int r = 0; r < 4; r++) sacc[nf][r] = 0.f;

        #pragma unroll
        for (int kf = 0; kf < 16; kf++) {
            int kd = kf << 3;
            const uint32_t* ap = Qs + (wm * 16 + lr) * QKPAD + kd + lc;
            uint4 af;
            af.x = ap[0];
            af.y = ap[8 * QKPAD];
            af.z = ap[4];
            af.w = ap[8 * QKPAD + 4];
            #pragma unroll
            for (int nf = 0; nf < 4; nf++) {
                const uint32_t* bp = Ks + (wn * 32 + nf * 8 + lr) * QKPAD + kd + lc;
                uint2 bf;
                bf.x = bp[0];
                bf.y = bp[4];
                mma_tf32(sacc[nf], af, bf);
            }
        }

        const float sc = 0.08838834764831845f;
        int r_lo = wm * 16 + lr, r_hi = r_lo + 8;
        int qi_lo = q0 + r_lo,  qi_hi = q0 + r_hi;
        #pragma unroll
        for (int nf = 0; nf < 4; nf++) {
            int col = wn * 32 + nf * 8 + lc * 2;
            int kj = j0 + col;
            float v0 = sacc[nf][0] * sc, v1 = sacc[nf][1] * sc;
            float v2 = sacc[nf][2] * sc, v3 = sacc[nf][3] * sc;
            if (kj     > qi_lo) v0 = -INFINITY;
            if (kj + 1 > qi_lo) v1 = -INFINITY;
            if (kj     > qi_hi) v2 = -INFINITY;
            if (kj + 1 > qi_hi) v3 = -INFINITY;
            Ss[r_lo * SSPAD + col]     = v0;
            Ss[r_lo * SSPAD + col + 1] = v1;
            Ss[r_hi * SSPAD + col]     = v2;
            Ss[r_hi * SSPAD + col + 1] = v3;
        }
        __syncthreads();

        #pragma unroll
        for (int r8 = 0; r8 < 8; r8++) {
            int r = (w << 3) + r8;
            float s0 = Ss[r * SSPAD + lane];
            float s1 = Ss[r * SSPAD + 32 + lane];
            float mx = fmaxf(s0, s1);
            #pragma unroll
            for (int off = 16; off; off >>= 1)
                mx = fmaxf(mx, __shfl_xor_sync(0xffffffffu, mx, off));
            float mold = m_s[r];
            float mn = fmaxf(mold, mx);
            float e0 = expf(s0 - mn);
            float e1 = expf(s1 - mn);
            e0 = __uint_as_float(f2tf32(e0));
            e1 = __uint_as_float(f2tf32(e1));
            Ss[r * SSPAD + lane]      = e0;
            Ss[r * SSPAD + 32 + lane] = e1;
            float sum = e0 + e1;
            #pragma unroll
            for (int off = 16; off; off >>= 1)
                sum += __shfl_xor_sync(0xffffffffu, sum, off);
            if (lane == 0) {
                float corr = expf(mold - mn);
                l_s[r] = l_s[r] * corr + sum;
                m_s[r] = mn;
                c_s[r] = corr;
            }
        }
        __syncthreads();

        float corr_lo = c_s[r_lo];
        float corr_hi = c_s[r_hi];
        #pragma unroll
        for (int nf = 0; nf < 8; nf++) {
            oacc[nf][0] *= corr_lo; oacc[nf][1] *= corr_lo;
            oacc[nf][2] *= corr_hi; oacc[nf][3] *= corr_hi;
        }

        #pragma unroll
        for (int kf = 0; kf < 8; kf++) {
            int kk = kf << 3;
            const float* pp = Ss + (wm * 16 + lr) * SSPAD + kk + lc;
            uint4 af;
            af.x = __float_as_uint(pp[0]);
            af.y = __float_as_uint(pp[8 * SSPAD]);
            af.z = __float_as_uint(pp[4]);
            af.w = __float_as_uint(pp[8 * SSPAD + 4]);
            #pragma unroll
            for (int nf = 0; nf < 8; nf++) {
                const uint32_t* bp = Vs + (kk + lc) * VPAD + wn * 64 + nf * 8 + lr;
                uint2 bf;
                bf.x = bp[0];
                bf.y = bp[4 * VPAD];
                mma_tf32(oacc[nf], af, bf);
            }
        }
        __syncthreads();
    }

    {
        int r_lo = wm * 16 + lr, r_hi = r_lo + 8;
        float inv_lo = 1.0f / l_s[r_lo];
        float inv_hi = 1.0f / l_s[r_hi];
        #pragma unroll
        for (int nf = 0; nf < 8; nf++) {
            int col = wn * 64 + nf * 8 + lc * 2;
            float* d0 = o + base + (size_t)(q0 + r_lo) * DM + col;
            float* d1 = o + base + (size_t)(q0 + r_hi) * DM + col;
            *(float2*)d0 = make_float2(oacc[nf][0] * inv_lo, oacc[nf][1] * inv_lo);
            *(float2*)d1 = make_float2(oacc[nf][2] * inv_hi, oacc[nf][3] * inv_hi);
        }
    }
}

// ---------------------------------------------------------------------------
// Launch
// ---------------------------------------------------------------------------
extern "C" void kernel_launch(void* const* d_in, const int* in_sizes, int n_in,
                              void* d_out, int out_size)
{
    const float* h  = (const float*)d_in[0];
    const float* wq = (const float*)d_in[1];
    const float* bq = (const float*)d_in[2];
    const float* wk = (const float*)d_in[3];
    const float* bk = (const float*)d_in[4];
    const float* wv = (const float*)d_in[5];
    const float* bv = (const float*)d_in[6];
    const float* wo = (const float*)d_in[7];
    const float* bo = (const float*)d_in[8];
    const float* lg = (const float*)d_in[9];
    const float* lb = (const float*)d_in[10];
    float* out = (float*)d_out;

    float *xn, *qb, *kb, *vb, *ob;
    float2* rt;
    cudaGetSymbolAddress((void**)&xn, g_xn);
    cudaGetSymbolAddress((void**)&qb, g_q);
    cudaGetSymbolAddress((void**)&kb, g_k);
    cudaGetSymbolAddress((void**)&vb, g_v);
    cudaGetSymbolAddress((void**)&ob, g_o);
    cudaGetSymbolAddress((void**)&rt, g_rope);

    // 0. RoPE table
    rope_table_kernel<<<(S_ * 64 + 255) / 256, 256>>>(rt);

    // 1. LayerNorm
    ln_kernel<<<MROWS, 256>>>(h, lg, lb, xn);

    // 2. QKV projections (pipelined tf32 mma + cp.async + ldmatrix)
    int smem_g = PSTAGES * PSTAGE_BYTES;     // 65536
    cudaFuncSetAttribute(pgemm_nt, cudaFuncAttributeMaxDynamicSharedMemorySize,
                         smem_g);
    dim3 gg(DM / 128, MROWS / 128);
    pgemm_nt<<<gg, 256, smem_g>>>(xn, wq, bq, nullptr, qb, DM, DM);
    pgemm_nt<<<gg, 256, smem_g>>>(xn, wk, bk, nullptr, kb, DM, DM);
    pgemm_nt<<<gg, 256, smem_g>>>(xn, wv, bv, nullptr, vb, DM, DM);

    // 3. RoPE on q, k
    rope_kernel<<<dim3((MROWS * NH * 64) / 256, 2), 256>>>(qb, kb, rt);

    // 4. Causal flash attention (tf32 mma.sync)
    int smem_attn = (64 * QKPAD * 2 + 64 * VPAD + 64 * SSPAD + 192) * 4;
    cudaFuncSetAttribute(attn_tc_kernel, cudaFuncAttributeMaxDynamicSharedMemorySize,
                         smem_attn);
    attn_tc_kernel<<<dim3(S_ / 64, NH, B_), 256, smem_attn>>>(qb, kb, vb, ob);

    // 5. Output projection + bias + residual
    pgemm_nt<<<gg, 256, smem_g>>>(ob, wo, bo, h, out, DM, DM);
}

// round 9
// speedup vs baseline: 4.0976x; 1.7546x over previous
#include <cuda_runtime.h>
#include <cuda_bf16.h>
#include <math.h>
#include <stdint.h>

// Problem constants (fixed shapes)
#define B_    2
#define S_    2048
#define DM    2048
#define NH    16
#define DK_   128
#define MROWS (B_ * S_)      // 4096
#define EPS_  1e-5f

// ---------------------------------------------------------------------------
// Scratch (no cudaMalloc allowed)
// ---------------------------------------------------------------------------
__device__ float g_xn[(size_t)MROWS * DM];   // reused as bf16 (16MB of 32MB)
__device__ float g_q [(size_t)MROWS * DM];
__device__ float g_k [(size_t)MROWS * DM];
__device__ float g_v [(size_t)MROWS * DM];
__device__ float g_o [(size_t)MROWS * DM];   // reused as bf16
__device__ __nv_bfloat16 g_wb[4][(size_t)DM * DM];  // bf16 weights
__device__ float2 g_rope[(size_t)S_ * 64];   // (cos, sin) per (pos, j)

// ---------------------------------------------------------------------------
// helpers
// ---------------------------------------------------------------------------
__device__ __forceinline__ uint32_t f2tf32(float f)
{
    uint32_t r;
    asm("cvt.rna.tf32.f32 %0, %1;" : "=r"(r) : "f"(f));
    return r;
}

__device__ __forceinline__ uint32_t packbf2(float a, float b)
{
    __nv_bfloat162 h = __floats2bfloat162_rn(a, b);
    return *(uint32_t*)&h;
}

__device__ __forceinline__ void mma_tf32(float* c, const uint4& a, const uint2& b)
{
    asm volatile(
        "mma.sync.aligned.m16n8k8.row.col.f32.tf32.tf32.f32 "
        "{%0,%1,%2,%3}, {%4,%5,%6,%7}, {%8,%9}, {%0,%1,%2,%3};\n"
        : "+f"(c[0]), "+f"(c[1]), "+f"(c[2]), "+f"(c[3])
        : "r"(a.x), "r"(a.y), "r"(a.z), "r"(a.w), "r"(b.x), "r"(b.y));
}

__device__ __forceinline__ void mma_bf16(float* c, const uint4& a, const uint2& b)
{
    asm volatile(
        "mma.sync.aligned.m16n8k16.row.col.f32.bf16.bf16.f32 "
        "{%0,%1,%2,%3}, {%4,%5,%6,%7}, {%8,%9}, {%0,%1,%2,%3};\n"
        : "+f"(c[0]), "+f"(c[1]), "+f"(c[2]), "+f"(c[3])
        : "r"(a.x), "r"(a.y), "r"(a.z), "r"(a.w), "r"(b.x), "r"(b.y));
}

#define CP_ASYNC16(dst, src) \
    asm volatile("cp.async.cg.shared.global [%0], [%1], 16;" \
                 :: "r"((uint32_t)(dst)), "l"(src))
#define CP_COMMIT() asm volatile("cp.async.commit_group;" ::: "memory")
#define CP_WAIT(N)  asm volatile("cp.async.wait_group %0;" :: "n"(N) : "memory")

#define LDSM_X4(d, addr) \
    asm volatile("ldmatrix.sync.aligned.m8n8.x4.shared.b16 {%0,%1,%2,%3}, [%4];" \
                 : "=r"((d).x), "=r"((d).y), "=r"((d).z), "=r"((d).w) \
                 : "r"((uint32_t)(addr)))
#define LDSM_X2(d, addr) \
    asm volatile("ldmatrix.sync.aligned.m8n8.x2.shared.b16 {%0,%1}, [%2];" \
                 : "=r"((d).x), "=r"((d).y) \
                 : "r"((uint32_t)(addr)))

// ---------------------------------------------------------------------------
// Weight conversion fp32 -> bf16 (rn). n = 4M elements, float4 vectorized.
// ---------------------------------------------------------------------------
__global__ __launch_bounds__(256)
void wconv_kernel(const float* __restrict__ src, __nv_bfloat16* __restrict__ dst,
                  int n4)
{
    int i = blockIdx.x * 256 + threadIdx.x;
    if (i >= n4) return;
    float4 x = ((const float4*)src)[i];
    uint2 u;
    u.x = packbf2(x.x, x.y);
    u.y = packbf2(x.z, x.w);
    ((uint2*)dst)[i] = u;
}

// ---------------------------------------------------------------------------
// RoPE table: accurate double-precision sincos of the fp32-quantized phase.
// ---------------------------------------------------------------------------
__global__ __launch_bounds__(256)
void rope_table_kernel(float2* __restrict__ tab)
{
    int idx = blockIdx.x * 256 + threadIdx.x;     // [0, S_*64)
    if (idx >= S_ * 64) return;
    int j   = idx & 63;
    int pos = idx >> 6;
    double theta_d = 1.0 / pow(10000.0, (double)j / 64.0);
    float  theta_f = (float)theta_d;
    float fr = (float)pos * theta_f;
    double dfr = (double)fr;
    tab[idx] = make_float2((float)cos(dfr), (float)sin(dfr));
}

// ---------------------------------------------------------------------------
// LayerNorm (outputs bf16)
// ---------------------------------------------------------------------------
__global__ __launch_bounds__(256)
void ln_kernel(const float* __restrict__ x, const float* __restrict__ g,
               const float* __restrict__ bb, __nv_bfloat16* __restrict__ out)
{
    int row = blockIdx.x;
    int t = threadIdx.x;
    const float4* xr = (const float4*)(x + (size_t)row * DM);
    uint2* orow = (uint2*)(out + (size_t)row * DM);

    float4 v0 = xr[t];
    float4 v1 = xr[t + 256];
    float sum = v0.x + v0.y + v0.z + v0.w + v1.x + v1.y + v1.z + v1.w;
    float sq  = v0.x*v0.x + v0.y*v0.y + v0.z*v0.z + v0.w*v0.w
              + v1.x*v1.x + v1.y*v1.y + v1.z*v1.z + v1.w*v1.w;

    #pragma unroll
    for (int off = 16; off; off >>= 1) {
        sum += __shfl_xor_sync(0xffffffffu, sum, off);
        sq  += __shfl_xor_sync(0xffffffffu, sq,  off);
    }
    __shared__ float s_sum[8], s_sq[8];
    int w = t >> 5;
    if ((t & 31) == 0) { s_sum[w] = sum; s_sq[w] = sq; }
    __syncthreads();
    if (t < 32) {
        float a = (t < 8) ? s_sum[t] : 0.f;
        float b = (t < 8) ? s_sq[t]  : 0.f;
        #pragma unroll
        for (int off = 4; off; off >>= 1) {
            a += __shfl_xor_sync(0xffffffffu, a, off);
            b += __shfl_xor_sync(0xffffffffu, b, off);
        }
        if (t == 0) { s_sum[0] = a; s_sq[0] = b; }
    }
    __syncthreads();

    float mu  = s_sum[0] * (1.0f / DM);
    float var = s_sq[0] * (1.0f / DM) - mu * mu;
    float rstd = rsqrtf(var + EPS_);

    const float4* g4 = (const float4*)g;
    const float4* b4 = (const float4*)bb;
    {
        float4 gv = g4[t], bv = b4[t];
        uint2 u;
        u.x = packbf2((v0.x - mu) * rstd * gv.x + bv.x,
                      (v0.y - mu) * rstd * gv.y + bv.y);
        u.y = packbf2((v0.z - mu) * rstd * gv.z + bv.z,
                      (v0.w - mu) * rstd * gv.w + bv.w);
        orow[t] = u;
    }
    {
        float4 gv = g4[t + 256], bv = b4[t + 256];
        uint2 u;
        u.x = packbf2((v1.x - mu) * rstd * gv.x + bv.x,
                      (v1.y - mu) * rstd * gv.y + bv.y);
        u.y = packbf2((v1.z - mu) * rstd * gv.z + bv.z,
                      (v1.w - mu) * rstd * gv.w + bv.w);
        orow[t + 256] = u;
    }
}

// ---------------------------------------------------------------------------
// Pipelined BF16 GEMM NT: C[M,N] = A[M,K] * W[N,K]^T + bias[N] (+ res)
// A, W are bf16; C/bias/res fp32. Block 128x128, BK=32 bf16, 256 threads
// (8 warps 2x4), warp tile 64x32, mma.m16n8k16. 4-stage cp.async pipeline.
// Stage layout: row-padded 80B (A rows 0..127, then B rows at +10240).
// Bank groups (20*r)%32 distinct for r mod 8 -> ldmatrix conflict-free.
// ---------------------------------------------------------------------------
#define BSTAGES 4
#define BROWB   80
#define BSTAGE_BYTES 20480      // 2 * 128 * 80

__global__ __launch_bounds__(256, 2)
void bgemm_nt(const __nv_bfloat16* __restrict__ A,
              const __nv_bfloat16* __restrict__ W,
              const float* __restrict__ bias, const float* __restrict__ res,
              float* __restrict__ C, int K, int N)
{
    extern __shared__ char smem[];
    uint32_t sb = (uint32_t)__cvta_generic_to_shared(smem);

    int t = threadIdx.x;
    int lane = t & 31;
    int w = t >> 5;
    int wm = w >> 2, wn = w & 3;           // 2(m) x 4(n) warps
    int m0 = blockIdx.y << 7, n0 = blockIdx.x << 7;

    // loader: thread t covers rows lm, lm+64; 16B chunk kq = t&3 (8 bf16)
    int lm = t >> 2;
    int kq = t & 3;
    const __nv_bfloat16* gA0 = A + (size_t)(m0 + lm) * K + kq * 8;
    const __nv_bfloat16* gA1 = gA0 + (size_t)64 * K;
    const __nv_bfloat16* gW0 = W + (size_t)(n0 + lm) * K + kq * 8;
    const __nv_bfloat16* gW1 = gW0 + (size_t)64 * K;
    uint32_t dA0 = (uint32_t)lm * BROWB + kq * 16;
    uint32_t dA1 = dA0 + 64 * BROWB;
    uint32_t dB0 = 10240 + dA0;
    uint32_t dB1 = 10240 + dA1;

    // ldmatrix offsets (bytes in stage), ks = k16 step (0/1)
    int aoff[2][4], boff[2][4];
    #pragma unroll
    for (int ks = 0; ks < 2; ks++) {
        #pragma unroll
        for (int i = 0; i < 4; i++) {
            int mrow = (wm * 4 + i) * 16 + (lane & 7) + ((lane >> 3) & 1) * 8;
            aoff[ks][i] = mrow * BROWB + ks * 32 + (lane >> 4) * 16;
            int nrow = (wn * 4 + i) * 8 + (lane & 7);
            boff[ks][i] = 10240 + nrow * BROWB + ks * 32 + ((lane >> 3) & 1) * 16;
        }
    }

    float acc[4][4][4];
    #pragma unroll
    for (int i = 0; i < 4; i++)
        #pragma unroll
        for (int j = 0; j < 4; j++)
            #pragma unroll
            for (int r = 0; r < 4; r++) acc[i][j][r] = 0.f;

    const int nIter = K >> 5;     // K / 32 = 64

    auto load_stage = [&](int c) {
        uint32_t s = sb + (uint32_t)(c & 3) * BSTAGE_BYTES;
        int ko = c << 5;          // elements
        CP_ASYNC16(s + dA0, gA0 + ko);
        CP_ASYNC16(s + dA1, gA1 + ko);
        CP_ASYNC16(s + dB0, gW0 + ko);
        CP_ASYNC16(s + dB1, gW1 + ko);
        CP_COMMIT();
    };

    load_stage(0); load_stage(1); load_stage(2);

    for (int c = 0; c < nIter; c++) {
        if (c <= nIter - 3)      CP_WAIT(2);
        else if (c == nIter - 2) CP_WAIT(1);
        else                     CP_WAIT(0);
        __syncthreads();

        if (c + 3 < nIter) load_stage(c + 3);

        uint32_t s = sb + (uint32_t)(c & 3) * BSTAGE_BYTES;
        #pragma unroll
        for (int ks = 0; ks < 2; ks++) {
            uint4 af[4]; uint2 bf[4];
            #pragma unroll
            for (int i = 0; i < 4; i++) LDSM_X4(af[i], s + aoff[ks][i]);
            #pragma unroll
            for (int j = 0; j < 4; j++) LDSM_X2(bf[j], s + boff[ks][j]);
            #pragma unroll
            for (int i = 0; i < 4; i++)
                #pragma unroll
                for (int j = 0; j < 4; j++)
                    mma_bf16(acc[i][j], af[i], bf[j]);
        }
    }

    // epilogue: C frag c0=(r,2c) c1=(r,2c+1) c2=(r+8,2c) c3=(r+8,2c+1)
    #pragma unroll
    for (int i = 0; i < 4; i++) {
        int r0 = m0 + wm * 64 + i * 16 + (lane >> 2);
        #pragma unroll
        for (int j = 0; j < 4; j++) {
            int c = n0 + wn * 32 + j * 8 + (lane & 3) * 2;
            float b0 = bias[c], b1 = bias[c + 1];
            size_t o0 = (size_t)r0 * N + c;
            size_t o1 = (size_t)(r0 + 8) * N + c;
            float2 v0 = make_float2(acc[i][j][0] + b0, acc[i][j][1] + b1);
            float2 v1 = make_float2(acc[i][j][2] + b0, acc[i][j][3] + b1);
            if (res) {
                float2 e0 = *(const float2*)(res + o0);
                float2 e1 = *(const float2*)(res + o1);
                v0.x += e0.x; v0.y += e0.y;
                v1.x += e1.x; v1.y += e1.y;
            }
            *(float2*)(C + o0) = v0;
            *(float2*)(C + o1) = v1;
        }
    }
}

// ---------------------------------------------------------------------------
// RoPE apply (fp32 q,k in place)
// ---------------------------------------------------------------------------
__global__ __launch_bounds__(256)
void rope_kernel(float* __restrict__ q, float* __restrict__ k,
                 const float2* __restrict__ tab)
{
    int idx = blockIdx.x * 256 + threadIdx.x;
    float* base = (blockIdx.y == 0) ? q : k;

    int j   = idx & 63;
    int hh  = (idx >> 6) & (NH - 1);
    int row = idx >> 10;
    int pos = row & (S_ - 1);

    float2 cs = tab[(pos << 6) + j];
    float c = cs.x, s = cs.y;

    float* p = base + (size_t)row * DM + (hh << 7) + j;
    float x0 = p[0], x1 = p[64];
    p[0]  = x0 * c - x1 * s;
    p[64] = x1 * c + x0 * s;
}

// ---------------------------------------------------------------------------
// TF32 tensor-core flash attention, causal. Output written as bf16.
// ---------------------------------------------------------------------------
#define QKPAD 132
#define VPAD  136
#define SSPAD 68

__global__ __launch_bounds__(256)
void attn_tc_kernel(const float* __restrict__ q, const float* __restrict__ k,
                    const float* __restrict__ v, __nv_bfloat16* __restrict__ o)
{
    extern __shared__ float sm[];
    uint32_t* Qs = (uint32_t*)sm;
    uint32_t* Ks = Qs + 64 * QKPAD;
    uint32_t* Vs = Ks + 64 * QKPAD;
    float* Ss  = (float*)(Vs + 64 * VPAD);
    float* m_s = Ss + 64 * SSPAD;
    float* l_s = m_s + 64;
    float* c_s = l_s + 64;

    int t = threadIdx.x;
    int lane = t & 31;
    int w = t >> 5;
    int wm = w >> 1;
    int wn = w & 1;
    int lr = lane >> 2;
    int lc = lane & 3;

    int q0 = blockIdx.x << 6;
    size_t base = ((size_t)blockIdx.z * S_) * DM + ((size_t)blockIdx.y << 7);

    #pragma unroll
    for (int it = 0; it < 8; it++) {
        int idx = t + (it << 8);
        int r = idx >> 5, c4 = idx & 31;
        float4 x = *(const float4*)(q + base + (size_t)(q0 + r) * DM + (c4 << 2));
        uint32_t* dst = Qs + r * QKPAD + (c4 << 2);
        dst[0] = f2tf32(x.x); dst[1] = f2tf32(x.y);
        dst[2] = f2tf32(x.z); dst[3] = f2tf32(x.w);
    }
    if (t < 64) { m_s[t] = -INFINITY; l_s[t] = 0.f; }

    float oacc[8][4];
    #pragma unroll
    for (int i = 0; i < 8; i++)
        #pragma unroll
        for (int r = 0; r < 4; r++) oacc[i][r] = 0.f;

    for (int j0 = 0; j0 <= q0; j0 += 64) {
        #pragma unroll
        for (int it = 0; it < 8; it++) {
            int idx = t + (it << 8);
            int r = idx >> 5, c4 = idx & 31;
            size_t goff = base + (size_t)(j0 + r) * DM + (c4 << 2);
            float4 xk = *(const float4*)(k + goff);
            uint32_t* dk = Ks + r * QKPAD + (c4 << 2);
            dk[0] = f2tf32(xk.x); dk[1] = f2tf32(xk.y);
            dk[2] = f2tf32(xk.z); dk[3] = f2tf32(xk.w);
            float4 xv = *(const float4*)(v + goff);
            uint32_t* dv = Vs + r * VPAD + (c4 << 2);
            dv[0] = f2tf32(xv.x); dv[1] = f2tf32(xv.y);
            dv[2] = f2tf32(xv.z); dv[3] = f2tf32(xv.w);
        }
        __syncthreads();

        float sacc[4][4];
        #pragma unroll
        for (int nf = 0; nf < 4; nf++)
            #pragma unroll
            for (int r = 0; r < 4; r++) sacc[nf][r] = 0.f;

        #pragma unroll
        for (int kf = 0; kf < 16; kf++) {
            int kd = kf << 3;
            const uint32_t* ap = Qs + (wm * 16 + lr) * QKPAD + kd + lc;
            uint4 af;
            af.x = ap[0];
            af.y = ap[8 * QKPAD];
            af.z = ap[4];
            af.w = ap[8 * QKPAD + 4];
            #pragma unroll
            for (int nf = 0; nf < 4; nf++) {
                const uint32_t* bp = Ks + (wn * 32 + nf * 8 + lr) * QKPAD + kd + lc;
                uint2 bf;
                bf.x = bp[0];
                bf.y = bp[4];
                mma_tf32(sacc[nf], af, bf);
            }
        }

        const float sc = 0.08838834764831845f;
        int r_lo = wm * 16 + lr, r_hi = r_lo + 8;
        int qi_lo = q0 + r_lo,  qi_hi = q0 + r_hi;
        #pragma unroll
        for (int nf = 0; nf < 4; nf++) {
            int col = wn * 32 + nf * 8 + lc * 2;
            int kj = j0 + col;
            float v0 = sacc[nf][0] * sc, v1 = sacc[nf][1] * sc;
            float v2 = sacc[nf][2] * sc, v3 = sacc[nf][3] * sc;
            if (kj     > qi_lo) v0 = -INFINITY;
            if (kj + 1 > qi_lo) v1 = -INFINITY;
            if (kj     > qi_hi) v2 = -INFINITY;
            if (kj + 1 > qi_hi) v3 = -INFINITY;
            Ss[r_lo * SSPAD + col]     = v0;
            Ss[r_lo * SSPAD + col + 1] = v1;
            Ss[r_hi * SSPAD + col]     = v2;
            Ss[r_hi * SSPAD + col + 1] = v3;
        }
        __syncthreads();

        #pragma unroll
        for (int r8 = 0; r8 < 8; r8++) {
            int r = (w << 3) + r8;
            float s0 = Ss[r * SSPAD + lane];
            float s1 = Ss[r * SSPAD + 32 + lane];
            float mx = fmaxf(s0, s1);
            #pragma unroll
            for (int off = 16; off; off >>= 1)
                mx = fmaxf(mx, __shfl_xor_sync(0xffffffffu, mx, off));
            float mold = m_s[r];
            float mn = fmaxf(mold, mx);
            float e0 = expf(s0 - mn);
            float e1 = expf(s1 - mn);
            e0 = __uint_as_float(f2tf32(e0));
            e1 = __uint_as_float(f2tf32(e1));
            Ss[r * SSPAD + lane]      = e0;
            Ss[r * SSPAD + 32 + lane] = e1;
            float sum = e0 + e1;
            #pragma unroll
            for (int off = 16; off; off >>= 1)
                sum += __shfl_xor_sync(0xffffffffu, sum, off);
            if (lane == 0) {
                float corr = expf(mold - mn);
                l_s[r] = l_s[r] * corr + sum;
                m_s[r] = mn;
                c_s[r] = corr;
            }
        }
        __syncthreads();

        float corr_lo = c_s[r_lo];
        float corr_hi = c_s[r_hi];
        #pragma unroll
        for (int nf = 0; nf < 8; nf++) {
            oacc[nf][0] *= corr_lo; oacc[nf][1] *= corr_lo;
            oacc[nf][2] *= corr_hi; oacc[nf][3] *= corr_hi;
        }

        #pragma unroll
        for (int kf = 0; kf < 8; kf++) {
            int kk = kf << 3;
            const float* pp = Ss + (wm * 16 + lr) * SSPAD + kk + lc;
            uint4 af;
            af.x = __float_as_uint(pp[0]);
            af.y = __float_as_uint(pp[8 * SSPAD]);
            af.z = __float_as_uint(pp[4]);
            af.w = __float_as_uint(pp[8 * SSPAD + 4]);
            #pragma unroll
            for (int nf = 0; nf < 8; nf++) {
                const uint32_t* bp = Vs + (kk + lc) * VPAD + wn * 64 + nf * 8 + lr;
                uint2 bf;
                bf.x = bp[0];
                bf.y = bp[4 * VPAD];
                mma_tf32(oacc[nf], af, bf);
            }
        }
        __syncthreads();
    }

    {
        int r_lo = wm * 16 + lr, r_hi = r_lo + 8;
        float inv_lo = 1.0f / l_s[r_lo];
        float inv_hi = 1.0f / l_s[r_hi];
        #pragma unroll
        for (int nf = 0; nf < 8; nf++) {
            int col = wn * 64 + nf * 8 + lc * 2;
            __nv_bfloat16* d0 = o + base + (size_t)(q0 + r_lo) * DM + col;
            __nv_bfloat16* d1 = o + base + (size_t)(q0 + r_hi) * DM + col;
            *(uint32_t*)d0 = packbf2(oacc[nf][0] * inv_lo, oacc[nf][1] * inv_lo);
            *(uint32_t*)d1 = packbf2(oacc[nf][2] * inv_hi, oacc[nf][3] * inv_hi);
        }
    }
}

// ---------------------------------------------------------------------------
// Launch
// ---------------------------------------------------------------------------
extern "C" void kernel_launch(void* const* d_in, const int* in_sizes, int n_in,
                              void* d_out, int out_size)
{
    const float* h  = (const float*)d_in[0];
    const float* wq = (const float*)d_in[1];
    const float* bq = (const float*)d_in[2];
    const float* wk = (const float*)d_in[3];
    const float* bk = (const float*)d_in[4];
    const float* wv = (const float*)d_in[5];
    const float* bv = (const float*)d_in[6];
    const float* wo = (const float*)d_in[7];
    const float* bo = (const float*)d_in[8];
    const float* lg = (const float*)d_in[9];
    const float* lb = (const float*)d_in[10];
    float* out = (float*)d_out;

    float *xn, *qb, *kb, *vb, *ob;
    __nv_bfloat16* wb;
    float2* rt;
    cudaGetSymbolAddress((void**)&xn, g_xn);
    cudaGetSymbolAddress((void**)&qb, g_q);
    cudaGetSymbolAddress((void**)&kb, g_k);
    cudaGetSymbolAddress((void**)&vb, g_v);
    cudaGetSymbolAddress((void**)&ob, g_o);
    cudaGetSymbolAddress((void**)&wb, g_wb);
    cudaGetSymbolAddress((void**)&rt, g_rope);

    __nv_bfloat16* xn_bf = (__nv_bfloat16*)xn;
    __nv_bfloat16* ob_bf = (__nv_bfloat16*)ob;
    __nv_bfloat16* wq_bf = wb;
    __nv_bfloat16* wk_bf = wb + (size_t)DM * DM;
    __nv_bfloat16* wv_bf = wb + 2 * (size_t)DM * DM;
    __nv_bfloat16* wo_bf = wb + 3 * (size_t)DM * DM;

    // 0. RoPE table + weight conversions (tiny)
    rope_table_kernel<<<(S_ * 64 + 255) / 256, 256>>>(rt);
    int n4 = DM * DM / 4;
    wconv_kernel<<<(n4 + 255) / 256, 256>>>(wq, wq_bf, n4);
    wconv_kernel<<<(n4 + 255) / 256, 256>>>(wk, wk_bf, n4);
    wconv_kernel<<<(n4 + 255) / 256, 256>>>(wv, wv_bf, n4);
    wconv_kernel<<<(n4 + 255) / 256, 256>>>(wo, wo_bf, n4);

    // 1. LayerNorm (bf16 out)
    ln_kernel<<<MROWS, 256>>>(h, lg, lb, xn_bf);

    // 2. QKV projections (bf16 mma pipeline)
    int smem_g = BSTAGES * BSTAGE_BYTES;     // 81920
    cudaFuncSetAttribute(bgemm_nt, cudaFuncAttributeMaxDynamicSharedMemorySize,
                         smem_g);
    dim3 gg(DM / 128, MROWS / 128);
    bgemm_nt<<<gg, 256, smem_g>>>(xn_bf, wq_bf, bq, nullptr, qb, DM, DM);
    bgemm_nt<<<gg, 256, smem_g>>>(xn_bf, wk_bf, bk, nullptr, kb, DM, DM);
    bgemm_nt<<<gg, 256, smem_g>>>(xn_bf, wv_bf, bv, nullptr, vb, DM, DM);

    // 3. RoPE on q, k (fp32)
    rope_kernel<<<dim3((MROWS * NH * 64) / 256, 2), 256>>>(qb, kb, rt);

    // 4. Causal flash attention (tf32 mma.sync, bf16 out)
    int smem_attn = (64 * QKPAD * 2 + 64 * VPAD + 64 * SSPAD + 192) * 4;
    cudaFuncSetAttribute(attn_tc_kernel, cudaFuncAttributeMaxDynamicSharedMemorySize,
                         smem_attn);
    attn_tc_kernel<<<dim3(S_ / 64, NH, B_), 256, smem_attn>>>(qb, kb, vb, ob_bf);

    // 5. Output projection + bias + residual
    bgemm_nt<<<gg, 256, smem_g>>>(ob_bf, wo_bf, bo, h, out, DM, DM);
}

// round 10
// speedup vs baseline: 5.2256x; 1.2753x over previous
#include <cuda_runtime.h>
#include <cuda_bf16.h>
#include <math.h>
#include <stdint.h>

// Problem constants (fixed shapes)
#define B_    2
#define S_    2048
#define DM    2048
#define NH    16
#define DK_   128
#define MROWS (B_ * S_)      // 4096
#define EPS_  1e-5f

// ---------------------------------------------------------------------------
// Scratch (no cudaMalloc allowed)
// ---------------------------------------------------------------------------
__device__ float g_xn[(size_t)MROWS * DM];   // reused as bf16
__device__ float g_q [(size_t)MROWS * DM];
__device__ float g_k [(size_t)MROWS * DM];
__device__ float g_v [(size_t)MROWS * DM];
__device__ float g_o [(size_t)MROWS * DM];   // reused as bf16
__device__ __nv_bfloat16 g_wb[4][(size_t)DM * DM];  // bf16 weights
__device__ float2 g_rope[(size_t)S_ * 64];   // (cos, sin) per (pos, j)

// ---------------------------------------------------------------------------
// helpers
// ---------------------------------------------------------------------------
__device__ __forceinline__ uint32_t packbf2(float a, float b)
{
    __nv_bfloat162 h = __floats2bfloat162_rn(a, b);
    return *(uint32_t*)&h;
}

__device__ __forceinline__ void mma_bf16(float* c, const uint4& a, const uint2& b)
{
    asm volatile(
        "mma.sync.aligned.m16n8k16.row.col.f32.bf16.bf16.f32 "
        "{%0,%1,%2,%3}, {%4,%5,%6,%7}, {%8,%9}, {%0,%1,%2,%3};\n"
        : "+f"(c[0]), "+f"(c[1]), "+f"(c[2]), "+f"(c[3])
        : "r"(a.x), "r"(a.y), "r"(a.z), "r"(a.w), "r"(b.x), "r"(b.y));
}

#define CP_ASYNC16(dst, src) \
    asm volatile("cp.async.cg.shared.global [%0], [%1], 16;" \
                 :: "r"((uint32_t)(dst)), "l"(src))
#define CP_COMMIT() asm volatile("cp.async.commit_group;" ::: "memory")
#define CP_WAIT(N)  asm volatile("cp.async.wait_group %0;" :: "n"(N) : "memory")

#define LDSM_X4(d, addr) \
    asm volatile("ldmatrix.sync.aligned.m8n8.x4.shared.b16 {%0,%1,%2,%3}, [%4];" \
                 : "=r"((d).x), "=r"((d).y), "=r"((d).z), "=r"((d).w) \
                 : "r"((uint32_t)(addr)))
#define LDSM_X2(d, addr) \
    asm volatile("ldmatrix.sync.aligned.m8n8.x2.shared.b16 {%0,%1}, [%2];" \
                 : "=r"((d).x), "=r"((d).y) \
                 : "r"((uint32_t)(addr)))
#define LDSM_X2T(d, addr) \
    asm volatile("ldmatrix.sync.aligned.m8n8.x2.trans.shared.b16 {%0,%1}, [%2];" \
                 : "=r"((d).x), "=r"((d).y) \
                 : "r"((uint32_t)(addr)))

// ---------------------------------------------------------------------------
// Weight conversion fp32 -> bf16 (rn)
// ---------------------------------------------------------------------------
__global__ __launch_bounds__(256)
void wconv_kernel(const float* __restrict__ src, __nv_bfloat16* __restrict__ dst,
                  int n4)
{
    int i = blockIdx.x * 256 + threadIdx.x;
    if (i >= n4) return;
    float4 x = ((const float4*)src)[i];
    uint2 u;
    u.x = packbf2(x.x, x.y);
    u.y = packbf2(x.z, x.w);
    ((uint2*)dst)[i] = u;
}

// ---------------------------------------------------------------------------
// RoPE table: accurate double-precision sincos of the fp32-quantized phase.
// ---------------------------------------------------------------------------
__global__ __launch_bounds__(256)
void rope_table_kernel(float2* __restrict__ tab)
{
    int idx = blockIdx.x * 256 + threadIdx.x;     // [0, S_*64)
    if (idx >= S_ * 64) return;
    int j   = idx & 63;
    int pos = idx >> 6;
    double theta_d = 1.0 / pow(10000.0, (double)j / 64.0);
    float  theta_f = (float)theta_d;
    float fr = (float)pos * theta_f;
    double dfr = (double)fr;
    tab[idx] = make_float2((float)cos(dfr), (float)sin(dfr));
}

// ---------------------------------------------------------------------------
// LayerNorm (outputs bf16)
// ---------------------------------------------------------------------------
__global__ __launch_bounds__(256)
void ln_kernel(const float* __restrict__ x, const float* __restrict__ g,
               const float* __restrict__ bb, __nv_bfloat16* __restrict__ out)
{
    int row = blockIdx.x;
    int t = threadIdx.x;
    const float4* xr = (const float4*)(x + (size_t)row * DM);
    uint2* orow = (uint2*)(out + (size_t)row * DM);

    float4 v0 = xr[t];
    float4 v1 = xr[t + 256];
    float sum = v0.x + v0.y + v0.z + v0.w + v1.x + v1.y + v1.z + v1.w;
    float sq  = v0.x*v0.x + v0.y*v0.y + v0.z*v0.z + v0.w*v0.w
              + v1.x*v1.x + v1.y*v1.y + v1.z*v1.z + v1.w*v1.w;

    #pragma unroll
    for (int off = 16; off; off >>= 1) {
        sum += __shfl_xor_sync(0xffffffffu, sum, off);
        sq  += __shfl_xor_sync(0xffffffffu, sq,  off);
    }
    __shared__ float s_sum[8], s_sq[8];
    int w = t >> 5;
    if ((t & 31) == 0) { s_sum[w] = sum; s_sq[w] = sq; }
    __syncthreads();
    if (t < 32) {
        float a = (t < 8) ? s_sum[t] : 0.f;
        float b = (t < 8) ? s_sq[t]  : 0.f;
        #pragma unroll
        for (int off = 4; off; off >>= 1) {
            a += __shfl_xor_sync(0xffffffffu, a, off);
            b += __shfl_xor_sync(0xffffffffu, b, off);
        }
        if (t == 0) { s_sum[0] = a; s_sq[0] = b; }
    }
    __syncthreads();

    float mu  = s_sum[0] * (1.0f / DM);
    float var = s_sq[0] * (1.0f / DM) - mu * mu;
    float rstd = rsqrtf(var + EPS_);

    const float4* g4 = (const float4*)g;
    const float4* b4 = (const float4*)bb;
    {
        float4 gv = g4[t], bv = b4[t];
        uint2 u;
        u.x = packbf2((v0.x - mu) * rstd * gv.x + bv.x,
                      (v0.y - mu) * rstd * gv.y + bv.y);
        u.y = packbf2((v0.z - mu) * rstd * gv.z + bv.z,
                      (v0.w - mu) * rstd * gv.w + bv.w);
        orow[t] = u;
    }
    {
        float4 gv = g4[t + 256], bv = b4[t + 256];
        uint2 u;
        u.x = packbf2((v1.x - mu) * rstd * gv.x + bv.x,
                      (v1.y - mu) * rstd * gv.y + bv.y);
        u.y = packbf2((v1.z - mu) * rstd * gv.z + bv.z,
                      (v1.w - mu) * rstd * gv.w + bv.w);
        orow[t + 256] = u;
    }
}

// ---------------------------------------------------------------------------
// Pipelined BF16 GEMM NT (unchanged from R9)
// ---------------------------------------------------------------------------
#define BSTAGES 4
#define BROWB   80
#define BSTAGE_BYTES 20480      // 2 * 128 * 80

__global__ __launch_bounds__(256, 2)
void bgemm_nt(const __nv_bfloat16* __restrict__ A,
              const __nv_bfloat16* __restrict__ W,
              const float* __restrict__ bias, const float* __restrict__ res,
              float* __restrict__ C, int K, int N)
{
    extern __shared__ char smem[];
    uint32_t sb = (uint32_t)__cvta_generic_to_shared(smem);

    int t = threadIdx.x;
    int lane = t & 31;
    int w = t >> 5;
    int wm = w >> 2, wn = w & 3;
    int m0 = blockIdx.y << 7, n0 = blockIdx.x << 7;

    int lm = t >> 2;
    int kq = t & 3;
    const __nv_bfloat16* gA0 = A + (size_t)(m0 + lm) * K + kq * 8;
    const __nv_bfloat16* gA1 = gA0 + (size_t)64 * K;
    const __nv_bfloat16* gW0 = W + (size_t)(n0 + lm) * K + kq * 8;
    const __nv_bfloat16* gW1 = gW0 + (size_t)64 * K;
    uint32_t dA0 = (uint32_t)lm * BROWB + kq * 16;
    uint32_t dA1 = dA0 + 64 * BROWB;
    uint32_t dB0 = 10240 + dA0;
    uint32_t dB1 = 10240 + dA1;

    int aoff[2][4], boff[2][4];
    #pragma unroll
    for (int ks = 0; ks < 2; ks++) {
        #pragma unroll
        for (int i = 0; i < 4; i++) {
            int mrow = (wm * 4 + i) * 16 + (lane & 7) + ((lane >> 3) & 1) * 8;
            aoff[ks][i] = mrow * BROWB + ks * 32 + (lane >> 4) * 16;
            int nrow = (wn * 4 + i) * 8 + (lane & 7);
            boff[ks][i] = 10240 + nrow * BROWB + ks * 32 + ((lane >> 3) & 1) * 16;
        }
    }

    float acc[4][4][4];
    #pragma unroll
    for (int i = 0; i < 4; i++)
        #pragma unroll
        for (int j = 0; j < 4; j++)
            #pragma unroll
            for (int r = 0; r < 4; r++) acc[i][j][r] = 0.f;

    const int nIter = K >> 5;

    auto load_stage = [&](int c) {
        uint32_t s = sb + (uint32_t)(c & 3) * BSTAGE_BYTES;
        int ko = c << 5;
        CP_ASYNC16(s + dA0, gA0 + ko);
        CP_ASYNC16(s + dA1, gA1 + ko);
        CP_ASYNC16(s + dB0, gW0 + ko);
        CP_ASYNC16(s + dB1, gW1 + ko);
        CP_COMMIT();
    };

    load_stage(0); load_stage(1); load_stage(2);

    for (int c = 0; c < nIter; c++) {
        if (c <= nIter - 3)      CP_WAIT(2);
        else if (c == nIter - 2) CP_WAIT(1);
        else                     CP_WAIT(0);
        __syncthreads();

        if (c + 3 < nIter) load_stage(c + 3);

        uint32_t s = sb + (uint32_t)(c & 3) * BSTAGE_BYTES;
        #pragma unroll
        for (int ks = 0; ks < 2; ks++) {
            uint4 af[4]; uint2 bf[4];
            #pragma unroll
            for (int i = 0; i < 4; i++) LDSM_X4(af[i], s + aoff[ks][i]);
            #pragma unroll
            for (int j = 0; j < 4; j++) LDSM_X2(bf[j], s + boff[ks][j]);
            #pragma unroll
            for (int i = 0; i < 4; i++)
                #pragma unroll
                for (int j = 0; j < 4; j++)
                    mma_bf16(acc[i][j], af[i], bf[j]);
        }
    }

    #pragma unroll
    for (int i = 0; i < 4; i++) {
        int r0 = m0 + wm * 64 + i * 16 + (lane >> 2);
        #pragma unroll
        for (int j = 0; j < 4; j++) {
            int c = n0 + wn * 32 + j * 8 + (lane & 3) * 2;
            float b0 = bias[c], b1 = bias[c + 1];
            size_t o0 = (size_t)r0 * N + c;
            size_t o1 = (size_t)(r0 + 8) * N + c;
            float2 v0 = make_float2(acc[i][j][0] + b0, acc[i][j][1] + b1);
            float2 v1 = make_float2(acc[i][j][2] + b0, acc[i][j][3] + b1);
            if (res) {
                float2 e0 = *(const float2*)(res + o0);
                float2 e1 = *(const float2*)(res + o1);
                v0.x += e0.x; v0.y += e0.y;
                v1.x += e1.x; v1.y += e1.y;
            }
            *(float2*)(C + o0) = v0;
            *(float2*)(C + o1) = v1;
        }
    }
}

// ---------------------------------------------------------------------------
// RoPE apply (fp32 q,k in place)
// ---------------------------------------------------------------------------
__global__ __launch_bounds__(256)
void rope_kernel(float* __restrict__ q, float* __restrict__ k,
                 const float2* __restrict__ tab)
{
    int idx = blockIdx.x * 256 + threadIdx.x;
    float* base = (blockIdx.y == 0) ? q : k;

    int j   = idx & 63;
    int hh  = (idx >> 6) & (NH - 1);
    int row = idx >> 10;
    int pos = row & (S_ - 1);

    float2 cs = tab[(pos << 6) + j];
    float c = cs.x, s = cs.y;

    float* p = base + (size_t)row * DM + (hh << 7) + j;
    float x0 = p[0], x1 = p[64];
    p[0]  = x0 * c - x1 * s;
    p[64] = x1 * c + x0 * s;
}

// ---------------------------------------------------------------------------
// BF16 tensor-core flash attention, causal. mma.m16n8k16 everywhere.
// Q/K/V bf16 in smem (row stride 272B: (17r)%32 conflict-free ldmatrix).
// S fp32 in smem (softmax), P bf16 (row stride 144B: (9r)%32 distinct).
// PV uses ldmatrix.x2.trans on row-major V. l sums bf16-rounded P.
// ---------------------------------------------------------------------------
#define AROWB  272
#define A_Q    0
#define A_K    17408
#define A_V    34816
#define A_SS   52224                 // fp32 64 x 68
#define SSPAD  68
#define A_PS   69632                 // bf16 64 x 72 (144B rows)
#define A_ST   78848                 // stats
#define A_SMEM 79616

__global__ __launch_bounds__(256)
void attn_bf_kernel(const float* __restrict__ q, const float* __restrict__ k,
                    const float* __restrict__ v, __nv_bfloat16* __restrict__ o)
{
    extern __shared__ char sm[];
    uint32_t sb = (uint32_t)__cvta_generic_to_shared(sm);
    float* Ss = (float*)(sm + A_SS);
    __nv_bfloat16* Ps = (__nv_bfloat16*)(sm + A_PS);
    float* m_s = (float*)(sm + A_ST);
    float* l_s = m_s + 64;
    float* c_s = l_s + 64;

    int t = threadIdx.x;
    int lane = t & 31;
    int w = t >> 5;
    int wm = w >> 1;          // 0..3 : 16-row group
    int wn = w & 1;           // 0..1
    int lr = lane >> 2;
    int lc = lane & 3;

    int q0 = blockIdx.x << 6;
    size_t base = ((size_t)blockIdx.z * S_) * DM + ((size_t)blockIdx.y << 7);

    // ---- load Q tile (fp32 -> bf16) ----
    #pragma unroll
    for (int it = 0; it < 8; it++) {
        int idx = t + (it << 8);
        int r = idx >> 5, c4 = idx & 31;
        float4 x = *(const float4*)(q + base + (size_t)(q0 + r) * DM + (c4 << 2));
        uint2 u;
        u.x = packbf2(x.x, x.y);
        u.y = packbf2(x.z, x.w);
        *(uint2*)(sm + A_Q + r * AROWB + c4 * 8) = u;
    }
    if (t < 64) { m_s[t] = -INFINITY; l_s[t] = 0.f; }

    float oacc[8][4];
    #pragma unroll
    for (int i = 0; i < 8; i++)
        #pragma unroll
        for (int r = 0; r < 4; r++) oacc[i][r] = 0.f;

    __syncthreads();

    for (int j0 = 0; j0 <= q0; j0 += 64) {
        // ---- load K, V tiles (fp32 -> bf16) ----
        #pragma unroll
        for (int it = 0; it < 8; it++) {
            int idx = t + (it << 8);
            int r = idx >> 5, c4 = idx & 31;
            size_t goff = base + (size_t)(j0 + r) * DM + (c4 << 2);
            float4 xk = *(const float4*)(k + goff);
            uint2 uk;
            uk.x = packbf2(xk.x, xk.y);
            uk.y = packbf2(xk.z, xk.w);
            *(uint2*)(sm + A_K + r * AROWB + c4 * 8) = uk;
            float4 xv = *(const float4*)(v + goff);
            uint2 uv;
            uv.x = packbf2(xv.x, xv.y);
            uv.y = packbf2(xv.z, xv.w);
            *(uint2*)(sm + A_V + r * AROWB + c4 * 8) = uv;
        }
        __syncthreads();

        // ---- S = Q K^T : warp tile rows [wm*16,+16), cols [wn*32,+32) ----
        float sacc[4][4];
        #pragma unroll
        for (int nf = 0; nf < 4; nf++)
            #pragma unroll
            for (int r = 0; r < 4; r++) sacc[nf][r] = 0.f;

        #pragma unroll
        for (int ks = 0; ks < 8; ks++) {
            uint4 af;
            LDSM_X4(af, sb + A_Q + (wm * 16 + (lane & 15)) * AROWB
                        + ks * 32 + (lane >> 4) * 16);
            #pragma unroll
            for (int nf = 0; nf < 4; nf++) {
                uint2 bf;
                LDSM_X2(bf, sb + A_K + (wn * 32 + nf * 8 + (lane & 7)) * AROWB
                            + ks * 32 + ((lane >> 3) & 1) * 16);
                mma_bf16(sacc[nf], af, bf);
            }
        }

        // ---- scale + causal mask + store S (fp32) ----
        const float sc = 0.08838834764831845f;   // 1/sqrt(128)
        int r_lo = wm * 16 + lr, r_hi = r_lo + 8;
        int qi_lo = q0 + r_lo,  qi_hi = q0 + r_hi;
        #pragma unroll
        for (int nf = 0; nf < 4; nf++) {
            int col = wn * 32 + nf * 8 + lc * 2;
            int kj = j0 + col;
            float v0 = sacc[nf][0] * sc, v1 = sacc[nf][1] * sc;
            float v2 = sacc[nf][2] * sc, v3 = sacc[nf][3] * sc;
            if (kj     > qi_lo) v0 = -INFINITY;
            if (kj + 1 > qi_lo) v1 = -INFINITY;
            if (kj     > qi_hi) v2 = -INFINITY;
            if (kj + 1 > qi_hi) v3 = -INFINITY;
            Ss[r_lo * SSPAD + col]     = v0;
            Ss[r_lo * SSPAD + col + 1] = v1;
            Ss[r_hi * SSPAD + col]     = v2;
            Ss[r_hi * SSPAD + col + 1] = v3;
        }
        __syncthreads();

        // ---- online softmax: warp w owns rows w*8..w*8+7; P -> bf16 ----
        #pragma unroll
        for (int r8 = 0; r8 < 8; r8++) {
            int r = (w << 3) + r8;
            float s0 = Ss[r * SSPAD + lane];
            float s1 = Ss[r * SSPAD + 32 + lane];
            float mx = fmaxf(s0, s1);
            #pragma unroll
            for (int off = 16; off; off >>= 1)
                mx = fmaxf(mx, __shfl_xor_sync(0xffffffffu, mx, off));
            float mold = m_s[r];
            float mn = fmaxf(mold, mx);
            __nv_bfloat16 b0 = __float2bfloat16(expf(s0 - mn));
            __nv_bfloat16 b1 = __float2bfloat16(expf(s1 - mn));
            Ps[r * 72 + lane]      = b0;
            Ps[r * 72 + 32 + lane] = b1;
            float sum = __bfloat162float(b0) + __bfloat162float(b1);
            #pragma unroll
            for (int off = 16; off; off >>= 1)
                sum += __shfl_xor_sync(0xffffffffu, sum, off);
            if (lane == 0) {
                float corr = expf(mold - mn);
                l_s[r] = l_s[r] * corr + sum;
                m_s[r] = mn;
                c_s[r] = corr;
            }
        }
        __syncthreads();

        // ---- rescale O, then O += P V : warp rows [wm*16,+16), cols [wn*64,+64)
        float corr_lo = c_s[r_lo];
        float corr_hi = c_s[r_hi];
        #pragma unroll
        for (int nf = 0; nf < 8; nf++) {
            oacc[nf][0] *= corr_lo; oacc[nf][1] *= corr_lo;
            oacc[nf][2] *= corr_hi; oacc[nf][3] *= corr_hi;
        }

        #pragma unroll
        for (int kf = 0; kf < 4; kf++) {
            uint4 af;
            LDSM_X4(af, sb + A_PS + (wm * 16 + (lane & 15)) * 144
                        + kf * 32 + (lane >> 4) * 16);
            #pragma unroll
            for (int nf = 0; nf < 8; nf++) {
                uint2 bf;
                LDSM_X2T(bf, sb + A_V
                             + (kf * 16 + ((lane >> 3) & 1) * 8 + (lane & 7)) * AROWB
                             + (wn * 64 + nf * 8) * 2);
                mma_bf16(oacc[nf], af, bf);
            }
        }
        __syncthreads();
    }

    // ---- epilogue: O / l -> bf16 ----
    {
        int r_lo = wm * 16 + lr, r_hi = r_lo + 8;
        float inv_lo = 1.0f / l_s[r_lo];
        float inv_hi = 1.0f / l_s[r_hi];
        #pragma unroll
        for (int nf = 0; nf < 8; nf++) {
            int col = wn * 64 + nf * 8 + lc * 2;
            __nv_bfloat16* d0 = o + base + (size_t)(q0 + r_lo) * DM + col;
            __nv_bfloat16* d1 = o + base + (size_t)(q0 + r_hi) * DM + col;
            *(uint32_t*)d0 = packbf2(oacc[nf][0] * inv_lo, oacc[nf][1] * inv_lo);
            *(uint32_t*)d1 = packbf2(oacc[nf][2] * inv_hi, oacc[nf][3] * inv_hi);
        }
    }
}

// ---------------------------------------------------------------------------
// Launch
// ---------------------------------------------------------------------------
extern "C" void kernel_launch(void* const* d_in, const int* in_sizes, int n_in,
                              void* d_out, int out_size)
{
    const float* h  = (const float*)d_in[0];
    const float* wq = (const float*)d_in[1];
    const float* bq = (const float*)d_in[2];
    const float* wk = (const float*)d_in[3];
    const float* bk = (const float*)d_in[4];
    const float* wv = (const float*)d_in[5];
    const float* bv = (const float*)d_in[6];
    const float* wo = (const float*)d_in[7];
    const float* bo = (const float*)d_in[8];
    const float* lg = (const float*)d_in[9];
    const float* lb = (const float*)d_in[10];
    float* out = (float*)d_out;

    float *xn, *qb, *kb, *vb, *ob;
    __nv_bfloat16* wb;
    float2* rt;
    cudaGetSymbolAddress((void**)&xn, g_xn);
    cudaGetSymbolAddress((void**)&qb, g_q);
    cudaGetSymbolAddress((void**)&kb, g_k);
    cudaGetSymbolAddress((void**)&vb, g_v);
    cudaGetSymbolAddress((void**)&ob, g_o);
    cudaGetSymbolAddress((void**)&wb, g_wb);
    cudaGetSymbolAddress((void**)&rt, g_rope);

    __nv_bfloat16* xn_bf = (__nv_bfloat16*)xn;
    __nv_bfloat16* ob_bf = (__nv_bfloat16*)ob;
    __nv_bfloat16* wq_bf = wb;
    __nv_bfloat16* wk_bf = wb + (size_t)DM * DM;
    __nv_bfloat16* wv_bf = wb + 2 * (size_t)DM * DM;
    __nv_bfloat16* wo_bf = wb + 3 * (size_t)DM * DM;

    // 0. RoPE table + weight conversions
    rope_table_kernel<<<(S_ * 64 + 255) / 256, 256>>>(rt);
    int n4 = DM * DM / 4;
    wconv_kernel<<<(n4 + 255) / 256, 256>>>(wq, wq_bf, n4);
    wconv_kernel<<<(n4 + 255) / 256, 256>>>(wk, wk_bf, n4);
    wconv_kernel<<<(n4 + 255) / 256, 256>>>(wv, wv_bf, n4);
    wconv_kernel<<<(n4 + 255) / 256, 256>>>(wo, wo_bf, n4);

    // 1. LayerNorm (bf16 out)
    ln_kernel<<<MROWS, 256>>>(h, lg, lb, xn_bf);

    // 2. QKV projections (bf16 mma pipeline)
    int smem_g = BSTAGES * BSTAGE_BYTES;     // 81920
    cudaFuncSetAttribute(bgemm_nt, cudaFuncAttributeMaxDynamicSharedMemorySize,
                         smem_g);
    dim3 gg(DM / 128, MROWS / 128);
    bgemm_nt<<<gg, 256, smem_g>>>(xn_bf, wq_bf, bq, nullptr, qb, DM, DM);
    bgemm_nt<<<gg, 256, smem_g>>>(xn_bf, wk_bf, bk, nullptr, kb, DM, DM);
    bgemm_nt<<<gg, 256, smem_g>>>(xn_bf, wv_bf, bv, nullptr, vb, DM, DM);

    // 3. RoPE on q, k (fp32)
    rope_kernel<<<dim3((MROWS * NH * 64) / 256, 2), 256>>>(qb, kb, rt);

    // 4. Causal flash attention (bf16 mma, bf16 out)
    cudaFuncSetAttribute(attn_bf_kernel, cudaFuncAttributeMaxDynamicSharedMemorySize,
                         A_SMEM);
    attn_bf_kernel<<<dim3(S_ / 64, NH, B_), 256, A_SMEM>>>(qb, kb, vb, ob_bf);

    // 5. Output projection + bias + residual
    bgemm_nt<<<gg, 256, smem_g>>>(ob_bf, wo_bf, bo, h, out, DM, DM);
}

// round 12
// speedup vs baseline: 5.5540x; 1.0628x over previous
#include <cuda_runtime.h>
#include <cuda_bf16.h>
#include <math.h>
#include <stdint.h>

// Problem constants (fixed shapes)
#define B_    2
#define S_    2048
#define DM    2048
#define NH    16
#define DK_   128
#define MROWS (B_ * S_)      // 4096
#define EPS_  1e-5f

// ---------------------------------------------------------------------------
// Scratch (no cudaMalloc allowed)
// ---------------------------------------------------------------------------
__device__ float g_xn[(size_t)MROWS * DM];   // phase1: bf16 xn; phase2: bf16 q,k
__device__ float g_q [(size_t)MROWS * DM];   // fp32 q (pre-rope)
__device__ float g_k [(size_t)MROWS * DM];   // fp32 k (pre-rope)
__device__ float g_v [(size_t)MROWS * DM];   // bf16 v (from GEMM)
__device__ float g_o [(size_t)MROWS * DM];   // bf16 attention out
__device__ __nv_bfloat16 g_wb[4][(size_t)DM * DM];  // bf16 weights
__device__ float2 g_rope[(size_t)S_ * 64];   // (cos, sin) per (pos, j)

// ---------------------------------------------------------------------------
// helpers
// ---------------------------------------------------------------------------
__device__ __forceinline__ uint32_t packbf2(float a, float b)
{
    __nv_bfloat162 h = __floats2bfloat162_rn(a, b);
    return *(uint32_t*)&h;
}

__device__ __forceinline__ void mma_bf16(float* c, const uint4& a, const uint2& b)
{
    asm volatile(
        "mma.sync.aligned.m16n8k16.row.col.f32.bf16.bf16.f32 "
        "{%0,%1,%2,%3}, {%4,%5,%6,%7}, {%8,%9}, {%0,%1,%2,%3};\n"
        : "+f"(c[0]), "+f"(c[1]), "+f"(c[2]), "+f"(c[3])
        : "r"(a.x), "r"(a.y), "r"(a.z), "r"(a.w), "r"(b.x), "r"(b.y));
}

#define CP_ASYNC16(dst, src) \
    asm volatile("cp.async.cg.shared.global [%0], [%1], 16;" \
                 :: "r"((uint32_t)(dst)), "l"(src))
#define CP_COMMIT() asm volatile("cp.async.commit_group;" ::: "memory")
#define CP_WAIT(N)  asm volatile("cp.async.wait_group %0;" :: "n"(N) : "memory")

#define LDSM_X4(d, addr) \
    asm volatile("ldmatrix.sync.aligned.m8n8.x4.shared.b16 {%0,%1,%2,%3}, [%4];" \
                 : "=r"((d).x), "=r"((d).y), "=r"((d).z), "=r"((d).w) \
                 : "r"((uint32_t)(addr)))
#define LDSM_X2(d, addr) \
    asm volatile("ldmatrix.sync.aligned.m8n8.x2.shared.b16 {%0,%1}, [%2];" \
                 : "=r"((d).x), "=r"((d).y) \
                 : "r"((uint32_t)(addr)))
#define LDSM_X2T(d, addr) \
    asm volatile("ldmatrix.sync.aligned.m8n8.x2.trans.shared.b16 {%0,%1}, [%2];" \
                 : "=r"((d).x), "=r"((d).y) \
                 : "r"((uint32_t)(addr)))

// ---------------------------------------------------------------------------
// Weight conversion fp32 -> bf16 (rn)
// ---------------------------------------------------------------------------
__global__ __launch_bounds__(256)
void wconv_kernel(const float* __restrict__ src, __nv_bfloat16* __restrict__ dst,
                  int n4)
{
    int i = blockIdx.x * 256 + threadIdx.x;
    if (i >= n4) return;
    float4 x = ((const float4*)src)[i];
    uint2 u;
    u.x = packbf2(x.x, x.y);
    u.y = packbf2(x.z, x.w);
    ((uint2*)dst)[i] = u;
}

// ---------------------------------------------------------------------------
// RoPE table: accurate double-precision sincos of the fp32-quantized phase.
// ---------------------------------------------------------------------------
__global__ __launch_bounds__(256)
void rope_table_kernel(float2* __restrict__ tab)
{
    int idx = blockIdx.x * 256 + threadIdx.x;     // [0, S_*64)
    if (idx >= S_ * 64) return;
    int j   = idx & 63;
    int pos = idx >> 6;
    double theta_d = 1.0 / pow(10000.0, (double)j / 64.0);
    float  theta_f = (float)theta_d;
    float fr = (float)pos * theta_f;
    double dfr = (double)fr;
    tab[idx] = make_float2((float)cos(dfr), (float)sin(dfr));
}

// ---------------------------------------------------------------------------
// LayerNorm (outputs bf16)
// ---------------------------------------------------------------------------
__global__ __launch_bounds__(256)
void ln_kernel(const float* __restrict__ x, const float* __restrict__ g,
               const float* __restrict__ bb, __nv_bfloat16* __restrict__ out)
{
    int row = blockIdx.x;
    int t = threadIdx.x;
    const float4* xr = (const float4*)(x + (size_t)row * DM);
    uint2* orow = (uint2*)(out + (size_t)row * DM);

    float4 v0 = xr[t];
    float4 v1 = xr[t + 256];
    float sum = v0.x + v0.y + v0.z + v0.w + v1.x + v1.y + v1.z + v1.w;
    float sq  = v0.x*v0.x + v0.y*v0.y + v0.z*v0.z + v0.w*v0.w
              + v1.x*v1.x + v1.y*v1.y + v1.z*v1.z + v1.w*v1.w;

    #pragma unroll
    for (int off = 16; off; off >>= 1) {
        sum += __shfl_xor_sync(0xffffffffu, sum, off);
        sq  += __shfl_xor_sync(0xffffffffu, sq,  off);
    }
    __shared__ float s_sum[8], s_sq[8];
    int w = t >> 5;
    if ((t & 31) == 0) { s_sum[w] = sum; s_sq[w] = sq; }
    __syncthreads();
    if (t < 32) {
        float a = (t < 8) ? s_sum[t] : 0.f;
        float b = (t < 8) ? s_sq[t]  : 0.f;
        #pragma unroll
        for (int off = 4; off; off >>= 1) {
            a += __shfl_xor_sync(0xffffffffu, a, off);
            b += __shfl_xor_sync(0xffffffffu, b, off);
        }
        if (t == 0) { s_sum[0] = a; s_sq[0] = b; }
    }
    __syncthreads();

    float mu  = s_sum[0] * (1.0f / DM);
    float var = s_sq[0] * (1.0f / DM) - mu * mu;
    float rstd = rsqrtf(var + EPS_);

    const float4* g4 = (const float4*)g;
    const float4* b4 = (const float4*)bb;
    {
        float4 gv = g4[t], bv = b4[t];
        uint2 u;
        u.x = packbf2((v0.x - mu) * rstd * gv.x + bv.x,
                      (v0.y - mu) * rstd * gv.y + bv.y);
        u.y = packbf2((v0.z - mu) * rstd * gv.z + bv.z,
                      (v0.w - mu) * rstd * gv.w + bv.w);
        orow[t] = u;
    }
    {
        float4 gv = g4[t + 256], bv = b4[t + 256];
        uint2 u;
        u.x = packbf2((v1.x - mu) * rstd * gv.x + bv.x,
                      (v1.y - mu) * rstd * gv.y + bv.y);
        u.y = packbf2((v1.z - mu) * rstd * gv.z + bv.z,
                      (v1.w - mu) * rstd * gv.w + bv.w);
        orow[t + 256] = u;
    }
}

// ---------------------------------------------------------------------------
// Pipelined BF16 GEMM NT. Optional bf16 output (Cb != null) or fp32 (C).
// ---------------------------------------------------------------------------
#define BSTAGES 4
#define BROWB   80
#define BSTAGE_BYTES 20480      // 2 * 128 * 80

__global__ __launch_bounds__(256, 2)
void bgemm_nt(const __nv_bfloat16* __restrict__ A,
              const __nv_bfloat16* __restrict__ W,
              const float* __restrict__ bias, const float* __restrict__ res,
              float* __restrict__ C, __nv_bfloat16* __restrict__ Cb,
              int K, int N)
{
    extern __shared__ char smem[];
    uint32_t sb = (uint32_t)__cvta_generic_to_shared(smem);

    int t = threadIdx.x;
    int lane = t & 31;
    int w = t >> 5;
    int wm = w >> 2, wn = w & 3;
    int m0 = blockIdx.y << 7, n0 = blockIdx.x << 7;

    int lm = t >> 2;
    int kq = t & 3;
    const __nv_bfloat16* gA0 = A + (size_t)(m0 + lm) * K + kq * 8;
    const __nv_bfloat16* gA1 = gA0 + (size_t)64 * K;
    const __nv_bfloat16* gW0 = W + (size_t)(n0 + lm) * K + kq * 8;
    const __nv_bfloat16* gW1 = gW0 + (size_t)64 * K;
    uint32_t dA0 = (uint32_t)lm * BROWB + kq * 16;
    uint32_t dA1 = dA0 + 64 * BROWB;
    uint32_t dB0 = 10240 + dA0;
    uint32_t dB1 = 10240 + dA1;

    int aoff[2][4], boff[2][4];
    #pragma unroll
    for (int ks = 0; ks < 2; ks++) {
        #pragma unroll
        for (int i = 0; i < 4; i++) {
            int mrow = (wm * 4 + i) * 16 + (lane & 7) + ((lane >> 3) & 1) * 8;
            aoff[ks][i] = mrow * BROWB + ks * 32 + (lane >> 4) * 16;
            int nrow = (wn * 4 + i) * 8 + (lane & 7);
            boff[ks][i] = 10240 + nrow * BROWB + ks * 32 + ((lane >> 3) & 1) * 16;
        }
    }

    float acc[4][4][4];
    #pragma unroll
    for (int i = 0; i < 4; i++)
        #pragma unroll
        for (int j = 0; j < 4; j++)
            #pragma unroll
            for (int r = 0; r < 4; r++) acc[i][j][r] = 0.f;

    const int nIter = K >> 5;

    auto load_stage = [&](int c) {
        uint32_t s = sb + (uint32_t)(c & 3) * BSTAGE_BYTES;
        int ko = c << 5;
        CP_ASYNC16(s + dA0, gA0 + ko);
        CP_ASYNC16(s + dA1, gA1 + ko);
        CP_ASYNC16(s + dB0, gW0 + ko);
        CP_ASYNC16(s + dB1, gW1 + ko);
        CP_COMMIT();
    };

    load_stage(0); load_stage(1); load_stage(2);

    for (int c = 0; c < nIter; c++) {
        if (c <= nIter - 3)      CP_WAIT(2);
        else if (c == nIter - 2) CP_WAIT(1);
        else                     CP_WAIT(0);
        __syncthreads();

        if (c + 3 < nIter) load_stage(c + 3);

        uint32_t s = sb + (uint32_t)(c & 3) * BSTAGE_BYTES;
        #pragma unroll
        for (int ks = 0; ks < 2; ks++) {
            uint4 af[4]; uint2 bf[4];
            #pragma unroll
            for (int i = 0; i < 4; i++) LDSM_X4(af[i], s + aoff[ks][i]);
            #pragma unroll
            for (int j = 0; j < 4; j++) LDSM_X2(bf[j], s + boff[ks][j]);
            #pragma unroll
            for (int i = 0; i < 4; i++)
                #pragma unroll
                for (int j = 0; j < 4; j++)
                    mma_bf16(acc[i][j], af[i], bf[j]);
        }
    }

    // epilogue
    #pragma unroll
    for (int i = 0; i < 4; i++) {
        int r0 = m0 + wm * 64 + i * 16 + (lane >> 2);
        #pragma unroll
        for (int j = 0; j < 4; j++) {
            int c = n0 + wn * 32 + j * 8 + (lane & 3) * 2;
            float b0 = bias[c], b1 = bias[c + 1];
            size_t o0 = (size_t)r0 * N + c;
            size_t o1 = (size_t)(r0 + 8) * N + c;
            float2 v0 = make_float2(acc[i][j][0] + b0, acc[i][j][1] + b1);
            float2 v1 = make_float2(acc[i][j][2] + b0, acc[i][j][3] + b1);
            if (res) {
                float2 e0 = *(const float2*)(res + o0);
                float2 e1 = *(const float2*)(res + o1);
                v0.x += e0.x; v0.y += e0.y;
                v1.x += e1.x; v1.y += e1.y;
            }
            if (Cb) {
                *(uint32_t*)(Cb + o0) = packbf2(v0.x, v0.y);
                *(uint32_t*)(Cb + o1) = packbf2(v1.x, v1.y);
            } else {
                *(float2*)(C + o0) = v0;
                *(float2*)(C + o1) = v1;
            }
        }
    }
}

// ---------------------------------------------------------------------------
// RoPE apply: reads fp32 q/k, rotates in fp32, writes bf16.
// ---------------------------------------------------------------------------
__global__ __launch_bounds__(256)
void rope_bf_kernel(const float* __restrict__ q, const float* __restrict__ k,
                    __nv_bfloat16* __restrict__ qo, __nv_bfloat16* __restrict__ ko,
                    const float2* __restrict__ tab)
{
    int idx = blockIdx.x * 256 + threadIdx.x;
    const float* src = (blockIdx.y == 0) ? q : k;
    __nv_bfloat16* dst = (blockIdx.y == 0) ? qo : ko;

    int j   = idx & 63;
    int hh  = (idx >> 6) & (NH - 1);
    int row = idx >> 10;
    int pos = row & (S_ - 1);

    float2 cs = tab[(pos << 6) + j];
    float c = cs.x, s = cs.y;

    size_t off = (size_t)row * DM + (hh << 7) + j;
    float x0 = src[off], x1 = src[off + 64];
    dst[off]      = __float2bfloat16(x0 * c - x1 * s);
    dst[off + 64] = __float2bfloat16(x1 * c + x0 * s);
}

// ---------------------------------------------------------------------------
// BF16 flash attention, causal. Q/K/V arrive as bf16 in global — load phase
// is a straight uint4 copy into smem (stride 272B), no conversion.
// ---------------------------------------------------------------------------
#define AROWB  272
#define A_Q    0
#define A_K    17408
#define A_V    34816
#define A_SS   52224                 // fp32 64 x 68
#define SSPAD  68
#define A_PS   69632                 // bf16 64 x 72 (144B rows)
#define A_ST   78848                 // stats
#define A_SMEM 79616

__global__ __launch_bounds__(256)
void attn_bf_kernel(const __nv_bfloat16* __restrict__ q,
                    const __nv_bfloat16* __restrict__ k,
                    const __nv_bfloat16* __restrict__ v,
                    __nv_bfloat16* __restrict__ o)
{
    extern __shared__ char sm[];
    uint32_t sb = (uint32_t)__cvta_generic_to_shared(sm);
    float* Ss = (float*)(sm + A_SS);
    __nv_bfloat16* Ps = (__nv_bfloat16*)(sm + A_PS);
    float* m_s = (float*)(sm + A_ST);
    float* l_s = m_s + 64;
    float* c_s = l_s + 64;

    int t = threadIdx.x;
    int lane = t & 31;
    int w = t >> 5;
    int wm = w >> 1;
    int wn = w & 1;
    int lr = lane >> 2;
    int lc = lane & 3;

    int q0 = blockIdx.x << 6;
    size_t base = ((size_t)blockIdx.z * S_) * DM + ((size_t)blockIdx.y << 7);

    // ---- load Q tile: 64 rows x 256B, raw copy ----
    #pragma unroll
    for (int it = 0; it < 4; it++) {
        int idx = t + (it << 8);          // 0..1023
        int r = idx >> 4, c16 = idx & 15;
        uint4 x = *(const uint4*)(q + base + (size_t)(q0 + r) * DM + c16 * 8);
        *(uint4*)(sm + A_Q + r * AROWB + c16 * 16) = x;
    }
    if (t < 64) { m_s[t] = -INFINITY; l_s[t] = 0.f; }

    float oacc[8][4];
    #pragma unroll
    for (int i = 0; i < 8; i++)
        #pragma unroll
        for (int r = 0; r < 4; r++) oacc[i][r] = 0.f;

    __syncthreads();

    for (int j0 = 0; j0 <= q0; j0 += 64) {
        // ---- load K, V tiles: raw copies ----
        #pragma unroll
        for (int it = 0; it < 4; it++) {
            int idx = t + (it << 8);
            int r = idx >> 4, c16 = idx & 15;
            size_t goff = base + (size_t)(j0 + r) * DM + c16 * 8;
            *(uint4*)(sm + A_K + r * AROWB + c16 * 16) = *(const uint4*)(k + goff);
            *(uint4*)(sm + A_V + r * AROWB + c16 * 16) = *(const uint4*)(v + goff);
        }
        __syncthreads();

        // ---- S = Q K^T ----
        float sacc[4][4];
        #pragma unroll
        for (int nf = 0; nf < 4; nf++)
            #pragma unroll
            for (int r = 0; r < 4; r++) sacc[nf][r] = 0.f;

        #pragma unroll
        for (int ks = 0; ks < 8; ks++) {
            uint4 af;
            LDSM_X4(af, sb + A_Q + (wm * 16 + (lane & 15)) * AROWB
                        + ks * 32 + (lane >> 4) * 16);
            #pragma unroll
            for (int nf = 0; nf < 4; nf++) {
                uint2 bf;
                LDSM_X2(bf, sb + A_K + (wn * 32 + nf * 8 + (lane & 7)) * AROWB
                            + ks * 32 + ((lane >> 3) & 1) * 16);
                mma_bf16(sacc[nf], af, bf);
            }
        }

        // ---- scale + causal mask + store S (fp32) ----
        const float sc = 0.08838834764831845f;   // 1/sqrt(128)
        int r_lo = wm * 16 + lr, r_hi = r_lo + 8;
        int qi_lo = q0 + r_lo,  qi_hi = q0 + r_hi;
        #pragma unroll
        for (int nf = 0; nf < 4; nf++) {
            int col = wn * 32 + nf * 8 + lc * 2;
            int kj = j0 + col;
            float v0 = sacc[nf][0] * sc, v1 = sacc[nf][1] * sc;
            float v2 = sacc[nf][2] * sc, v3 = sacc[nf][3] * sc;
            if (kj     > qi_lo) v0 = -INFINITY;
            if (kj + 1 > qi_lo) v1 = -INFINITY;
            if (kj     > qi_hi) v2 = -INFINITY;
            if (kj + 1 > qi_hi) v3 = -INFINITY;
            Ss[r_lo * SSPAD + col]     = v0;
            Ss[r_lo * SSPAD + col + 1] = v1;
            Ss[r_hi * SSPAD + col]     = v2;
            Ss[r_hi * SSPAD + col + 1] = v3;
        }
        __syncthreads();

        // ---- online softmax: warp w owns rows w*8..w*8+7; P -> bf16 ----
        #pragma unroll
        for (int r8 = 0; r8 < 8; r8++) {
            int r = (w << 3) + r8;
            float s0 = Ss[r * SSPAD + lane];
            float s1 = Ss[r * SSPAD + 32 + lane];
            float mx = fmaxf(s0, s1);
            #pragma unroll
            for (int off = 16; off; off >>= 1)
                mx = fmaxf(mx, __shfl_xor_sync(0xffffffffu, mx, off));
            float mold = m_s[r];
            float mn = fmaxf(mold, mx);
            __nv_bfloat16 b0 = __float2bfloat16(expf(s0 - mn));
            __nv_bfloat16 b1 = __float2bfloat16(expf(s1 - mn));
            Ps[r * 72 + lane]      = b0;
            Ps[r * 72 + 32 + lane] = b1;
            float sum = __bfloat162float(b0) + __bfloat162float(b1);
            #pragma unroll
            for (int off = 16; off; off >>= 1)
                sum += __shfl_xor_sync(0xffffffffu, sum, off);
            if (lane == 0) {
                float corr = expf(mold - mn);
                l_s[r] = l_s[r] * corr + sum;
                m_s[r] = mn;
                c_s[r] = corr;
            }
        }
        __syncthreads();

        // ---- rescale O, then O += P V ----
        float corr_lo = c_s[r_lo];
        float corr_hi = c_s[r_hi];
        #pragma unroll
        for (int nf = 0; nf < 8; nf++) {
            oacc[nf][0] *= corr_lo; oacc[nf][1] *= corr_lo;
            oacc[nf][2] *= corr_hi; oacc[nf][3] *= corr_hi;
        }

        #pragma unroll
        for (int kf = 0; kf < 4; kf++) {
            uint4 af;
            LDSM_X4(af, sb + A_PS + (wm * 16 + (lane & 15)) * 144
                        + kf * 32 + (lane >> 4) * 16);
            #pragma unroll
            for (int nf = 0; nf < 8; nf++) {
                uint2 bf;
                LDSM_X2T(bf, sb + A_V
                             + (kf * 16 + ((lane >> 3) & 1) * 8 + (lane & 7)) * AROWB
                             + (wn * 64 + nf * 8) * 2);
                mma_bf16(oacc[nf], af, bf);
            }
        }
        __syncthreads();
    }

    // ---- epilogue: O / l -> bf16 ----
    {
        int r_lo = wm * 16 + lr, r_hi = r_lo + 8;
        float inv_lo = 1.0f / l_s[r_lo];
        float inv_hi = 1.0f / l_s[r_hi];
        #pragma unroll
        for (int nf = 0; nf < 8; nf++) {
            int col = wn * 64 + nf * 8 + lc * 2;
            __nv_bfloat16* d0 = o + base + (size_t)(q0 + r_lo) * DM + col;
            __nv_bfloat16* d1 = o + base + (size_t)(q0 + r_hi) * DM + col;
            *(uint32_t*)d0 = packbf2(oacc[nf][0] * inv_lo, oacc[nf][1] * inv_lo);
            *(uint32_t*)d1 = packbf2(oacc[nf][2] * inv_hi, oacc[nf][3] * inv_hi);
        }
    }
}

// ---------------------------------------------------------------------------
// Launch
// ---------------------------------------------------------------------------
extern "C" void kernel_launch(void* const* d_in, const int* in_sizes, int n_in,
                              void* d_out, int out_size)
{
    const float* h  = (const float*)d_in[0];
    const float* wq = (const float*)d_in[1];
    const float* bq = (const float*)d_in[2];
    const float* wk = (const float*)d_in[3];
    const float* bk = (const float*)d_in[4];
    const float* wv = (const float*)d_in[5];
    const float* bv = (const float*)d_in[6];
    const float* wo = (const float*)d_in[7];
    const float* bo = (const float*)d_in[8];
    const float* lg = (const float*)d_in[9];
    const float* lb = (const float*)d_in[10];
    float* out = (float*)d_out;

    float *xn, *qb, *kb, *vb, *ob;
    __nv_bfloat16* wb;
    float2* rt;
    cudaGetSymbolAddress((void**)&xn, g_xn);
    cudaGetSymbolAddress((void**)&qb, g_q);
    cudaGetSymbolAddress((void**)&kb, g_k);
    cudaGetSymbolAddress((void**)&vb, g_v);
    cudaGetSymbolAddress((void**)&ob, g_o);
    cudaGetSymbolAddress((void**)&wb, g_wb);
    cudaGetSymbolAddress((void**)&rt, g_rope);

    __nv_bfloat16* xn_bf = (__nv_bfloat16*)xn;                     // first 16MB
    __nv_bfloat16* q_bf  = (__nv_bfloat16*)xn;                     // reuse after GEMMs
    __nv_bfloat16* k_bf  = (__nv_bfloat16*)xn + (size_t)MROWS * DM;// second 16MB
    __nv_bfloat16* v_bf  = (__nv_bfloat16*)vb;
    __nv_bfloat16* ob_bf = (__nv_bfloat16*)ob;
    __nv_bfloat16* wq_bf = wb;
    __nv_bfloat16* wk_bf = wb + (size_t)DM * DM;
    __nv_bfloat16* wv_bf = wb + 2 * (size_t)DM * DM;
    __nv_bfloat16* wo_bf = wb + 3 * (size_t)DM * DM;

    // 0. RoPE table + weight conversions
    rope_table_kernel<<<(S_ * 64 + 255) / 256, 256>>>(rt);
    int n4 = DM * DM / 4;
    wconv_kernel<<<(n4 + 255) / 256, 256>>>(wq, wq_bf, n4);
    wconv_kernel<<<(n4 + 255) / 256, 256>>>(wk, wk_bf, n4);
    wconv_kernel<<<(n4 + 255) / 256, 256>>>(wv, wv_bf, n4);
    wconv_kernel<<<(n4 + 255) / 256, 256>>>(wo, wo_bf, n4);

    // 1. LayerNorm (bf16 out)
    ln_kernel<<<MROWS, 256>>>(h, lg, lb, xn_bf);

    // 2. QKV projections. q,k -> fp32 (rope next); v -> bf16 directly.
    int smem_g = BSTAGES * BSTAGE_BYTES;     // 81920
    cudaFuncSetAttribute(bgemm_nt, cudaFuncAttributeMaxDynamicSharedMemorySize,
                         smem_g);
    dim3 gg(DM / 128, MROWS / 128);
    bgemm_nt<<<gg, 256, smem_g>>>(xn_bf, wq_bf, bq, nullptr, qb, nullptr, DM, DM);
    bgemm_nt<<<gg, 256, smem_g>>>(xn_bf, wk_bf, bk, nullptr, kb, nullptr, DM, DM);
    bgemm_nt<<<gg, 256, smem_g>>>(xn_bf, wv_bf, bv, nullptr, nullptr, v_bf, DM, DM);

    // 3. RoPE on q, k: fp32 in, bf16 out (xn buffer reused — GEMMs done)
    rope_bf_kernel<<<dim3((MROWS * NH * 64) / 256, 2), 256>>>(qb, kb, q_bf, k_bf, rt);

    // 4. Causal flash attention (all-bf16 inputs)
    cudaFuncSetAttribute(attn_bf_kernel, cudaFuncAttributeMaxDynamicSharedMemorySize,
                         A_SMEM);
    attn_bf_kernel<<<dim3(S_ / 64, NH, B_), 256, A_SMEM>>>(q_bf, k_bf, v_bf, ob_bf);

    // 5. Output projection + bias + residual (fp32 out)
    bgemm_nt<<<gg, 256, smem_g>>>(ob_bf, wo_bf, bo, h, out, nullptr, DM, DM);
}

// round 14
// speedup vs baseline: 6.6266x; 1.1931x over previous
#include <cuda_runtime.h>
#include <cuda_bf16.h>
#include <math.h>
#include <stdint.h>

// Problem constants (fixed shapes)
#define B_    2
#define S_    2048
#define DM    2048
#define NH    16
#define DK_   128
#define MROWS (B_ * S_)      // 4096
#define EPS_  1e-5f

// ---------------------------------------------------------------------------
// Scratch (no cudaMalloc allowed)
// ---------------------------------------------------------------------------
__device__ float g_xn[(size_t)MROWS * DM];   // phase1: bf16 xn; phase2: bf16 q,k
__device__ float g_q [(size_t)MROWS * DM];   // fp32 q (pre-rope)
__device__ float g_k [(size_t)MROWS * DM];   // fp32 k (pre-rope)
__device__ float g_v [(size_t)MROWS * DM];   // bf16 v (from GEMM)
__device__ float g_o [(size_t)MROWS * DM];   // bf16 attention out
__device__ __nv_bfloat16 g_wb[4][(size_t)DM * DM];  // bf16 weights
__device__ float2 g_rope[(size_t)S_ * 64];   // (cos, sin) per (pos, j)

// ---------------------------------------------------------------------------
// helpers
// ---------------------------------------------------------------------------
__device__ __forceinline__ uint32_t packbf2(float a, float b)
{
    __nv_bfloat162 h = __floats2bfloat162_rn(a, b);
    return *(uint32_t*)&h;
}

__device__ __forceinline__ void mma_bf16(float* c, const uint4& a, const uint2& b)
{
    asm volatile(
        "mma.sync.aligned.m16n8k16.row.col.f32.bf16.bf16.f32 "
        "{%0,%1,%2,%3}, {%4,%5,%6,%7}, {%8,%9}, {%0,%1,%2,%3};\n"
        : "+f"(c[0]), "+f"(c[1]), "+f"(c[2]), "+f"(c[3])
        : "r"(a.x), "r"(a.y), "r"(a.z), "r"(a.w), "r"(b.x), "r"(b.y));
}

#define CP_ASYNC16(dst, src) \
    asm volatile("cp.async.cg.shared.global [%0], [%1], 16;" \
                 :: "r"((uint32_t)(dst)), "l"(src))
#define CP_COMMIT() asm volatile("cp.async.commit_group;" ::: "memory")
#define CP_WAIT(N)  asm volatile("cp.async.wait_group %0;" :: "n"(N) : "memory")

#define LDSM_X4(d, addr) \
    asm volatile("ldmatrix.sync.aligned.m8n8.x4.shared.b16 {%0,%1,%2,%3}, [%4];" \
                 : "=r"((d).x), "=r"((d).y), "=r"((d).z), "=r"((d).w) \
                 : "r"((uint32_t)(addr)))
#define LDSM_X2(d, addr) \
    asm volatile("ldmatrix.sync.aligned.m8n8.x2.shared.b16 {%0,%1}, [%2];" \
                 : "=r"((d).x), "=r"((d).y) \
                 : "r"((uint32_t)(addr)))
#define LDSM_X2T(d, addr) \
    asm volatile("ldmatrix.sync.aligned.m8n8.x2.trans.shared.b16 {%0,%1}, [%2];" \
                 : "=r"((d).x), "=r"((d).y) \
                 : "r"((uint32_t)(addr)))

// ---------------------------------------------------------------------------
// Fused weight conversion fp32 -> bf16 (rn): all 4 matrices in one launch.
// ---------------------------------------------------------------------------
__global__ __launch_bounds__(256)
void wconv4_kernel(const float* __restrict__ s0, const float* __restrict__ s1,
                   const float* __restrict__ s2, const float* __restrict__ s3,
                   __nv_bfloat16* __restrict__ d0, __nv_bfloat16* __restrict__ d1,
                   __nv_bfloat16* __restrict__ d2, __nv_bfloat16* __restrict__ d3,
                   int n4)
{
    int i = blockIdx.x * 256 + threadIdx.x;
    if (i >= n4) return;
    const float* src;
    __nv_bfloat16* dst;
    switch (blockIdx.y) {
        case 0:  src = s0; dst = d0; break;
        case 1:  src = s1; dst = d1; break;
        case 2:  src = s2; dst = d2; break;
        default: src = s3; dst = d3; break;
    }
    float4 x = ((const float4*)src)[i];
    uint2 u;
    u.x = packbf2(x.x, x.y);
    u.y = packbf2(x.z, x.w);
    ((uint2*)dst)[i] = u;
}

// ---------------------------------------------------------------------------
// RoPE table: accurate double-precision sincos of the fp32-quantized phase.
// ---------------------------------------------------------------------------
__global__ __launch_bounds__(256)
void rope_table_kernel(float2* __restrict__ tab)
{
    int idx = blockIdx.x * 256 + threadIdx.x;     // [0, S_*64)
    if (idx >= S_ * 64) return;
    int j   = idx & 63;
    int pos = idx >> 6;
    double theta_d = 1.0 / pow(10000.0, (double)j / 64.0);
    float  theta_f = (float)theta_d;
    float fr = (float)pos * theta_f;
    double dfr = (double)fr;
    tab[idx] = make_float2((float)cos(dfr), (float)sin(dfr));
}

// ---------------------------------------------------------------------------
// LayerNorm (outputs bf16)
// ---------------------------------------------------------------------------
__global__ __launch_bounds__(256)
void ln_kernel(const float* __restrict__ x, const float* __restrict__ g,
               const float* __restrict__ bb, __nv_bfloat16* __restrict__ out)
{
    int row = blockIdx.x;
    int t = threadIdx.x;
    const float4* xr = (const float4*)(x + (size_t)row * DM);
    uint2* orow = (uint2*)(out + (size_t)row * DM);

    float4 v0 = xr[t];
    float4 v1 = xr[t + 256];
    float sum = v0.x + v0.y + v0.z + v0.w + v1.x + v1.y + v1.z + v1.w;
    float sq  = v0.x*v0.x + v0.y*v0.y + v0.z*v0.z + v0.w*v0.w
              + v1.x*v1.x + v1.y*v1.y + v1.z*v1.z + v1.w*v1.w;

    #pragma unroll
    for (int off = 16; off; off >>= 1) {
        sum += __shfl_xor_sync(0xffffffffu, sum, off);
        sq  += __shfl_xor_sync(0xffffffffu, sq,  off);
    }
    __shared__ float s_sum[8], s_sq[8];
    int w = t >> 5;
    if ((t & 31) == 0) { s_sum[w] = sum; s_sq[w] = sq; }
    __syncthreads();
    if (t < 32) {
        float a = (t < 8) ? s_sum[t] : 0.f;
        float b = (t < 8) ? s_sq[t]  : 0.f;
        #pragma unroll
        for (int off = 4; off; off >>= 1) {
            a += __shfl_xor_sync(0xffffffffu, a, off);
            b += __shfl_xor_sync(0xffffffffu, b, off);
        }
        if (t == 0) { s_sum[0] = a; s_sq[0] = b; }
    }
    __syncthreads();

    float mu  = s_sum[0] * (1.0f / DM);
    float var = s_sq[0] * (1.0f / DM) - mu * mu;
    float rstd = rsqrtf(var + EPS_);

    const float4* g4 = (const float4*)g;
    const float4* b4 = (const float4*)bb;
    {
        float4 gv = g4[t], bv = b4[t];
        uint2 u;
        u.x = packbf2((v0.x - mu) * rstd * gv.x + bv.x,
                      (v0.y - mu) * rstd * gv.y + bv.y);
        u.y = packbf2((v0.z - mu) * rstd * gv.z + bv.z,
                      (v0.w - mu) * rstd * gv.w + bv.w);
        orow[t] = u;
    }
    {
        float4 gv = g4[t + 256], bv = b4[t + 256];
        uint2 u;
        u.x = packbf2((v1.x - mu) * rstd * gv.x + bv.x,
                      (v1.y - mu) * rstd * gv.y + bv.y);
        u.y = packbf2((v1.z - mu) * rstd * gv.z + bv.z,
                      (v1.w - mu) * rstd * gv.w + bv.w);
        orow[t + 256] = u;
    }
}

// ---------------------------------------------------------------------------
// Pipelined BF16 GEMM NT. Optional bf16 output (Cb != null) or fp32 (C).
// ---------------------------------------------------------------------------
#define BSTAGES 4
#define BROWB   80
#define BSTAGE_BYTES 20480      // 2 * 128 * 80

__global__ __launch_bounds__(256, 2)
void bgemm_nt(const __nv_bfloat16* __restrict__ A,
              const __nv_bfloat16* __restrict__ W,
              const float* __restrict__ bias, const float* __restrict__ res,
              float* __restrict__ C, __nv_bfloat16* __restrict__ Cb,
              int K, int N)
{
    extern __shared__ char smem[];
    uint32_t sb = (uint32_t)__cvta_generic_to_shared(smem);

    int t = threadIdx.x;
    int lane = t & 31;
    int w = t >> 5;
    int wm = w >> 2, wn = w & 3;
    int m0 = blockIdx.y << 7, n0 = blockIdx.x << 7;

    int lm = t >> 2;
    int kq = t & 3;
    const __nv_bfloat16* gA0 = A + (size_t)(m0 + lm) * K + kq * 8;
    const __nv_bfloat16* gA1 = gA0 + (size_t)64 * K;
    const __nv_bfloat16* gW0 = W + (size_t)(n0 + lm) * K + kq * 8;
    const __nv_bfloat16* gW1 = gW0 + (size_t)64 * K;
    uint32_t dA0 = (uint32_t)lm * BROWB + kq * 16;
    uint32_t dA1 = dA0 + 64 * BROWB;
    uint32_t dB0 = 10240 + dA0;
    uint32_t dB1 = 10240 + dA1;

    int aoff[2][4], boff[2][4];
    #pragma unroll
    for (int ks = 0; ks < 2; ks++) {
        #pragma unroll
        for (int i = 0; i < 4; i++) {
            int mrow = (wm * 4 + i) * 16 + (lane & 7) + ((lane >> 3) & 1) * 8;
            aoff[ks][i] = mrow * BROWB + ks * 32 + (lane >> 4) * 16;
            int nrow = (wn * 4 + i) * 8 + (lane & 7);
            boff[ks][i] = 10240 + nrow * BROWB + ks * 32 + ((lane >> 3) & 1) * 16;
        }
    }

    float acc[4][4][4];
    #pragma unroll
    for (int i = 0; i < 4; i++)
        #pragma unroll
        for (int j = 0; j < 4; j++)
            #pragma unroll
            for (int r = 0; r < 4; r++) acc[i][j][r] = 0.f;

    const int nIter = K >> 5;

    auto load_stage = [&](int c) {
        uint32_t s = sb + (uint32_t)(c & 3) * BSTAGE_BYTES;
        int ko = c << 5;
        CP_ASYNC16(s + dA0, gA0 + ko);
        CP_ASYNC16(s + dA1, gA1 + ko);
        CP_ASYNC16(s + dB0, gW0 + ko);
        CP_ASYNC16(s + dB1, gW1 + ko);
        CP_COMMIT();
    };

    load_stage(0); load_stage(1); load_stage(2);

    for (int c = 0; c < nIter; c++) {
        if (c <= nIter - 3)      CP_WAIT(2);
        else if (c == nIter - 2) CP_WAIT(1);
        else                     CP_WAIT(0);
        __syncthreads();

        if (c + 3 < nIter) load_stage(c + 3);

        uint32_t s = sb + (uint32_t)(c & 3) * BSTAGE_BYTES;
        #pragma unroll
        for (int ks = 0; ks < 2; ks++) {
            uint4 af[4]; uint2 bf[4];
            #pragma unroll
            for (int i = 0; i < 4; i++) LDSM_X4(af[i], s + aoff[ks][i]);
            #pragma unroll
            for (int j = 0; j < 4; j++) LDSM_X2(bf[j], s + boff[ks][j]);
            #pragma unroll
            for (int i = 0; i < 4; i++)
                #pragma unroll
                for (int j = 0; j < 4; j++)
                    mma_bf16(acc[i][j], af[i], bf[j]);
        }
    }

    // epilogue
    #pragma unroll
    for (int i = 0; i < 4; i++) {
        int r0 = m0 + wm * 64 + i * 16 + (lane >> 2);
        #pragma unroll
        for (int j = 0; j < 4; j++) {
            int c = n0 + wn * 32 + j * 8 + (lane & 3) * 2;
            float b0 = bias[c], b1 = bias[c + 1];
            size_t o0 = (size_t)r0 * N + c;
            size_t o1 = (size_t)(r0 + 8) * N + c;
            float2 v0 = make_float2(acc[i][j][0] + b0, acc[i][j][1] + b1);
            float2 v1 = make_float2(acc[i][j][2] + b0, acc[i][j][3] + b1);
            if (res) {
                float2 e0 = *(const float2*)(res + o0);
                float2 e1 = *(const float2*)(res + o1);
                v0.x += e0.x; v0.y += e0.y;
                v1.x += e1.x; v1.y += e1.y;
            }
            if (Cb) {
                *(uint32_t*)(Cb + o0) = packbf2(v0.x, v0.y);
                *(uint32_t*)(Cb + o1) = packbf2(v1.x, v1.y);
            } else {
                *(float2*)(C + o0) = v0;
                *(float2*)(C + o1) = v1;
            }
        }
    }
}

// ---------------------------------------------------------------------------
// RoPE apply: reads fp32 q/k, rotates in fp32, writes bf16.
// ---------------------------------------------------------------------------
__global__ __launch_bounds__(256)
void rope_bf_kernel(const float* __restrict__ q, const float* __restrict__ k,
                    __nv_bfloat16* __restrict__ qo, __nv_bfloat16* __restrict__ ko,
                    const float2* __restrict__ tab)
{
    int idx = blockIdx.x * 256 + threadIdx.x;
    const float* src = (blockIdx.y == 0) ? q : k;
    __nv_bfloat16* dst = (blockIdx.y == 0) ? qo : ko;

    int j   = idx & 63;
    int hh  = (idx >> 6) & (NH - 1);
    int row = idx >> 10;
    int pos = row & (S_ - 1);

    float2 cs = tab[(pos << 6) + j];
    float c = cs.x, s = cs.y;

    size_t off = (size_t)row * DM + (hh << 7) + j;
    float x0 = src[off], x1 = src[off + 64];
    dst[off]      = __float2bfloat16(x0 * c - x1 * s);
    dst[off + 64] = __float2bfloat16(x1 * c + x0 * s);
}

// ---------------------------------------------------------------------------
// BF16 flash attention, causal. BQ=128, BK=64, register-resident softmax.
// Warp w owns rows 16w..16w+15 end-to-end (S, softmax, P, PV, epilogue):
// row stats m/l live in registers across tiles; P written/read by the same
// warp (only __syncwarp between); 2 block barriers per tile.
// Causal tile-skip predicate is WARP-UNIFORM (max row of the warp) —
// a lane-dependent predicate here diverges around ldmatrix/mma and hangs.
// smem: Q 128x272B, K 64x272B, V 64x272B, P bf16 128x144B.
// ---------------------------------------------------------------------------
#define ZROWB  272
#define Z_Q    0
#define Z_K    34816
#define Z_V    52224
#define Z_P    69632                 // 128 rows * 144B
#define Z_SMEM 88064

__global__ __launch_bounds__(256)
void attn_bq128_kernel(const __nv_bfloat16* __restrict__ q,
                       const __nv_bfloat16* __restrict__ k,
                       const __nv_bfloat16* __restrict__ v,
                       __nv_bfloat16* __restrict__ o)
{
    extern __shared__ char sm[];
    uint32_t sb = (uint32_t)__cvta_generic_to_shared(sm);

    int t = threadIdx.x;
    int lane = t & 31;
    int w = t >> 5;
    int lr = lane >> 2;
    int lc = lane & 3;

    int q0 = blockIdx.x << 7;
    size_t base = ((size_t)blockIdx.z * S_) * DM + ((size_t)blockIdx.y << 7);

    // ---- load Q tile: 128 rows x 256B raw copy ----
    #pragma unroll
    for (int it = 0; it < 8; it++) {
        int idx = t + (it << 8);          // 0..2047
        int r = idx >> 4, c16 = idx & 15;
        uint4 x = *(const uint4*)(q + base + (size_t)(q0 + r) * DM + c16 * 8);
        *(uint4*)(sm + Z_Q + r * ZROWB + c16 * 16) = x;
    }

    int r_lo = (w << 4) + lr;            // block-local rows this thread owns
    int r_hi = r_lo + 8;
    int qi_lo = q0 + r_lo;
    int qi_hi = q0 + r_hi;

    float m_lo = -INFINITY, m_hi = -INFINITY;
    float l_lo = 0.f, l_hi = 0.f;
    float oacc[16][4];
    #pragma unroll
    for (int i = 0; i < 16; i++)
        #pragma unroll
        for (int r = 0; r < 4; r++) oacc[i][r] = 0.f;

    __syncthreads();

    for (int j0 = 0; j0 <= q0 + 64; j0 += 64) {
        // ---- load K, V tiles: raw copies ----
        #pragma unroll
        for (int it = 0; it < 4; it++) {
            int idx = t + (it << 8);
            int r = idx >> 4, c16 = idx & 15;
            size_t goff = base + (size_t)(j0 + r) * DM + c16 * 8;
            *(uint4*)(sm + Z_K + r * ZROWB + c16 * 16) = *(const uint4*)(k + goff);
            *(uint4*)(sm + Z_V + r * ZROWB + c16 * 16) = *(const uint4*)(v + goff);
        }
        __syncthreads();

        // WARP-UNIFORM causal skip: warp's last row is q0 + 16w + 15
        bool active = (q0 + (w << 4) + 15 >= j0);
        if (active) {
            // ---- S = Q K^T : rows 16w..16w+15, all 64 cols ----
            float sacc[8][4];
            #pragma unroll
            for (int nf = 0; nf < 8; nf++)
                #pragma unroll
                for (int r = 0; r < 4; r++) sacc[nf][r] = 0.f;

            #pragma unroll
            for (int ks = 0; ks < 8; ks++) {
                uint4 af;
                LDSM_X4(af, sb + Z_Q + ((w << 4) + (lane & 15)) * ZROWB
                            + ks * 32 + (lane >> 4) * 16);
                #pragma unroll
                for (int nf = 0; nf < 8; nf++) {
                    uint2 bf;
                    LDSM_X2(bf, sb + Z_K + (nf * 8 + (lane & 7)) * ZROWB
                                + ks * 32 + ((lane >> 3) & 1) * 16);
                    mma_bf16(sacc[nf], af, bf);
                }
            }

            // ---- scale + mask + register softmax ----
            const float sc = 0.08838834764831845f;   // 1/sqrt(128)
            float mx_lo = -INFINITY, mx_hi = -INFINITY;
            #pragma unroll
            for (int nf = 0; nf < 8; nf++) {
                int kj = j0 + nf * 8 + lc * 2;
                float v0 = sacc[nf][0] * sc; if (kj     > qi_lo) v0 = -INFINITY;
                float v1 = sacc[nf][1] * sc; if (kj + 1 > qi_lo) v1 = -INFINITY;
                float v2 = sacc[nf][2] * sc; if (kj     > qi_hi) v2 = -INFINITY;
                float v3 = sacc[nf][3] * sc; if (kj + 1 > qi_hi) v3 = -INFINITY;
                sacc[nf][0] = v0; sacc[nf][1] = v1;
                sacc[nf][2] = v2; sacc[nf][3] = v3;
                mx_lo = fmaxf(mx_lo, fmaxf(v0, v1));
                mx_hi = fmaxf(mx_hi, fmaxf(v2, v3));
            }
            mx_lo = fmaxf(mx_lo, __shfl_xor_sync(0xffffffffu, mx_lo, 1));
            mx_lo = fmaxf(mx_lo, __shfl_xor_sync(0xffffffffu, mx_lo, 2));
            mx_hi = fmaxf(mx_hi, __shfl_xor_sync(0xffffffffu, mx_hi, 1));
            mx_hi = fmaxf(mx_hi, __shfl_xor_sync(0xffffffffu, mx_hi, 2));

            float mn_lo = fmaxf(m_lo, mx_lo);
            float mn_hi = fmaxf(m_hi, mx_hi);
            float corr_lo = expf(m_lo - mn_lo);
            float corr_hi = expf(m_hi - mn_hi);

            float sum_lo = 0.f, sum_hi = 0.f;
            #pragma unroll
            for (int nf = 0; nf < 8; nf++) {
                __nv_bfloat16 e0 = __float2bfloat16(expf(sacc[nf][0] - mn_lo));
                __nv_bfloat16 e1 = __float2bfloat16(expf(sacc[nf][1] - mn_lo));
                __nv_bfloat16 e2 = __float2bfloat16(expf(sacc[nf][2] - mn_hi));
                __nv_bfloat16 e3 = __float2bfloat16(expf(sacc[nf][3] - mn_hi));
                int colb = (nf * 8 + lc * 2) * 2;
                __nv_bfloat162 p01; p01.x = e0; p01.y = e1;
                __nv_bfloat162 p23; p23.x = e2; p23.y = e3;
                *(uint32_t*)(sm + Z_P + r_lo * 144 + colb) = *(uint32_t*)&p01;
                *(uint32_t*)(sm + Z_P + r_hi * 144 + colb) = *(uint32_t*)&p23;
                sum_lo += __bfloat162float(e0) + __bfloat162float(e1);
                sum_hi += __bfloat162float(e2) + __bfloat162float(e3);
            }
            sum_lo += __shfl_xor_sync(0xffffffffu, sum_lo, 1);
            sum_lo += __shfl_xor_sync(0xffffffffu, sum_lo, 2);
            sum_hi += __shfl_xor_sync(0xffffffffu, sum_hi, 1);
            sum_hi += __shfl_xor_sync(0xffffffffu, sum_hi, 2);

            l_lo = l_lo * corr_lo + sum_lo;
            l_hi = l_hi * corr_hi + sum_hi;
            m_lo = mn_lo;
            m_hi = mn_hi;

            #pragma unroll
            for (int nf = 0; nf < 16; nf++) {
                oacc[nf][0] *= corr_lo; oacc[nf][1] *= corr_lo;
                oacc[nf][2] *= corr_hi; oacc[nf][3] *= corr_hi;
            }

            __syncwarp();

            // ---- O += P V : rows 16w..16w+15, cols 0..127 ----
            #pragma unroll
            for (int kf = 0; kf < 4; kf++) {
                uint4 af;
                LDSM_X4(af, sb + Z_P + ((w << 4) + (lane & 15)) * 144
                            + kf * 32 + (lane >> 4) * 16);
                #pragma unroll
                for (int nf = 0; nf < 16; nf++) {
                    uint2 bf;
                    LDSM_X2T(bf, sb + Z_V
                                 + (kf * 16 + ((lane >> 3) & 1) * 8 + (lane & 7)) * ZROWB
                                 + nf * 16);
                    mma_bf16(oacc[nf], af, bf);
                }
            }
        }
        __syncthreads();   // protect K/V before next tile's load
    }

    // ---- epilogue: O / l -> bf16 ----
    {
        float inv_lo = 1.0f / l_lo;
        float inv_hi = 1.0f / l_hi;
        #pragma unroll
        for (int nf = 0; nf < 16; nf++) {
            int col = nf * 8 + lc * 2;
            __nv_bfloat16* d0 = o + base + (size_t)(q0 + r_lo) * DM + col;
            __nv_bfloat16* d1 = o + base + (size_t)(q0 + r_hi) * DM + col;
            *(uint32_t*)d0 = packbf2(oacc[nf][0] * inv_lo, oacc[nf][1] * inv_lo);
            *(uint32_t*)d1 = packbf2(oacc[nf][2] * inv_hi, oacc[nf][3] * inv_hi);
        }
    }
}

// ---------------------------------------------------------------------------
// Launch
// ---------------------------------------------------------------------------
extern "C" void kernel_launch(void* const* d_in, const int* in_sizes, int n_in,
                              void* d_out, int out_size)
{
    const float* h  = (const float*)d_in[0];
    const float* wq = (const float*)d_in[1];
    const float* bq = (const float*)d_in[2];
    const float* wk = (const float*)d_in[3];
    const float* bk = (const float*)d_in[4];
    const float* wv = (const float*)d_in[5];
    const float* bv = (const float*)d_in[6];
    const float* wo = (const float*)d_in[7];
    const float* bo = (const float*)d_in[8];
    const float* lg = (const float*)d_in[9];
    const float* lb = (const float*)d_in[10];
    float* out = (float*)d_out;

    float *xn, *qb, *kb, *vb, *ob;
    __nv_bfloat16* wb;
    float2* rt;
    cudaGetSymbolAddress((void**)&xn, g_xn);
    cudaGetSymbolAddress((void**)&qb, g_q);
    cudaGetSymbolAddress((void**)&kb, g_k);
    cudaGetSymbolAddress((void**)&vb, g_v);
    cudaGetSymbolAddress((void**)&ob, g_o);
    cudaGetSymbolAddress((void**)&wb, g_wb);
    cudaGetSymbolAddress((void**)&rt, g_rope);

    __nv_bfloat16* xn_bf = (__nv_bfloat16*)xn;                     // first 16MB
    __nv_bfloat16* q_bf  = (__nv_bfloat16*)xn;                     // reuse after GEMMs
    __nv_bfloat16* k_bf  = (__nv_bfloat16*)xn + (size_t)MROWS * DM;// second 16MB
    __nv_bfloat16* v_bf  = (__nv_bfloat16*)vb;
    __nv_bfloat16* ob_bf = (__nv_bfloat16*)ob;
    __nv_bfloat16* wq_bf = wb;
    __nv_bfloat16* wk_bf = wb + (size_t)DM * DM;
    __nv_bfloat16* wv_bf = wb + 2 * (size_t)DM * DM;
    __nv_bfloat16* wo_bf = wb + 3 * (size_t)DM * DM;

    // 0. RoPE table + fused weight conversion
    rope_table_kernel<<<(S_ * 64 + 255) / 256, 256>>>(rt);
    int n4 = DM * DM / 4;
    wconv4_kernel<<<dim3((n4 + 255) / 256, 4), 256>>>(
        wq, wk, wv, wo, wq_bf, wk_bf, wv_bf, wo_bf, n4);

    // 1. LayerNorm (bf16 out)
    ln_kernel<<<MROWS, 256>>>(h, lg, lb, xn_bf);

    // 2. QKV projections. q,k -> fp32 (rope next); v -> bf16 directly.
    int smem_g = BSTAGES * BSTAGE_BYTES;     // 81920
    cudaFuncSetAttribute(bgemm_nt, cudaFuncAttributeMaxDynamicSharedMemorySize,
                         smem_g);
    dim3 gg(DM / 128, MROWS / 128);
    bgemm_nt<<<gg, 256, smem_g>>>(xn_bf, wq_bf, bq, nullptr, qb, nullptr, DM, DM);
    bgemm_nt<<<gg, 256, smem_g>>>(xn_bf, wk_bf, bk, nullptr, kb, nullptr, DM, DM);
    bgemm_nt<<<gg, 256, smem_g>>>(xn_bf, wv_bf, bv, nullptr, nullptr, v_bf, DM, DM);

    // 3. RoPE on q, k: fp32 in, bf16 out (xn buffer reused — GEMMs done)
    rope_bf_kernel<<<dim3((MROWS * NH * 64) / 256, 2), 256>>>(qb, kb, q_bf, k_bf, rt);

    // 4. Causal flash attention (BQ=128, register softmax)
    cudaFuncSetAttribute(attn_bq128_kernel,
                         cudaFuncAttributeMaxDynamicSharedMemorySize, Z_SMEM);
    attn_bq128_kernel<<<dim3(S_ / 128, NH, B_), 256, Z_SMEM>>>(q_bf, k_bf, v_bf, ob_bf);

    // 5. Output projection + bias + residual (fp32 out)
    bgemm_nt<<<gg, 256, smem_g>>>(ob_bf, wo_bf, bo, h, out, nullptr, DM, DM);
}

// round 15
// speedup vs baseline: 6.8422x; 1.0325x over previous
#include <cuda_runtime.h>
#include <cuda_bf16.h>
#include <math.h>
#include <stdint.h>

// Problem constants (fixed shapes)
#define B_    2
#define S_    2048
#define DM    2048
#define NH    16
#define DK_   128
#define MROWS (B_ * S_)      // 4096
#define EPS_  1e-5f

// ---------------------------------------------------------------------------
// Scratch (no cudaMalloc allowed)
// ---------------------------------------------------------------------------
__device__ float g_xn[(size_t)MROWS * DM];   // phase1: bf16 xn; phase2: bf16 q,k (roped)
__device__ float g_q [(size_t)MROWS * DM];   // bf16 q (pre-rope, from GEMM)
__device__ float g_k [(size_t)MROWS * DM];   // bf16 k (pre-rope, from GEMM)
__device__ float g_v [(size_t)MROWS * DM];   // bf16 v (from GEMM)
__device__ float g_o [(size_t)MROWS * DM];   // bf16 attention out
__device__ __nv_bfloat16 g_wb[4][(size_t)DM * DM];  // bf16 weights
__device__ float2 g_rope[(size_t)S_ * 64];   // (cos, sin) per (pos, j)

// ---------------------------------------------------------------------------
// helpers
// ---------------------------------------------------------------------------
__device__ __forceinline__ uint32_t packbf2(float a, float b)
{
    __nv_bfloat162 h = __floats2bfloat162_rn(a, b);
    return *(uint32_t*)&h;
}

__device__ __forceinline__ void mma_bf16(float* c, const uint4& a, const uint2& b)
{
    asm volatile(
        "mma.sync.aligned.m16n8k16.row.col.f32.bf16.bf16.f32 "
        "{%0,%1,%2,%3}, {%4,%5,%6,%7}, {%8,%9}, {%0,%1,%2,%3};\n"
        : "+f"(c[0]), "+f"(c[1]), "+f"(c[2]), "+f"(c[3])
        : "r"(a.x), "r"(a.y), "r"(a.z), "r"(a.w), "r"(b.x), "r"(b.y));
}

#define CP_ASYNC16(dst, src) \
    asm volatile("cp.async.cg.shared.global [%0], [%1], 16;" \
                 :: "r"((uint32_t)(dst)), "l"(src))
#define CP_COMMIT() asm volatile("cp.async.commit_group;" ::: "memory")
#define CP_WAIT(N)  asm volatile("cp.async.wait_group %0;" :: "n"(N) : "memory")

#define LDSM_X4(d, addr) \
    asm volatile("ldmatrix.sync.aligned.m8n8.x4.shared.b16 {%0,%1,%2,%3}, [%4];" \
                 : "=r"((d).x), "=r"((d).y), "=r"((d).z), "=r"((d).w) \
                 : "r"((uint32_t)(addr)))
#define LDSM_X2(d, addr) \
    asm volatile("ldmatrix.sync.aligned.m8n8.x2.shared.b16 {%0,%1}, [%2];" \
                 : "=r"((d).x), "=r"((d).y) \
                 : "r"((uint32_t)(addr)))
#define LDSM_X2T(d, addr) \
    asm volatile("ldmatrix.sync.aligned.m8n8.x2.trans.shared.b16 {%0,%1}, [%2];" \
                 : "=r"((d).x), "=r"((d).y) \
                 : "r"((uint32_t)(addr)))

// ---------------------------------------------------------------------------
// Fused weight conversion fp32 -> bf16 (rn): all 4 matrices in one launch.
// ---------------------------------------------------------------------------
__global__ __launch_bounds__(256)
void wconv4_kernel(const float* __restrict__ s0, const float* __restrict__ s1,
                   const float* __restrict__ s2, const float* __restrict__ s3,
                   __nv_bfloat16* __restrict__ d0, __nv_bfloat16* __restrict__ d1,
                   __nv_bfloat16* __restrict__ d2, __nv_bfloat16* __restrict__ d3,
                   int n4)
{
    int i = blockIdx.x * 256 + threadIdx.x;
    if (i >= n4) return;
    const float* src;
    __nv_bfloat16* dst;
    switch (blockIdx.y) {
        case 0:  src = s0; dst = d0; break;
        case 1:  src = s1; dst = d1; break;
        case 2:  src = s2; dst = d2; break;
        default: src = s3; dst = d3; break;
    }
    float4 x = ((const float4*)src)[i];
    uint2 u;
    u.x = packbf2(x.x, x.y);
    u.y = packbf2(x.z, x.w);
    ((uint2*)dst)[i] = u;
}

// ---------------------------------------------------------------------------
// RoPE table: accurate double-precision sincos of the fp32-quantized phase.
// ---------------------------------------------------------------------------
__global__ __launch_bounds__(256)
void rope_table_kernel(float2* __restrict__ tab)
{
    int idx = blockIdx.x * 256 + threadIdx.x;     // [0, S_*64)
    if (idx >= S_ * 64) return;
    int j   = idx & 63;
    int pos = idx >> 6;
    double theta_d = 1.0 / pow(10000.0, (double)j / 64.0);
    float  theta_f = (float)theta_d;
    float fr = (float)pos * theta_f;
    double dfr = (double)fr;
    tab[idx] = make_float2((float)cos(dfr), (float)sin(dfr));
}

// ---------------------------------------------------------------------------
// LayerNorm (outputs bf16)
// ---------------------------------------------------------------------------
__global__ __launch_bounds__(256)
void ln_kernel(const float* __restrict__ x, const float* __restrict__ g,
               const float* __restrict__ bb, __nv_bfloat16* __restrict__ out)
{
    int row = blockIdx.x;
    int t = threadIdx.x;
    const float4* xr = (const float4*)(x + (size_t)row * DM);
    uint2* orow = (uint2*)(out + (size_t)row * DM);

    float4 v0 = xr[t];
    float4 v1 = xr[t + 256];
    float sum = v0.x + v0.y + v0.z + v0.w + v1.x + v1.y + v1.z + v1.w;
    float sq  = v0.x*v0.x + v0.y*v0.y + v0.z*v0.z + v0.w*v0.w
              + v1.x*v1.x + v1.y*v1.y + v1.z*v1.z + v1.w*v1.w;

    #pragma unroll
    for (int off = 16; off; off >>= 1) {
        sum += __shfl_xor_sync(0xffffffffu, sum, off);
        sq  += __shfl_xor_sync(0xffffffffu, sq,  off);
    }
    __shared__ float s_sum[8], s_sq[8];
    int w = t >> 5;
    if ((t & 31) == 0) { s_sum[w] = sum; s_sq[w] = sq; }
    __syncthreads();
    if (t < 32) {
        float a = (t < 8) ? s_sum[t] : 0.f;
        float b = (t < 8) ? s_sq[t]  : 0.f;
        #pragma unroll
        for (int off = 4; off; off >>= 1) {
            a += __shfl_xor_sync(0xffffffffu, a, off);
            b += __shfl_xor_sync(0xffffffffu, b, off);
        }
        if (t == 0) { s_sum[0] = a; s_sq[0] = b; }
    }
    __syncthreads();

    float mu  = s_sum[0] * (1.0f / DM);
    float var = s_sq[0] * (1.0f / DM) - mu * mu;
    float rstd = rsqrtf(var + EPS_);

    const float4* g4 = (const float4*)g;
    const float4* b4 = (const float4*)bb;
    {
        float4 gv = g4[t], bv = b4[t];
        uint2 u;
        u.x = packbf2((v0.x - mu) * rstd * gv.x + bv.x,
                      (v0.y - mu) * rstd * gv.y + bv.y);
        u.y = packbf2((v0.z - mu) * rstd * gv.z + bv.z,
                      (v0.w - mu) * rstd * gv.w + bv.w);
        orow[t] = u;
    }
    {
        float4 gv = g4[t + 256], bv = b4[t + 256];
        uint2 u;
        u.x = packbf2((v1.x - mu) * rstd * gv.x + bv.x,
                      (v1.y - mu) * rstd * gv.y + bv.y);
        u.y = packbf2((v1.z - mu) * rstd * gv.z + bv.z,
                      (v1.w - mu) * rstd * gv.w + bv.w);
        orow[t + 256] = u;
    }
}

// ---------------------------------------------------------------------------
// Pipelined BF16 GEMM NT. Optional bf16 output (Cb != null) or fp32 (C).
// 2 K-chunks per barrier: prologue loads chunks 0..1; each pair issues the
// next pair's loads right after its barrier (they have the whole pair compute
// to land), then computes both chunks. 32 barriers total, 64 HMMA per region.
// ---------------------------------------------------------------------------
#define BSTAGES 4
#define BROWB   80
#define BSTAGE_BYTES 20480      // 2 * 128 * 80

__global__ __launch_bounds__(256, 2)
void bgemm_nt(const __nv_bfloat16* __restrict__ A,
              const __nv_bfloat16* __restrict__ W,
              const float* __restrict__ bias, const float* __restrict__ res,
              float* __restrict__ C, __nv_bfloat16* __restrict__ Cb,
              int K, int N)
{
    extern __shared__ char smem[];
    uint32_t sb = (uint32_t)__cvta_generic_to_shared(smem);

    int t = threadIdx.x;
    int lane = t & 31;
    int w = t >> 5;
    int wm = w >> 2, wn = w & 3;
    int m0 = blockIdx.y << 7, n0 = blockIdx.x << 7;

    int lm = t >> 2;
    int kq = t & 3;
    const __nv_bfloat16* gA0 = A + (size_t)(m0 + lm) * K + kq * 8;
    const __nv_bfloat16* gA1 = gA0 + (size_t)64 * K;
    const __nv_bfloat16* gW0 = W + (size_t)(n0 + lm) * K + kq * 8;
    const __nv_bfloat16* gW1 = gW0 + (size_t)64 * K;
    uint32_t dA0 = (uint32_t)lm * BROWB + kq * 16;
    uint32_t dA1 = dA0 + 64 * BROWB;
    uint32_t dB0 = 10240 + dA0;
    uint32_t dB1 = 10240 + dA1;

    int aoff[2][4], boff[2][4];
    #pragma unroll
    for (int ks = 0; ks < 2; ks++) {
        #pragma unroll
        for (int i = 0; i < 4; i++) {
            int mrow = (wm * 4 + i) * 16 + (lane & 7) + ((lane >> 3) & 1) * 8;
            aoff[ks][i] = mrow * BROWB + ks * 32 + (lane >> 4) * 16;
            int nrow = (wn * 4 + i) * 8 + (lane & 7);
            boff[ks][i] = 10240 + nrow * BROWB + ks * 32 + ((lane >> 3) & 1) * 16;
        }
    }

    float acc[4][4][4];
    #pragma unroll
    for (int i = 0; i < 4; i++)
        #pragma unroll
        for (int j = 0; j < 4; j++)
            #pragma unroll
            for (int r = 0; r < 4; r++) acc[i][j][r] = 0.f;

    const int nIter = K >> 5;      // 64 (even)

    auto load_stage = [&](int c) {
        uint32_t s = sb + (uint32_t)(c & 3) * BSTAGE_BYTES;
        int ko = c << 5;
        CP_ASYNC16(s + dA0, gA0 + ko);
        CP_ASYNC16(s + dA1, gA1 + ko);
        CP_ASYNC16(s + dB0, gW0 + ko);
        CP_ASYNC16(s + dB1, gW1 + ko);
        CP_COMMIT();
    };

    load_stage(0); load_stage(1);

    for (int c = 0; c < nIter; c += 2) {
        CP_WAIT(0);
        __syncthreads();

        // issue next pair's loads (they land during this pair's compute)
        if (c + 2 < nIter) { load_stage(c + 2); load_stage(c + 3); }

        #pragma unroll
        for (int hh = 0; hh < 2; hh++) {
            uint32_t s = sb + (uint32_t)((c + hh) & 3) * BSTAGE_BYTES;
            #pragma unroll
            for (int ks = 0; ks < 2; ks++) {
                uint4 af[4]; uint2 bf[4];
                #pragma unroll
                for (int i = 0; i < 4; i++) LDSM_X4(af[i], s + aoff[ks][i]);
                #pragma unroll
                for (int j = 0; j < 4; j++) LDSM_X2(bf[j], s + boff[ks][j]);
                #pragma unroll
                for (int i = 0; i < 4; i++)
                    #pragma unroll
                    for (int j = 0; j < 4; j++)
                        mma_bf16(acc[i][j], af[i], bf[j]);
            }
        }
    }

    // epilogue
    #pragma unroll
    for (int i = 0; i < 4; i++) {
        int r0 = m0 + wm * 64 + i * 16 + (lane >> 2);
        #pragma unroll
        for (int j = 0; j < 4; j++) {
            int c = n0 + wn * 32 + j * 8 + (lane & 3) * 2;
            float b0 = bias[c], b1 = bias[c + 1];
            size_t o0 = (size_t)r0 * N + c;
            size_t o1 = (size_t)(r0 + 8) * N + c;
            float2 v0 = make_float2(acc[i][j][0] + b0, acc[i][j][1] + b1);
            float2 v1 = make_float2(acc[i][j][2] + b0, acc[i][j][3] + b1);
            if (res) {
                float2 e0 = *(const float2*)(res + o0);
                float2 e1 = *(const float2*)(res + o1);
                v0.x += e0.x; v0.y += e0.y;
                v1.x += e1.x; v1.y += e1.y;
            }
            if (Cb) {
                *(uint32_t*)(Cb + o0) = packbf2(v0.x, v0.y);
                *(uint32_t*)(Cb + o1) = packbf2(v1.x, v1.y);
            } else {
                *(float2*)(C + o0) = v0;
                *(float2*)(C + o1) = v1;
            }
        }
    }
}

// ---------------------------------------------------------------------------
// RoPE apply: reads bf16 q/k (from GEMM), rotates in fp32, writes bf16.
// ---------------------------------------------------------------------------
__global__ __launch_bounds__(256)
void rope_bf_kernel(const __nv_bfloat16* __restrict__ q,
                    const __nv_bfloat16* __restrict__ k,
                    __nv_bfloat16* __restrict__ qo, __nv_bfloat16* __restrict__ ko,
                    const float2* __restrict__ tab)
{
    int idx = blockIdx.x * 256 + threadIdx.x;
    const __nv_bfloat16* src = (blockIdx.y == 0) ? q : k;
    __nv_bfloat16* dst = (blockIdx.y == 0) ? qo : ko;

    int j   = idx & 63;
    int hh  = (idx >> 6) & (NH - 1);
    int row = idx >> 10;
    int pos = row & (S_ - 1);

    float2 cs = tab[(pos << 6) + j];
    float c = cs.x, s = cs.y;

    size_t off = (size_t)row * DM + (hh << 7) + j;
    float x0 = __bfloat162float(src[off]);
    float x1 = __bfloat162float(src[off + 64]);
    dst[off]      = __float2bfloat16(x0 * c - x1 * s);
    dst[off + 64] = __float2bfloat16(x1 * c + x0 * s);
}

// ---------------------------------------------------------------------------
// BF16 flash attention, causal. BQ=128, BK=64, register-resident softmax.
// (unchanged from R14 — warp-uniform causal skip)
// ---------------------------------------------------------------------------
#define ZROWB  272
#define Z_Q    0
#define Z_K    34816
#define Z_V    52224
#define Z_P    69632                 // 128 rows * 144B
#define Z_SMEM 88064

__global__ __launch_bounds__(256)
void attn_bq128_kernel(const __nv_bfloat16* __restrict__ q,
                       const __nv_bfloat16* __restrict__ k,
                       const __nv_bfloat16* __restrict__ v,
                       __nv_bfloat16* __restrict__ o)
{
    extern __shared__ char sm[];
    uint32_t sb = (uint32_t)__cvta_generic_to_shared(sm);

    int t = threadIdx.x;
    int lane = t & 31;
    int w = t >> 5;
    int lr = lane >> 2;
    int lc = lane & 3;

    int q0 = blockIdx.x << 7;
    size_t base = ((size_t)blockIdx.z * S_) * DM + ((size_t)blockIdx.y << 7);

    // ---- load Q tile: 128 rows x 256B raw copy ----
    #pragma unroll
    for (int it = 0; it < 8; it++) {
        int idx = t + (it << 8);          // 0..2047
        int r = idx >> 4, c16 = idx & 15;
        uint4 x = *(const uint4*)(q + base + (size_t)(q0 + r) * DM + c16 * 8);
        *(uint4*)(sm + Z_Q + r * ZROWB + c16 * 16) = x;
    }

    int r_lo = (w << 4) + lr;
    int r_hi = r_lo + 8;
    int qi_lo = q0 + r_lo;
    int qi_hi = q0 + r_hi;

    float m_lo = -INFINITY, m_hi = -INFINITY;
    float l_lo = 0.f, l_hi = 0.f;
    float oacc[16][4];
    #pragma unroll
    for (int i = 0; i < 16; i++)
        #pragma unroll
        for (int r = 0; r < 4; r++) oacc[i][r] = 0.f;

    __syncthreads();

    for (int j0 = 0; j0 <= q0 + 64; j0 += 64) {
        #pragma unroll
        for (int it = 0; it < 4; it++) {
            int idx = t + (it << 8);
            int r = idx >> 4, c16 = idx & 15;
            size_t goff = base + (size_t)(j0 + r) * DM + c16 * 8;
            *(uint4*)(sm + Z_K + r * ZROWB + c16 * 16) = *(const uint4*)(k + goff);
            *(uint4*)(sm + Z_V + r * ZROWB + c16 * 16) = *(const uint4*)(v + goff);
        }
        __syncthreads();

        // WARP-UNIFORM causal skip
        bool active = (q0 + (w << 4) + 15 >= j0);
        if (active) {
            float sacc[8][4];
            #pragma unroll
            for (int nf = 0; nf < 8; nf++)
                #pragma unroll
                for (int r = 0; r < 4; r++) sacc[nf][r] = 0.f;

            #pragma unroll
            for (int ks = 0; ks < 8; ks++) {
                uint4 af;
                LDSM_X4(af, sb + Z_Q + ((w << 4) + (lane & 15)) * ZROWB
                            + ks * 32 + (lane >> 4) * 16);
                #pragma unroll
                for (int nf = 0; nf < 8; nf++) {
                    uint2 bf;
                    LDSM_X2(bf, sb + Z_K + (nf * 8 + (lane & 7)) * ZROWB
                                + ks * 32 + ((lane >> 3) & 1) * 16);
                    mma_bf16(sacc[nf], af, bf);
                }
            }

            const float sc = 0.08838834764831845f;
            float mx_lo = -INFINITY, mx_hi = -INFINITY;
            #pragma unroll
            for (int nf = 0; nf < 8; nf++) {
                int kj = j0 + nf * 8 + lc * 2;
                float v0 = sacc[nf][0] * sc; if (kj     > qi_lo) v0 = -INFINITY;
                float v1 = sacc[nf][1] * sc; if (kj + 1 > qi_lo) v1 = -INFINITY;
                float v2 = sacc[nf][2] * sc; if (kj     > qi_hi) v2 = -INFINITY;
                float v3 = sacc[nf][3] * sc; if (kj + 1 > qi_hi) v3 = -INFINITY;
                sacc[nf][0] = v0; sacc[nf][1] = v1;
                sacc[nf][2] = v2; sacc[nf][3] = v3;
                mx_lo = fmaxf(mx_lo, fmaxf(v0, v1));
                mx_hi = fmaxf(mx_hi, fmaxf(v2, v3));
            }
            mx_lo = fmaxf(mx_lo, __shfl_xor_sync(0xffffffffu, mx_lo, 1));
            mx_lo = fmaxf(mx_lo, __shfl_xor_sync(0xffffffffu, mx_lo, 2));
            mx_hi = fmaxf(mx_hi, __shfl_xor_sync(0xffffffffu, mx_hi, 1));
            mx_hi = fmaxf(mx_hi, __shfl_xor_sync(0xffffffffu, mx_hi, 2));

            float mn_lo = fmaxf(m_lo, mx_lo);
            float mn_hi = fmaxf(m_hi, mx_hi);
            float corr_lo = expf(m_lo - mn_lo);
            float corr_hi = expf(m_hi - mn_hi);

            float sum_lo = 0.f, sum_hi = 0.f;
            #pragma unroll
            for (int nf = 0; nf < 8; nf++) {
                __nv_bfloat16 e0 = __float2bfloat16(expf(sacc[nf][0] - mn_lo));
                __nv_bfloat16 e1 = __float2bfloat16(expf(sacc[nf][1] - mn_lo));
                __nv_bfloat16 e2 = __float2bfloat16(expf(sacc[nf][2] - mn_hi));
                __nv_bfloat16 e3 = __float2bfloat16(expf(sacc[nf][3] - mn_hi));
                int colb = (nf * 8 + lc * 2) * 2;
                __nv_bfloat162 p01; p01.x = e0; p01.y = e1;
                __nv_bfloat162 p23; p23.x = e2; p23.y = e3;
                *(uint32_t*)(sm + Z_P + r_lo * 144 + colb) = *(uint32_t*)&p01;
                *(uint32_t*)(sm + Z_P + r_hi * 144 + colb) = *(uint32_t*)&p23;
                sum_lo += __bfloat162float(e0) + __bfloat162float(e1);
                sum_hi += __bfloat162float(e2) + __bfloat162float(e3);
            }
            sum_lo += __shfl_xor_sync(0xffffffffu, sum_lo, 1);
            sum_lo += __shfl_xor_sync(0xffffffffu, sum_lo, 2);
            sum_hi += __shfl_xor_sync(0xffffffffu, sum_hi, 1);
            sum_hi += __shfl_xor_sync(0xffffffffu, sum_hi, 2);

            l_lo = l_lo * corr_lo + sum_lo;
            l_hi = l_hi * corr_hi + sum_hi;
            m_lo = mn_lo;
            m_hi = mn_hi;

            #pragma unroll
            for (int nf = 0; nf < 16; nf++) {
                oacc[nf][0] *= corr_lo; oacc[nf][1] *= corr_lo;
                oacc[nf][2] *= corr_hi; oacc[nf][3] *= corr_hi;
            }

            __syncwarp();

            #pragma unroll
            for (int kf = 0; kf < 4; kf++) {
                uint4 af;
                LDSM_X4(af, sb + Z_P + ((w << 4) + (lane & 15)) * 144
                            + kf * 32 + (lane >> 4) * 16);
                #pragma unroll
                for (int nf = 0; nf < 16; nf++) {
                    uint2 bf;
                    LDSM_X2T(bf, sb + Z_V
                                 + (kf * 16 + ((lane >> 3) & 1) * 8 + (lane & 7)) * ZROWB
                                 + nf * 16);
                    mma_bf16(oacc[nf], af, bf);
                }
            }
        }
        __syncthreads();
    }

    // ---- epilogue: O / l -> bf16 ----
    {
        float inv_lo = 1.0f / l_lo;
        float inv_hi = 1.0f / l_hi;
        #pragma unroll
        for (int nf = 0; nf < 16; nf++) {
            int col = nf * 8 + lc * 2;
            __nv_bfloat16* d0 = o + base + (size_t)(q0 + r_lo) * DM + col;
            __nv_bfloat16* d1 = o + base + (size_t)(q0 + r_hi) * DM + col;
            *(uint32_t*)d0 = packbf2(oacc[nf][0] * inv_lo, oacc[nf][1] * inv_lo);
            *(uint32_t*)d1 = packbf2(oacc[nf][2] * inv_hi, oacc[nf][3] * inv_hi);
        }
    }
}

// ---------------------------------------------------------------------------
// Launch
// ---------------------------------------------------------------------------
extern "C" void kernel_launch(void* const* d_in, const int* in_sizes, int n_in,
                              void* d_out, int out_size)
{
    const float* h  = (const float*)d_in[0];
    const float* wq = (const float*)d_in[1];
    const float* bq = (const float*)d_in[2];
    const float* wk = (const float*)d_in[3];
    const float* bk = (const float*)d_in[4];
    const float* wv = (const float*)d_in[5];
    const float* bv = (const float*)d_in[6];
    const float* wo = (const float*)d_in[7];
    const float* bo = (const float*)d_in[8];
    const float* lg = (const float*)d_in[9];
    const float* lb = (const float*)d_in[10];
    float* out = (float*)d_out;

    float *xn, *qb, *kb, *vb, *ob;
    __nv_bfloat16* wb;
    float2* rt;
    cudaGetSymbolAddress((void**)&xn, g_xn);
    cudaGetSymbolAddress((void**)&qb, g_q);
    cudaGetSymbolAddress((void**)&kb, g_k);
    cudaGetSymbolAddress((void**)&vb, g_v);
    cudaGetSymbolAddress((void**)&ob, g_o);
    cudaGetSymbolAddress((void**)&wb, g_wb);
    cudaGetSymbolAddress((void**)&rt, g_rope);

    __nv_bfloat16* xn_bf = (__nv_bfloat16*)xn;                     // first 16MB
    __nv_bfloat16* q_bf  = (__nv_bfloat16*)xn;                     // roped q (reuse)
    __nv_bfloat16* k_bf  = (__nv_bfloat16*)xn + (size_t)MROWS * DM;// roped k
    __nv_bfloat16* qraw  = (__nv_bfloat16*)qb;                     // pre-rope q
    __nv_bfloat16* kraw  = (__nv_bfloat16*)kb;                     // pre-rope k
    __nv_bfloat16* v_bf  = (__nv_bfloat16*)vb;
    __nv_bfloat16* ob_bf = (__nv_bfloat16*)ob;
    __nv_bfloat16* wq_bf = wb;
    __nv_bfloat16* wk_bf = wb + (size_t)DM * DM;
    __nv_bfloat16* wv_bf = wb + 2 * (size_t)DM * DM;
    __nv_bfloat16* wo_bf = wb + 3 * (size_t)DM * DM;

    // 0. RoPE table + fused weight conversion
    rope_table_kernel<<<(S_ * 64 + 255) / 256, 256>>>(rt);
    int n4 = DM * DM / 4;
    wconv4_kernel<<<dim3((n4 + 255) / 256, 4), 256>>>(
        wq, wk, wv, wo, wq_bf, wk_bf, wv_bf, wo_bf, n4);

    // 1. LayerNorm (bf16 out)
    ln_kernel<<<MROWS, 256>>>(h, lg, lb, xn_bf);

    // 2. QKV projections — all outputs bf16 now.
    int smem_g = BSTAGES * BSTAGE_BYTES;     // 81920
    cudaFuncSetAttribute(bgemm_nt, cudaFuncAttributeMaxDynamicSharedMemorySize,
                         smem_g);
    dim3 gg(DM / 128, MROWS / 128);
    bgemm_nt<<<gg, 256, smem_g>>>(xn_bf, wq_bf, bq, nullptr, nullptr, qraw, DM, DM);
    bgemm_nt<<<gg, 256, smem_g>>>(xn_bf, wk_bf, bk, nullptr, nullptr, kraw, DM, DM);
    bgemm_nt<<<gg, 256, smem_g>>>(xn_bf, wv_bf, bv, nullptr, nullptr, v_bf, DM, DM);

    // 3. RoPE on q, k: bf16 in, bf16 out (xn buffer reused — GEMMs done)
    rope_bf_kernel<<<dim3((MROWS * NH * 64) / 256, 2), 256>>>(qraw, kraw, q_bf, k_bf, rt);

    // 4. Causal flash attention (BQ=128, register softmax)
    cudaFuncSetAttribute(attn_bq128_kernel,
                         cudaFuncAttributeMaxDynamicSharedMemorySize, Z_SMEM);
    attn_bq128_kernel<<<dim3(S_ / 128, NH, B_), 256, Z_SMEM>>>(q_bf, k_bf, v_bf, ob_bf);

    // 5. Output projection + bias + residual (fp32 out)
    bgemm_nt<<<gg, 256, smem_g>>>(ob_bf, wo_bf, bo, h, out, nullptr, DM, DM);
}

// round 17
// speedup vs baseline: 6.9776x; 1.0198x over previous
#include <cuda_runtime.h>
#include <cuda_bf16.h>
#include <math.h>
#include <stdint.h>

// Problem constants (fixed shapes)
#define B_    2
#define S_    2048
#define DM    2048
#define NH    16
#define DK_   128
#define MROWS (B_ * S_)      // 4096
#define EPS_  1e-5f

// ---------------------------------------------------------------------------
// Scratch (no cudaMalloc allowed)
// ---------------------------------------------------------------------------
__device__ float g_xn[(size_t)MROWS * DM];   // [0:16MB) bf16 xn ; [16MB:32MB) bf16 roped k
__device__ float g_q [(size_t)MROWS * DM / 2]; // bf16 roped q (16MB) — MUST NOT alias xn
__device__ float g_v [(size_t)MROWS * DM];   // bf16 v (from GEMM)
__device__ float g_o [(size_t)MROWS * DM];   // bf16 attention out
__device__ __nv_bfloat16 g_wb[4][(size_t)DM * DM];  // bf16 weights
__device__ float2 g_rope[(size_t)S_ * 64];   // (cos, sin) per (pos, j)

// ---------------------------------------------------------------------------
// helpers
// ---------------------------------------------------------------------------
__device__ __forceinline__ uint32_t packbf2(float a, float b)
{
    __nv_bfloat162 h = __floats2bfloat162_rn(a, b);
    return *(uint32_t*)&h;
}

__device__ __forceinline__ void mma_bf16(float* c, const uint4& a, const uint2& b)
{
    asm volatile(
        "mma.sync.aligned.m16n8k16.row.col.f32.bf16.bf16.f32 "
        "{%0,%1,%2,%3}, {%4,%5,%6,%7}, {%8,%9}, {%0,%1,%2,%3};\n"
        : "+f"(c[0]), "+f"(c[1]), "+f"(c[2]), "+f"(c[3])
        : "r"(a.x), "r"(a.y), "r"(a.z), "r"(a.w), "r"(b.x), "r"(b.y));
}

#define CP_ASYNC16(dst, src) \
    asm volatile("cp.async.cg.shared.global [%0], [%1], 16;" \
                 :: "r"((uint32_t)(dst)), "l"(src))
#define CP_COMMIT() asm volatile("cp.async.commit_group;" ::: "memory")
#define CP_WAIT(N)  asm volatile("cp.async.wait_group %0;" :: "n"(N) : "memory")

#define LDSM_X4(d, addr) \
    asm volatile("ldmatrix.sync.aligned.m8n8.x4.shared.b16 {%0,%1,%2,%3}, [%4];" \
                 : "=r"((d).x), "=r"((d).y), "=r"((d).z), "=r"((d).w) \
                 : "r"((uint32_t)(addr)))
#define LDSM_X2(d, addr) \
    asm volatile("ldmatrix.sync.aligned.m8n8.x2.shared.b16 {%0,%1}, [%2];" \
                 : "=r"((d).x), "=r"((d).y) \
                 : "r"((uint32_t)(addr)))
#define LDSM_X2T(d, addr) \
    asm volatile("ldmatrix.sync.aligned.m8n8.x2.trans.shared.b16 {%0,%1}, [%2];" \
                 : "=r"((d).x), "=r"((d).y) \
                 : "r"((uint32_t)(addr)))

// ---------------------------------------------------------------------------
// Fused weight conversion fp32 -> bf16 (rn): all 4 matrices, 4 float4/thread.
// ---------------------------------------------------------------------------
__global__ __launch_bounds__(256)
void wconv4_kernel(const float* __restrict__ s0, const float* __restrict__ s1,
                   const float* __restrict__ s2, const float* __restrict__ s3,
                   __nv_bfloat16* __restrict__ d0, __nv_bfloat16* __restrict__ d1,
                   __nv_bfloat16* __restrict__ d2, __nv_bfloat16* __restrict__ d3,
                   int n4)
{
    const float* src;
    __nv_bfloat16* dst;
    switch (blockIdx.y) {
        case 0:  src = s0; dst = d0; break;
        case 1:  src = s1; dst = d1; break;
        case 2:  src = s2; dst = d2; break;
        default: src = s3; dst = d3; break;
    }
    int i0 = blockIdx.x * 1024 + threadIdx.x;
    float4 x[4];
    #pragma unroll
    for (int u = 0; u < 4; u++) {
        int idx = i0 + u * 256;
        if (idx < n4) x[u] = ((const float4*)src)[idx];
    }
    #pragma unroll
    for (int u = 0; u < 4; u++) {
        int idx = i0 + u * 256;
        if (idx < n4) {
            uint2 v;
            v.x = packbf2(x[u].x, x[u].y);
            v.y = packbf2(x[u].z, x[u].w);
            ((uint2*)dst)[idx] = v;
        }
    }
}

// ---------------------------------------------------------------------------
// RoPE table: accurate double-precision sincos of the fp32-quantized phase.
// ---------------------------------------------------------------------------
__global__ __launch_bounds__(256)
void rope_table_kernel(float2* __restrict__ tab)
{
    int idx = blockIdx.x * 256 + threadIdx.x;     // [0, S_*64)
    if (idx >= S_ * 64) return;
    int j   = idx & 63;
    int pos = idx >> 6;
    double theta_d = 1.0 / pow(10000.0, (double)j / 64.0);
    float  theta_f = (float)theta_d;
    float fr = (float)pos * theta_f;
    double dfr = (double)fr;
    tab[idx] = make_float2((float)cos(dfr), (float)sin(dfr));
}

// ---------------------------------------------------------------------------
// LayerNorm (outputs bf16)
// ---------------------------------------------------------------------------
__global__ __launch_bounds__(256)
void ln_kernel(const float* __restrict__ x, const float* __restrict__ g,
               const float* __restrict__ bb, __nv_bfloat16* __restrict__ out)
{
    int row = blockIdx.x;
    int t = threadIdx.x;
    const float4* xr = (const float4*)(x + (size_t)row * DM);
    uint2* orow = (uint2*)(out + (size_t)row * DM);

    float4 v0 = xr[t];
    float4 v1 = xr[t + 256];
    float sum = v0.x + v0.y + v0.z + v0.w + v1.x + v1.y + v1.z + v1.w;
    float sq  = v0.x*v0.x + v0.y*v0.y + v0.z*v0.z + v0.w*v0.w
              + v1.x*v1.x + v1.y*v1.y + v1.z*v1.z + v1.w*v1.w;

    #pragma unroll
    for (int off = 16; off; off >>= 1) {
        sum += __shfl_xor_sync(0xffffffffu, sum, off);
        sq  += __shfl_xor_sync(0xffffffffu, sq,  off);
    }
    __shared__ float s_sum[8], s_sq[8];
    int w = t >> 5;
    if ((t & 31) == 0) { s_sum[w] = sum; s_sq[w] = sq; }
    __syncthreads();
    if (t < 32) {
        float a = (t < 8) ? s_sum[t] : 0.f;
        float b = (t < 8) ? s_sq[t]  : 0.f;
        #pragma unroll
        for (int off = 4; off; off >>= 1) {
            a += __shfl_xor_sync(0xffffffffu, a, off);
            b += __shfl_xor_sync(0xffffffffu, b, off);
        }
        if (t == 0) { s_sum[0] = a; s_sq[0] = b; }
    }
    __syncthreads();

    float mu  = s_sum[0] * (1.0f / DM);
    float var = s_sq[0] * (1.0f / DM) - mu * mu;
    float rstd = rsqrtf(var + EPS_);

    const float4* g4 = (const float4*)g;
    const float4* b4 = (const float4*)bb;
    {
        float4 gv = g4[t], bv = b4[t];
        uint2 u;
        u.x = packbf2((v0.x - mu) * rstd * gv.x + bv.x,
                      (v0.y - mu) * rstd * gv.y + bv.y);
        u.y = packbf2((v0.z - mu) * rstd * gv.z + bv.z,
                      (v0.w - mu) * rstd * gv.w + bv.w);
        orow[t] = u;
    }
    {
        float4 gv = g4[t + 256], bv = b4[t + 256];
        uint2 u;
        u.x = packbf2((v1.x - mu) * rstd * gv.x + bv.x,
                      (v1.y - mu) * rstd * gv.y + bv.y);
        u.y = packbf2((v1.z - mu) * rstd * gv.z + bv.z,
                      (v1.w - mu) * rstd * gv.w + bv.w);
        orow[t + 256] = u;
    }
}

// ---------------------------------------------------------------------------
// Pipelined BF16 GEMM NT. Outputs:
//   ropeTab != null : RoPE applied in epilogue, bf16 out to Cb (Q/K GEMMs).
//   else Cb != null : plain bf16 out (V GEMM).
//   else            : fp32 out to C with optional residual (output GEMM).
// Cb MUST NOT alias A (intra-launch RAW hazard).
// ---------------------------------------------------------------------------
#define BSTAGES 4
#define BROWB   80
#define BSTAGE_BYTES 20480      // 2 * 128 * 80

__global__ __launch_bounds__(256, 2)
void bgemm_nt(const __nv_bfloat16* __restrict__ A,
              const __nv_bfloat16* __restrict__ W,
              const float* __restrict__ bias, const float* __restrict__ res,
              float* __restrict__ C, __nv_bfloat16* __restrict__ Cb,
              const float2* __restrict__ ropeTab, int K, int N)
{
    extern __shared__ char smem[];
    uint32_t sb = (uint32_t)__cvta_generic_to_shared(smem);

    int t = threadIdx.x;
    int lane = t & 31;
    int w = t >> 5;
    int wm = w >> 2, wn = w & 3;
    int m0 = blockIdx.y << 7, n0 = blockIdx.x << 7;

    int lm = t >> 2;
    int kq = t & 3;
    const __nv_bfloat16* gA0 = A + (size_t)(m0 + lm) * K + kq * 8;
    const __nv_bfloat16* gA1 = gA0 + (size_t)64 * K;
    const __nv_bfloat16* gW0 = W + (size_t)(n0 + lm) * K + kq * 8;
    const __nv_bfloat16* gW1 = gW0 + (size_t)64 * K;
    uint32_t dA0 = (uint32_t)lm * BROWB + kq * 16;
    uint32_t dA1 = dA0 + 64 * BROWB;
    uint32_t dB0 = 10240 + dA0;
    uint32_t dB1 = 10240 + dA1;

    int aoff[2][4], boff[2][4];
    #pragma unroll
    for (int ks = 0; ks < 2; ks++) {
        #pragma unroll
        for (int i = 0; i < 4; i++) {
            int mrow = (wm * 4 + i) * 16 + (lane & 7) + ((lane >> 3) & 1) * 8;
            aoff[ks][i] = mrow * BROWB + ks * 32 + (lane >> 4) * 16;
            int nrow = (wn * 4 + i) * 8 + (lane & 7);
            boff[ks][i] = 10240 + nrow * BROWB + ks * 32 + ((lane >> 3) & 1) * 16;
        }
    }

    float acc[4][4][4];
    #pragma unroll
    for (int i = 0; i < 4; i++)
        #pragma unroll
        for (int j = 0; j < 4; j++)
            #pragma unroll
            for (int r = 0; r < 4; r++) acc[i][j][r] = 0.f;

    const int nIter = K >> 5;      // 64 (even)

    auto load_stage = [&](int c) {
        uint32_t s = sb + (uint32_t)(c & 3) * BSTAGE_BYTES;
        int ko = c << 5;
        CP_ASYNC16(s + dA0, gA0 + ko);
        CP_ASYNC16(s + dA1, gA1 + ko);
        CP_ASYNC16(s + dB0, gW0 + ko);
        CP_ASYNC16(s + dB1, gW1 + ko);
        CP_COMMIT();
    };

    load_stage(0); load_stage(1);

    for (int c = 0; c < nIter; c += 2) {
        CP_WAIT(0);
        __syncthreads();

        if (c + 2 < nIter) { load_stage(c + 2); load_stage(c + 3); }

        #pragma unroll
        for (int hh = 0; hh < 2; hh++) {
            uint32_t s = sb + (uint32_t)((c + hh) & 3) * BSTAGE_BYTES;
            #pragma unroll
            for (int ks = 0; ks < 2; ks++) {
                uint4 af[4]; uint2 bf[4];
                #pragma unroll
                for (int i = 0; i < 4; i++) LDSM_X4(af[i], s + aoff[ks][i]);
                #pragma unroll
                for (int j = 0; j < 4; j++) LDSM_X2(bf[j], s + boff[ks][j]);
                #pragma unroll
                for (int i = 0; i < 4; i++)
                    #pragma unroll
                    for (int j = 0; j < 4; j++)
                        mma_bf16(acc[i][j], af[i], bf[j]);
            }
        }
    }

    if (ropeTab) {
        // ---- RoPE epilogue: stage C+bias fp32 in smem, rotate, bf16 out ----
        float* cs = (float*)smem;          // [128][132]
        __syncthreads();                   // stage buffers fully consumed
        #pragma unroll
        for (int i = 0; i < 4; i++) {
            int r = wm * 64 + i * 16 + (lane >> 2);
            #pragma unroll
            for (int j = 0; j < 4; j++) {
                int c = wn * 32 + j * 8 + (lane & 3) * 2;
                float b0 = bias[n0 + c], b1 = bias[n0 + c + 1];
                cs[r * 132 + c]     = acc[i][j][0] + b0;
                cs[r * 132 + c + 1] = acc[i][j][1] + b1;
                cs[(r + 8) * 132 + c]     = acc[i][j][2] + b0;
                cs[(r + 8) * 132 + c + 1] = acc[i][j][3] + b1;
            }
        }
        __syncthreads();
        #pragma unroll
        for (int u = 0; u < 16; u++) {
            int unit = t + u * 256;        // 0..4095
            int r = unit >> 5;             // 0..127
            int jp = (unit & 31) << 1;     // 0,2,..,62
            float x0a = cs[r * 132 + jp];
            float x0b = cs[r * 132 + jp + 1];
            float x1a = cs[r * 132 + 64 + jp];
            float x1b = cs[r * 132 + 64 + jp + 1];
            int pos = (m0 + r) & (S_ - 1);
            float2 t0 = ropeTab[(pos << 6) + jp];
            float2 t1 = ropeTab[(pos << 6) + jp + 1];
            size_t go = (size_t)(m0 + r) * N + n0;
            *(uint32_t*)(Cb + go + jp) =
                packbf2(x0a * t0.x - x1a * t0.y, x0b * t1.x - x1b * t1.y);
            *(uint32_t*)(Cb + go + 64 + jp) =
                packbf2(x1a * t0.x + x0a * t0.y, x1b * t1.x + x0b * t1.y);
        }
        return;
    }

    // ---- plain epilogue ----
    #pragma unroll
    for (int i = 0; i < 4; i++) {
        int r0 = m0 + wm * 64 + i * 16 + (lane >> 2);
        #pragma unroll
        for (int j = 0; j < 4; j++) {
            int c = n0 + wn * 32 + j * 8 + (lane & 3) * 2;
            float b0 = bias[c], b1 = bias[c + 1];
            size_t o0 = (size_t)r0 * N + c;
            size_t o1 = (size_t)(r0 + 8) * N + c;
            float2 v0 = make_float2(acc[i][j][0] + b0, acc[i][j][1] + b1);
            float2 v1 = make_float2(acc[i][j][2] + b0, acc[i][j][3] + b1);
            if (res) {
                float2 e0 = *(const float2*)(res + o0);
                float2 e1 = *(const float2*)(res + o1);
                v0.x += e0.x; v0.y += e0.y;
                v1.x += e1.x; v1.y += e1.y;
            }
            if (Cb) {
                *(uint32_t*)(Cb + o0) = packbf2(v0.x, v0.y);
                *(uint32_t*)(Cb + o1) = packbf2(v1.x, v1.y);
            } else {
                *(float2*)(C + o0) = v0;
                *(float2*)(C + o1) = v1;
            }
        }
    }
}

// ---------------------------------------------------------------------------
// BF16 flash attention, causal. BQ=128, BK=64, register-resident softmax.
// (unchanged — warp-uniform causal skip)
// ---------------------------------------------------------------------------
#define ZROWB  272
#define Z_Q    0
#define Z_K    34816
#define Z_V    52224
#define Z_P    69632                 // 128 rows * 144B
#define Z_SMEM 88064

__global__ __launch_bounds__(256)
void attn_bq128_kernel(const __nv_bfloat16* __restrict__ q,
                       const __nv_bfloat16* __restrict__ k,
                       const __nv_bfloat16* __restrict__ v,
                       __nv_bfloat16* __restrict__ o)
{
    extern __shared__ char sm[];
    uint32_t sb = (uint32_t)__cvta_generic_to_shared(sm);

    int t = threadIdx.x;
    int lane = t & 31;
    int w = t >> 5;
    int lr = lane >> 2;
    int lc = lane & 3;

    int q0 = blockIdx.x << 7;
    size_t base = ((size_t)blockIdx.z * S_) * DM + ((size_t)blockIdx.y << 7);

    #pragma unroll
    for (int it = 0; it < 8; it++) {
        int idx = t + (it << 8);
        int r = idx >> 4, c16 = idx & 15;
        uint4 x = *(const uint4*)(q + base + (size_t)(q0 + r) * DM + c16 * 8);
        *(uint4*)(sm + Z_Q + r * ZROWB + c16 * 16) = x;
    }

    int r_lo = (w << 4) + lr;
    int r_hi = r_lo + 8;
    int qi_lo = q0 + r_lo;
    int qi_hi = q0 + r_hi;

    float m_lo = -INFINITY, m_hi = -INFINITY;
    float l_lo = 0.f, l_hi = 0.f;
    float oacc[16][4];
    #pragma unroll
    for (int i = 0; i < 16; i++)
        #pragma unroll
        for (int r = 0; r < 4; r++) oacc[i][r] = 0.f;

    __syncthreads();

    for (int j0 = 0; j0 <= q0 + 64; j0 += 64) {
        #pragma unroll
        for (int it = 0; it < 4; it++) {
            int idx = t + (it << 8);
            int r = idx >> 4, c16 = idx & 15;
            size_t goff = base + (size_t)(j0 + r) * DM + c16 * 8;
            *(uint4*)(sm + Z_K + r * ZROWB + c16 * 16) = *(const uint4*)(k + goff);
            *(uint4*)(sm + Z_V + r * ZROWB + c16 * 16) = *(const uint4*)(v + goff);
        }
        __syncthreads();

        bool active = (q0 + (w << 4) + 15 >= j0);   // WARP-UNIFORM
        if (active) {
            float sacc[8][4];
            #pragma unroll
            for (int nf = 0; nf < 8; nf++)
                #pragma unroll
                for (int r = 0; r < 4; r++) sacc[nf][r] = 0.f;

            #pragma unroll
            for (int ks = 0; ks < 8; ks++) {
                uint4 af;
                LDSM_X4(af, sb + Z_Q + ((w << 4) + (lane & 15)) * ZROWB
                            + ks * 32 + (lane >> 4) * 16);
                #pragma unroll
                for (int nf = 0; nf < 8; nf++) {
                    uint2 bf;
                    LDSM_X2(bf, sb + Z_K + (nf * 8 + (lane & 7)) * ZROWB
                                + ks * 32 + ((lane >> 3) & 1) * 16);
                    mma_bf16(sacc[nf], af, bf);
                }
            }

            const float sc = 0.08838834764831845f;
            float mx_lo = -INFINITY, mx_hi = -INFINITY;
            #pragma unroll
            for (int nf = 0; nf < 8; nf++) {
                int kj = j0 + nf * 8 + lc * 2;
                float v0 = sacc[nf][0] * sc; if (kj     > qi_lo) v0 = -INFINITY;
                float v1 = sacc[nf][1] * sc; if (kj + 1 > qi_lo) v1 = -INFINITY;
                float v2 = sacc[nf][2] * sc; if (kj     > qi_hi) v2 = -INFINITY;
                float v3 = sacc[nf][3] * sc; if (kj + 1 > qi_hi) v3 = -INFINITY;
                sacc[nf][0] = v0; sacc[nf][1] = v1;
                sacc[nf][2] = v2; sacc[nf][3] = v3;
                mx_lo = fmaxf(mx_lo, fmaxf(v0, v1));
                mx_hi = fmaxf(mx_hi, fmaxf(v2, v3));
            }
            mx_lo = fmaxf(mx_lo, __shfl_xor_sync(0xffffffffu, mx_lo, 1));
            mx_lo = fmaxf(mx_lo, __shfl_xor_sync(0xffffffffu, mx_lo, 2));
            mx_hi = fmaxf(mx_hi, __shfl_xor_sync(0xffffffffu, mx_hi, 1));
            mx_hi = fmaxf(mx_hi, __shfl_xor_sync(0xffffffffu, mx_hi, 2));

            float mn_lo = fmaxf(m_lo, mx_lo);
            float mn_hi = fmaxf(m_hi, mx_hi);
            float corr_lo = expf(m_lo - mn_lo);
            float corr_hi = expf(m_hi - mn_hi);

            float sum_lo = 0.f, sum_hi = 0.f;
            #pragma unroll
            for (int nf = 0; nf < 8; nf++) {
                __nv_bfloat16 e0 = __float2bfloat16(expf(sacc[nf][0] - mn_lo));
                __nv_bfloat16 e1 = __float2bfloat16(expf(sacc[nf][1] - mn_lo));
                __nv_bfloat16 e2 = __float2bfloat16(expf(sacc[nf][2] - mn_hi));
                __nv_bfloat16 e3 = __float2bfloat16(expf(sacc[nf][3] - mn_hi));
                int colb = (nf * 8 + lc * 2) * 2;
                __nv_bfloat162 p01; p01.x = e0; p01.y = e1;
                __nv_bfloat162 p23; p23.x = e2; p23.y = e3;
                *(uint32_t*)(sm + Z_P + r_lo * 144 + colb) = *(uint32_t*)&p01;
                *(uint32_t*)(sm + Z_P + r_hi * 144 + colb) = *(uint32_t*)&p23;
                sum_lo += __bfloat162float(e0) + __bfloat162float(e1);
                sum_hi += __bfloat162float(e2) + __bfloat162float(e3);
            }
            sum_lo += __shfl_xor_sync(0xffffffffu, sum_lo, 1);
            sum_lo += __shfl_xor_sync(0xffffffffu, sum_lo, 2);
            sum_hi += __shfl_xor_sync(0xffffffffu, sum_hi, 1);
            sum_hi += __shfl_xor_sync(0xffffffffu, sum_hi, 2);

            l_lo = l_lo * corr_lo + sum_lo;
            l_hi = l_hi * corr_hi + sum_hi;
            m_lo = mn_lo;
            m_hi = mn_hi;

            #pragma unroll
            for (int nf = 0; nf < 16; nf++) {
                oacc[nf][0] *= corr_lo; oacc[nf][1] *= corr_lo;
                oacc[nf][2] *= corr_hi; oacc[nf][3] *= corr_hi;
            }

            __syncwarp();

            #pragma unroll
            for (int kf = 0; kf < 4; kf++) {
                uint4 af;
                LDSM_X4(af, sb + Z_P + ((w << 4) + (lane & 15)) * 144
                            + kf * 32 + (lane >> 4) * 16);
                #pragma unroll
                for (int nf = 0; nf < 16; nf++) {
                    uint2 bf;
                    LDSM_X2T(bf, sb + Z_V
                                 + (kf * 16 + ((lane >> 3) & 1) * 8 + (lane & 7)) * ZROWB
                                 + nf * 16);
                    mma_bf16(oacc[nf], af, bf);
                }
            }
        }
        __syncthreads();
    }

    {
        float inv_lo = 1.0f / l_lo;
        float inv_hi = 1.0f / l_hi;
        #pragma unroll
        for (int nf = 0; nf < 16; nf++) {
            int col = nf * 8 + lc * 2;
            __nv_bfloat16* d0 = o + base + (size_t)(q0 + r_lo) * DM + col;
            __nv_bfloat16* d1 = o + base + (size_t)(q0 + r_hi) * DM + col;
            *(uint32_t*)d0 = packbf2(oacc[nf][0] * inv_lo, oacc[nf][1] * inv_lo);
            *(uint32_t*)d1 = packbf2(oacc[nf][2] * inv_hi, oacc[nf][3] * inv_hi);
        }
    }
}

// ---------------------------------------------------------------------------
// Launch
// ---------------------------------------------------------------------------
extern "C" void kernel_launch(void* const* d_in, const int* in_sizes, int n_in,
                              void* d_out, int out_size)
{
    const float* h  = (const float*)d_in[0];
    const float* wq = (const float*)d_in[1];
    const float* bq = (const float*)d_in[2];
    const float* wk = (const float*)d_in[3];
    const float* bk = (const float*)d_in[4];
    const float* wv = (const float*)d_in[5];
    const float* bv = (const float*)d_in[6];
    const float* wo = (const float*)d_in[7];
    const float* bo = (const float*)d_in[8];
    const float* lg = (const float*)d_in[9];
    const float* lb = (const float*)d_in[10];
    float* out = (float*)d_out;

    float *xn, *qq, *vb, *ob;
    __nv_bfloat16* wb;
    float2* rt;
    cudaGetSymbolAddress((void**)&xn, g_xn);
    cudaGetSymbolAddress((void**)&qq, g_q);
    cudaGetSymbolAddress((void**)&vb, g_v);
    cudaGetSymbolAddress((void**)&ob, g_o);
    cudaGetSymbolAddress((void**)&wb, g_wb);
    cudaGetSymbolAddress((void**)&rt, g_rope);

    __nv_bfloat16* xn_bf = (__nv_bfloat16*)xn;                     // first 16MB of g_xn
    __nv_bfloat16* k_bf  = (__nv_bfloat16*)xn + (size_t)MROWS * DM;// second 16MB (no alias)
    __nv_bfloat16* q_bf  = (__nv_bfloat16*)qq;                     // DEDICATED buffer
    __nv_bfloat16* v_bf  = (__nv_bfloat16*)vb;
    __nv_bfloat16* ob_bf = (__nv_bfloat16*)ob;
    __nv_bfloat16* wq_bf = wb;
    __nv_bfloat16* wk_bf = wb + (size_t)DM * DM;
    __nv_bfloat16* wv_bf = wb + 2 * (size_t)DM * DM;
    __nv_bfloat16* wo_bf = wb + 3 * (size_t)DM * DM;

    // 0. RoPE table + fused weight conversion (4 f4/thread)
    rope_table_kernel<<<(S_ * 64 + 255) / 256, 256>>>(rt);
    int n4 = DM * DM / 4;
    wconv4_kernel<<<dim3((n4 + 1023) / 1024, 4), 256>>>(
        wq, wk, wv, wo, wq_bf, wk_bf, wv_bf, wo_bf, n4);

    // 1. LayerNorm (bf16 out)
    ln_kernel<<<MROWS, 256>>>(h, lg, lb, xn_bf);

    // 2. QKV projections with fused RoPE on Q/K. All outputs disjoint from xn.
    int smem_g = BSTAGES * BSTAGE_BYTES;     // 81920
    cudaFuncSetAttribute(bgemm_nt, cudaFuncAttributeMaxDynamicSharedMemorySize,
                         smem_g);
    dim3 gg(DM / 128, MROWS / 128);
    bgemm_nt<<<gg, 256, smem_g>>>(xn_bf, wq_bf, bq, nullptr, nullptr, q_bf, rt, DM, DM);
    bgemm_nt<<<gg, 256, smem_g>>>(xn_bf, wk_bf, bk, nullptr, nullptr, k_bf, rt, DM, DM);
    bgemm_nt<<<gg, 256, smem_g>>>(xn_bf, wv_bf, bv, nullptr, nullptr, v_bf, nullptr, DM, DM);

    // 3. Causal flash attention (BQ=128, register softmax)
    cudaFuncSetAttribute(attn_bq128_kernel,
                         cudaFuncAttributeMaxDynamicSharedMemorySize, Z_SMEM);
    attn_bq128_kernel<<<dim3(S_ / 128, NH, B_), 256, Z_SMEM>>>(q_bf, k_bf, v_bf, ob_bf);

    // 4. Output projection + bias + residual (fp32 out)
    bgemm_nt<<<gg, 256, smem_g>>>(ob_bf, wo_bf, bo, h, out, nullptr, nullptr, DM, DM);
}